// round 1
// baseline (speedup 1.0000x reference)
#include <cuda_runtime.h>

#define LSEQ 2048
#define DMODEL 2048
#define NH 16
#define DH 128
#define BATCH 2
#define MTOK (BATCH * LSEQ)   // 4096

// ---------------- scratch (static device arrays; no allocs) ----------------
__device__ float g_qh[(size_t)BATCH * NH * LSEQ * DH];
__device__ float g_kh[(size_t)BATCH * NH * LSEQ * DH];
__device__ float g_vh[(size_t)BATCH * NH * LSEQ * DH];
__device__ float g_ao[(size_t)MTOK * DMODEL];

// ---------------------------------------------------------------------------
// GEMM with bias: C = A[M,K] @ W[N,K]^T + bias[N]
// M=4096, N=K=2048 fixed. 128x128 tile, BK=16, 256 threads, 8x8 micro-tile.
// MODE 0: C laid out [M, N] row-major.
// MODE 1: C laid out [b, h, l, d]  (n = h*DH + d, m = b*L + l).
// ---------------------------------------------------------------------------
template <int MODE>
__global__ __launch_bounds__(256, 2)
void gemm_bias(const float* __restrict__ A, const float* __restrict__ W,
               const float* __restrict__ bias, float* __restrict__ C)
{
    __shared__ float As[16][132];
    __shared__ float Bs[16][132];

    const int tid = threadIdx.x;
    const int tx = tid & 15;        // 0..15  (N direction)
    const int ty = tid >> 4;        // 0..15  (M direction)
    const int bm = blockIdx.y * 128;
    const int bn = blockIdx.x * 128;

    const int lrow = tid >> 2;          // 0..63
    const int lk   = (tid & 3) << 2;    // 0,4,8,12

    const float* Ap = A + (size_t)(bm + lrow) * DMODEL + lk;
    const float* Wp = W + (size_t)(bn + lrow) * DMODEL + lk;

    float acc[8][8];
#pragma unroll
    for (int i = 0; i < 8; i++)
#pragma unroll
        for (int j = 0; j < 8; j++) acc[i][j] = 0.f;

    for (int k0 = 0; k0 < DMODEL; k0 += 16) {
        float4 a0 = *(const float4*)(Ap);
        float4 a1 = *(const float4*)(Ap + (size_t)64 * DMODEL);
        float4 w0 = *(const float4*)(Wp);
        float4 w1 = *(const float4*)(Wp + (size_t)64 * DMODEL);
        __syncthreads();
        As[lk + 0][lrow] = a0.x; As[lk + 1][lrow] = a0.y;
        As[lk + 2][lrow] = a0.z; As[lk + 3][lrow] = a0.w;
        As[lk + 0][lrow + 64] = a1.x; As[lk + 1][lrow + 64] = a1.y;
        As[lk + 2][lrow + 64] = a1.z; As[lk + 3][lrow + 64] = a1.w;
        Bs[lk + 0][lrow] = w0.x; Bs[lk + 1][lrow] = w0.y;
        Bs[lk + 2][lrow] = w0.z; Bs[lk + 3][lrow] = w0.w;
        Bs[lk + 0][lrow + 64] = w1.x; Bs[lk + 1][lrow + 64] = w1.y;
        Bs[lk + 2][lrow + 64] = w1.z; Bs[lk + 3][lrow + 64] = w1.w;
        __syncthreads();

#pragma unroll
        for (int kk = 0; kk < 16; kk++) {
            float4 af0 = *(const float4*)&As[kk][ty * 8];
            float4 af1 = *(const float4*)&As[kk][ty * 8 + 4];
            float4 bf0 = *(const float4*)&Bs[kk][tx * 8];
            float4 bf1 = *(const float4*)&Bs[kk][tx * 8 + 4];
            float a[8] = {af0.x, af0.y, af0.z, af0.w, af1.x, af1.y, af1.z, af1.w};
            float bb[8] = {bf0.x, bf0.y, bf0.z, bf0.w, bf1.x, bf1.y, bf1.z, bf1.w};
#pragma unroll
            for (int i = 0; i < 8; i++)
#pragma unroll
                for (int j = 0; j < 8; j++)
                    acc[i][j] += a[i] * bb[j];
        }
        Ap += 16;
        Wp += 16;
    }

    // epilogue
#pragma unroll
    for (int i = 0; i < 8; i++) {
        const int m = bm + ty * 8 + i;
        float out[8];
#pragma unroll
        for (int j = 0; j < 8; j++) {
            const int n = bn + tx * 8 + j;
            out[j] = acc[i][j] + bias[n];
        }
        if (MODE == 0) {
            float* dst = C + (size_t)m * DMODEL + bn + tx * 8;
            *(float4*)(dst)     = make_float4(out[0], out[1], out[2], out[3]);
            *(float4*)(dst + 4) = make_float4(out[4], out[5], out[6], out[7]);
        } else {
            // n = bn + tx*8 + j; head fixed per CTA column block
            const int h = bn >> 7;             // bn multiple of 128
            const int d = tx * 8;              // 8tx+j < 128 within block
            const int b = m >> 11;             // m / 2048
            const int l = m & (LSEQ - 1);
            float* dst = C + (((size_t)(b * NH + h) * LSEQ + l) * DH) + d;
            *(float4*)(dst)     = make_float4(out[0], out[1], out[2], out[3]);
            *(float4*)(dst + 4) = make_float4(out[4], out[5], out[6], out[7]);
        }
    }
}

// ---------------------------------------------------------------------------
// Flash attention (causal), fp32. One CTA = 64 q-rows of one (b, h).
// scores = (q . k) * sqrt(DH); masked entries get -1e7 (faithful to ref).
// Thread layout: 16x16 (ty rows, tx cols). S micro-tile 4x4, O micro 4x8.
// Dynamic smem: QsT[128][68] + KsT[128][68] + Vs[64][132] + Ps[64][68]
// ---------------------------------------------------------------------------
#define FA_SMEM_FLOATS (128 * 68 + 128 * 68 + 64 * 132 + 64 * 68)

__global__ __launch_bounds__(256)
void flash_attn(const float* __restrict__ Q, const float* __restrict__ K,
                const float* __restrict__ V, float* __restrict__ O)
{
    extern __shared__ float sm[];
    float* QsT = sm;                    // [128][68]  (d-major, row in col)
    float* KsT = QsT + 128 * 68;        // [128][68]
    float* Vs  = KsT + 128 * 68;        // [64][132]
    float* Ps  = Vs + 64 * 132;         // [64][68]

    const int tid = threadIdx.x;
    const int tx = tid & 15;
    const int ty = tid >> 4;
    const int qt = blockIdx.x;          // q tile (0..31)
    const int h  = blockIdx.y;
    const int b  = blockIdx.z;
    const float scale = 11.31370849898476f;   // sqrt(128)

    const float* Qb = Q + ((size_t)(b * NH + h) * LSEQ + qt * 64) * DH;

    // Load Q tile transposed (coalesced LDG, 4-way STS conflict acceptable)
    for (int i = tid; i < 64 * 128; i += 256) {
        int r = i >> 7, d = i & 127;
        QsT[d * 68 + r] = Qb[i];
    }

    float m_i[4], l_i[4], o[4][8];
#pragma unroll
    for (int i = 0; i < 4; i++) {
        m_i[i] = -3.0e38f;
        l_i[i] = 0.f;
#pragma unroll
        for (int c = 0; c < 8; c++) o[i][c] = 0.f;
    }

    for (int kt = 0; kt <= qt; kt++) {
        __syncthreads();   // prior PV reads of Vs / Ps done
        const float* Kb = K + ((size_t)(b * NH + h) * LSEQ + kt * 64) * DH;
        const float* Vb = V + ((size_t)(b * NH + h) * LSEQ + kt * 64) * DH;
        for (int i = tid; i < 64 * 128; i += 256) {
            int r = i >> 7, d = i & 127;
            KsT[d * 68 + r] = Kb[i];
            Vs[r * 132 + d] = Vb[i];
        }
        __syncthreads();

        // ---- S = Q K^T (4x4 per thread) ----
        float s[4][4];
#pragma unroll
        for (int i = 0; i < 4; i++)
#pragma unroll
            for (int j = 0; j < 4; j++) s[i][j] = 0.f;

#pragma unroll 4
        for (int d = 0; d < 128; d++) {
            float4 q4 = *(const float4*)&QsT[d * 68 + ty * 4];
            float4 k4 = *(const float4*)&KsT[d * 68 + tx * 4];
            float qa[4] = {q4.x, q4.y, q4.z, q4.w};
            float ka[4] = {k4.x, k4.y, k4.z, k4.w};
#pragma unroll
            for (int i = 0; i < 4; i++)
#pragma unroll
                for (int j = 0; j < 4; j++)
                    s[i][j] += qa[i] * ka[j];
        }

        // ---- scale + causal mask ----
#pragma unroll
        for (int i = 0; i < 4; i++) {
            const int ig = qt * 64 + ty * 4 + i;
#pragma unroll
            for (int j = 0; j < 4; j++) {
                const int jg = kt * 64 + tx * 4 + j;
                float v = s[i][j] * scale;
                if (jg > ig) v -= 1e7f;
                s[i][j] = v;
            }
        }

        // ---- online softmax (row reduce across 16 tx lanes) ----
#pragma unroll
        for (int i = 0; i < 4; i++) {
            float mx = fmaxf(fmaxf(s[i][0], s[i][1]), fmaxf(s[i][2], s[i][3]));
            mx = fmaxf(mx, __shfl_xor_sync(0xffffffffu, mx, 8));
            mx = fmaxf(mx, __shfl_xor_sync(0xffffffffu, mx, 4));
            mx = fmaxf(mx, __shfl_xor_sync(0xffffffffu, mx, 2));
            mx = fmaxf(mx, __shfl_xor_sync(0xffffffffu, mx, 1));
            const float nm = fmaxf(m_i[i], mx);
            const float alpha = __expf(m_i[i] - nm);
            m_i[i] = nm;
            float sum = 0.f;
#pragma unroll
            for (int j = 0; j < 4; j++) {
                float p = __expf(s[i][j] - nm);
                s[i][j] = p;
                sum += p;
            }
            sum += __shfl_xor_sync(0xffffffffu, sum, 8);
            sum += __shfl_xor_sync(0xffffffffu, sum, 4);
            sum += __shfl_xor_sync(0xffffffffu, sum, 2);
            sum += __shfl_xor_sync(0xffffffffu, sum, 1);
            l_i[i] = l_i[i] * alpha + sum;
#pragma unroll
            for (int c = 0; c < 8; c++) o[i][c] *= alpha;
        }

        // ---- stage P ----
#pragma unroll
        for (int i = 0; i < 4; i++) {
            *(float4*)&Ps[(ty * 4 + i) * 68 + tx * 4] =
                make_float4(s[i][0], s[i][1], s[i][2], s[i][3]);
        }
        __syncthreads();

        // ---- O += P @ V ----
#pragma unroll 2
        for (int j = 0; j < 64; j++) {
            float4 v0 = *(const float4*)&Vs[j * 132 + tx * 8];
            float4 v1 = *(const float4*)&Vs[j * 132 + tx * 8 + 4];
            float va[8] = {v0.x, v0.y, v0.z, v0.w, v1.x, v1.y, v1.z, v1.w};
#pragma unroll
            for (int i = 0; i < 4; i++) {
                const float p = Ps[(ty * 4 + i) * 68 + j];
#pragma unroll
                for (int c = 0; c < 8; c++)
                    o[i][c] += p * va[c];
            }
        }
    }

    // ---- epilogue: normalize + write [b, l, D] layout ----
#pragma unroll
    for (int i = 0; i < 4; i++) {
        const float inv = 1.0f / l_i[i];
        const int row = b * LSEQ + qt * 64 + ty * 4 + i;
        float* dst = O + (size_t)row * DMODEL + h * DH + tx * 8;
        *(float4*)(dst) =
            make_float4(o[i][0] * inv, o[i][1] * inv, o[i][2] * inv, o[i][3] * inv);
        *(float4*)(dst + 4) =
            make_float4(o[i][4] * inv, o[i][5] * inv, o[i][6] * inv, o[i][7] * inv);
    }
}

// ---------------------------------------------------------------------------
extern "C" void kernel_launch(void* const* d_in, const int* in_sizes, int n_in,
                              void* d_out, int out_size)
{
    (void)in_sizes; (void)n_in; (void)out_size;
    const float* q  = (const float*)d_in[0];
    const float* k  = (const float*)d_in[1];
    const float* v  = (const float*)d_in[2];
    const float* Wq = (const float*)d_in[3];
    const float* bq = (const float*)d_in[4];
    const float* Wk = (const float*)d_in[5];
    const float* bk = (const float*)d_in[6];
    const float* Wv = (const float*)d_in[7];
    const float* bv = (const float*)d_in[8];
    const float* Wo = (const float*)d_in[9];
    const float* bo = (const float*)d_in[10];
    float* out = (float*)d_out;

    float *qh = nullptr, *kh = nullptr, *vh = nullptr, *ao = nullptr;
    cudaGetSymbolAddress((void**)&qh, g_qh);
    cudaGetSymbolAddress((void**)&kh, g_kh);
    cudaGetSymbolAddress((void**)&vh, g_vh);
    cudaGetSymbolAddress((void**)&ao, g_ao);

    const size_t fa_smem = FA_SMEM_FLOATS * sizeof(float);
    // Set once on the correctness call (pre-capture); ignore errors if
    // repeated during capture — the attribute is sticky.
    cudaFuncSetAttribute(flash_attn, cudaFuncAttributeMaxDynamicSharedMemorySize,
                         (int)fa_smem);

    dim3 ggrid(DMODEL / 128, MTOK / 128);   // (16, 32)

    gemm_bias<1><<<ggrid, 256>>>(q, Wq, bq, qh);
    gemm_bias<1><<<ggrid, 256>>>(k, Wk, bk, kh);
    gemm_bias<1><<<ggrid, 256>>>(v, Wv, bv, vh);

    flash_attn<<<dim3(LSEQ / 64, NH, BATCH), 256, fa_smem>>>(qh, kh, vh, ao);

    gemm_bias<0><<<ggrid, 256>>>(ao, Wo, bo, out);
}

// round 3
// speedup vs baseline: 1.6742x; 1.6742x over previous
#include <cuda_runtime.h>
#include <cuda_bf16.h>
#include <cstdint>

#define LSEQ 2048
#define DMODEL 2048
#define NH 16
#define DH 128
#define BATCH 2
#define MTOK (BATCH * LSEQ)                 // 4096
#define ACT_ELEMS ((size_t)MTOK * DMODEL)   // 8388608
#define W_ELEMS ((size_t)DMODEL * DMODEL)   // 4194304

// ---------------- scratch (static device arrays; no allocs) ----------------
__device__ float g_qh[(size_t)BATCH * NH * LSEQ * DH];
__device__ float g_kh[(size_t)BATCH * NH * LSEQ * DH];
__device__ float g_vh[(size_t)BATCH * NH * LSEQ * DH];
__device__ float g_ao[ACT_ELEMS];

// hi/lo bf16 splits: [0..N) = hi, [N..2N) = lo
__device__ __nv_bfloat16 g_sq[2 * ACT_ELEMS];
__device__ __nv_bfloat16 g_sk[2 * ACT_ELEMS];
__device__ __nv_bfloat16 g_sv[2 * ACT_ELEMS];
__device__ __nv_bfloat16 g_sa[2 * ACT_ELEMS];
__device__ __nv_bfloat16 g_swq[2 * W_ELEMS];
__device__ __nv_bfloat16 g_swk[2 * W_ELEMS];
__device__ __nv_bfloat16 g_swv[2 * W_ELEMS];
__device__ __nv_bfloat16 g_swo[2 * W_ELEMS];

// ---------------------------- PTX helpers ----------------------------------
__device__ __forceinline__ uint32_t smem_u32(const void* p) {
    uint32_t a;
    asm("{ .reg .u64 t; cvta.to.shared.u64 t, %1; cvt.u32.u64 %0, t; }"
        : "=r"(a) : "l"(p));
    return a;
}

__device__ __forceinline__ void cp16(uint32_t saddr, const void* g) {
    asm volatile("cp.async.cg.shared.global [%0], [%1], 16;"
                 :: "r"(saddr), "l"(g) : "memory");
}
#define CP_COMMIT() asm volatile("cp.async.commit_group;" ::: "memory")
#define CP_WAIT(n)  asm volatile("cp.async.wait_group %0;" :: "n"(n) : "memory")

__device__ __forceinline__ void ldsm_x4(uint32_t* r, uint32_t a) {
    asm volatile("ldmatrix.sync.aligned.m8n8.x4.shared.b16 {%0,%1,%2,%3}, [%4];"
                 : "=r"(r[0]), "=r"(r[1]), "=r"(r[2]), "=r"(r[3]) : "r"(a));
}
__device__ __forceinline__ void ldsm_x2(uint32_t* r, uint32_t a) {
    asm volatile("ldmatrix.sync.aligned.m8n8.x2.shared.b16 {%0,%1}, [%2];"
                 : "=r"(r[0]), "=r"(r[1]) : "r"(a));
}
__device__ __forceinline__ void mma_bf16(float* d, const uint32_t* a,
                                         const uint32_t* b) {
    asm volatile(
        "mma.sync.aligned.m16n8k16.row.col.f32.bf16.bf16.f32 "
        "{%0,%1,%2,%3}, {%4,%5,%6,%7}, {%8,%9}, {%0,%1,%2,%3};"
        : "+f"(d[0]), "+f"(d[1]), "+f"(d[2]), "+f"(d[3])
        : "r"(a[0]), "r"(a[1]), "r"(a[2]), "r"(a[3]), "r"(b[0]), "r"(b[1]));
}

// ---------------------------------------------------------------------------
// split: x (fp32) -> hi bf16 at out[0..n), lo bf16 at out[n..2n)
// ---------------------------------------------------------------------------
__global__ __launch_bounds__(256)
void split_hilo(const float* __restrict__ x, __nv_bfloat16* __restrict__ out,
                int n4, int n)
{
    int i = blockIdx.x * blockDim.x + threadIdx.x;
    if (i >= n4) return;
    float4 v = ((const float4*)x)[i];
    __nv_bfloat16 h0 = __float2bfloat16(v.x);
    __nv_bfloat16 h1 = __float2bfloat16(v.y);
    __nv_bfloat16 h2 = __float2bfloat16(v.z);
    __nv_bfloat16 h3 = __float2bfloat16(v.w);
    __nv_bfloat16 l0 = __float2bfloat16(v.x - __bfloat162float(h0));
    __nv_bfloat16 l1 = __float2bfloat16(v.y - __bfloat162float(h1));
    __nv_bfloat16 l2 = __float2bfloat16(v.z - __bfloat162float(h2));
    __nv_bfloat16 l3 = __float2bfloat16(v.w - __bfloat162float(h3));
    __nv_bfloat162* hp = (__nv_bfloat162*)out;
    __nv_bfloat162* lp = (__nv_bfloat162*)(out + n);
    hp[2 * i]     = __nv_bfloat162(h0, h1);
    hp[2 * i + 1] = __nv_bfloat162(h2, h3);
    lp[2 * i]     = __nv_bfloat162(l0, l1);
    lp[2 * i + 1] = __nv_bfloat162(l2, l3);
}

// ---------------------------------------------------------------------------
// mma.sync GEMM: C[4096, 2048] = (Ahi+Alo)[M,K] @ (Bhi+Blo)[N,K]^T + bias
// 128x128 CTA tile, 8 warps (64x32 warp tile), BK=32, cp.async 3-stage.
// 3 split products (hi*hi + hi*lo + lo*hi) into fp32 accumulators.
// Smem tile row = 64B (32 bf16), XOR swizzle: seg' = seg ^ ((row>>1)&3).
// MODE 0: C row-major [M, N].  MODE 1: C as [b, h, l, d].
// ---------------------------------------------------------------------------
#define TILE_B  8192                 // 128 rows * 64 B
#define STAGE_B (4 * TILE_B)         // Ahi, Alo, Bhi, Blo = 32 KB
#define NSTAGE  3
#define GSMEM_B (NSTAGE * STAGE_B)   // 96 KB
#define NCHUNK  (DMODEL / 32)        // 64

template <int MODE>
__global__ __launch_bounds__(256)
void gemm_mma(const __nv_bfloat16* __restrict__ Ahi,
              const __nv_bfloat16* __restrict__ Alo,
              const __nv_bfloat16* __restrict__ Bhi,
              const __nv_bfloat16* __restrict__ Blo,
              const float* __restrict__ bias, float* __restrict__ C)
{
    extern __shared__ char smb[];
    const uint32_t sbase = smem_u32(smb);

    const int tid = threadIdx.x;
    const int lane = tid & 31;
    const int wid = tid >> 5;
    const int wm = wid & 1;          // 2 m-blocks of 64
    const int wn = wid >> 1;         // 4 n-blocks of 32
    const int bn = blockIdx.x * 128;
    const int bm = blockIdx.y * 128;

    // loader coords: thread t handles rows (r, r+64) at 16B-segment q
    const int r = tid >> 2;          // 0..63
    const int q = tid & 3;           // 0..3

    auto load_stage = [&](int kc, int s) {
        const int k0 = kc * 32;
        const uint32_t st = sbase + (uint32_t)s * STAGE_B;
        const __nv_bfloat16* srcs[4] = {Ahi, Alo, Bhi, Blo};
        const int row0[4] = {bm, bm, bn, bn};
#pragma unroll
        for (int t = 0; t < 4; t++) {
            const __nv_bfloat16* g0 =
                srcs[t] + (size_t)(row0[t] + r) * DMODEL + k0 + q * 8;
#pragma unroll
            for (int half = 0; half < 2; half++) {
                const int rr = r + half * 64;
                const uint32_t soff = (uint32_t)t * TILE_B + rr * 64 +
                                      ((q ^ ((rr >> 1) & 3)) * 16);
                cp16(st + soff, g0 + (size_t)half * 64 * DMODEL);
            }
        }
    };

    float acc[4][4][4];
#pragma unroll
    for (int i = 0; i < 4; i++)
#pragma unroll
        for (int j = 0; j < 4; j++)
#pragma unroll
            for (int c = 0; c < 4; c++) acc[i][j][c] = 0.f;

    load_stage(0, 0); CP_COMMIT();
    load_stage(1, 1); CP_COMMIT();

    for (int kc = 0; kc < NCHUNK; kc++) {
        const int s = kc % NSTAGE;
        CP_WAIT(1);
        __syncthreads();
        if (kc + 2 < NCHUNK) load_stage(kc + 2, (kc + 2) % NSTAGE);
        CP_COMMIT();

        const uint32_t st = sbase + (uint32_t)s * STAGE_B;
        const uint32_t sAh = st;
        const uint32_t sAl = st + TILE_B;
        const uint32_t sBh = st + 2 * TILE_B;
        const uint32_t sBl = st + 3 * TILE_B;

#pragma unroll
        for (int ks = 0; ks < 2; ks++) {
            uint32_t ah[4][4], al[4][4], bh[4][2], bl[4][2];
#pragma unroll
            for (int mt = 0; mt < 4; mt++) {
                const int row = wm * 64 + mt * 16 + (lane & 15);
                const int kseg = ks * 2 + (lane >> 4);
                const uint32_t off =
                    row * 64 + ((kseg ^ ((row >> 1) & 3)) * 16);
                ldsm_x4(ah[mt], sAh + off);
                ldsm_x4(al[mt], sAl + off);
            }
#pragma unroll
            for (int nt = 0; nt < 4; nt++) {
                const int nrow = wn * 32 + nt * 8 + (lane & 7);
                const int kseg = ks * 2 + ((lane >> 3) & 1);
                const uint32_t off =
                    nrow * 64 + ((kseg ^ ((nrow >> 1) & 3)) * 16);
                ldsm_x2(bh[nt], sBh + off);
                ldsm_x2(bl[nt], sBl + off);
            }
#pragma unroll
            for (int mt = 0; mt < 4; mt++)
#pragma unroll
                for (int nt = 0; nt < 4; nt++) {
                    mma_bf16(acc[mt][nt], ah[mt], bh[nt]);
                    mma_bf16(acc[mt][nt], ah[mt], bl[nt]);
                    mma_bf16(acc[mt][nt], al[mt], bh[nt]);
                }
        }
    }

    // ---- epilogue ----
#pragma unroll
    for (int mt = 0; mt < 4; mt++) {
#pragma unroll
        for (int nt = 0; nt < 4; nt++) {
            const int m0 = bm + wm * 64 + mt * 16 + (lane >> 2);
            const int n0 = bn + wn * 32 + nt * 8 + (lane & 3) * 2;
            const float bia0 = __ldg(&bias[n0]);
            const float bia1 = __ldg(&bias[n0 + 1]);
#pragma unroll
            for (int half = 0; half < 2; half++) {
                const int m = m0 + half * 8;
                float2 o = make_float2(acc[mt][nt][half * 2] + bia0,
                                       acc[mt][nt][half * 2 + 1] + bia1);
                float* dst;
                if (MODE == 0) {
                    dst = C + (size_t)m * DMODEL + n0;
                } else {
                    const int h = bn >> 7;
                    const int b = m >> 11;
                    const int l = m & (LSEQ - 1);
                    dst = C + (((size_t)(b * NH + h) * LSEQ + l) * DH) +
                          (n0 & 127);
                }
                *(float2*)dst = o;
            }
        }
    }
}

// ---------------------------------------------------------------------------
// Flash attention (causal), fp32 — unchanged (proven correct).
// ---------------------------------------------------------------------------
#define FA_SMEM_FLOATS (128 * 68 + 128 * 68 + 64 * 132 + 64 * 68)

__global__ __launch_bounds__(256)
void flash_attn(const float* __restrict__ Q, const float* __restrict__ K,
                const float* __restrict__ V, float* __restrict__ O)
{
    extern __shared__ float sm[];
    float* QsT = sm;
    float* KsT = QsT + 128 * 68;
    float* Vs  = KsT + 128 * 68;
    float* Ps  = Vs + 64 * 132;

    const int tid = threadIdx.x;
    const int tx = tid & 15;
    const int ty = tid >> 4;
    const int qt = blockIdx.x;
    const int h  = blockIdx.y;
    const int b  = blockIdx.z;
    const float scale = 11.31370849898476f;   // sqrt(128)

    const float* Qb = Q + ((size_t)(b * NH + h) * LSEQ + qt * 64) * DH;

    for (int i = tid; i < 64 * 128; i += 256) {
        int r = i >> 7, d = i & 127;
        QsT[d * 68 + r] = Qb[i];
    }

    float m_i[4], l_i[4], o[4][8];
#pragma unroll
    for (int i = 0; i < 4; i++) {
        m_i[i] = -3.0e38f;
        l_i[i] = 0.f;
#pragma unroll
        for (int c = 0; c < 8; c++) o[i][c] = 0.f;
    }

    for (int kt = 0; kt <= qt; kt++) {
        __syncthreads();
        const float* Kb = K + ((size_t)(b * NH + h) * LSEQ + kt * 64) * DH;
        const float* Vb = V + ((size_t)(b * NH + h) * LSEQ + kt * 64) * DH;
        for (int i = tid; i < 64 * 128; i += 256) {
            int r = i >> 7, d = i & 127;
            KsT[d * 68 + r] = Kb[i];
            Vs[r * 132 + d] = Vb[i];
        }
        __syncthreads();

        float s[4][4];
#pragma unroll
        for (int i = 0; i < 4; i++)
#pragma unroll
            for (int j = 0; j < 4; j++) s[i][j] = 0.f;

#pragma unroll 4
        for (int d = 0; d < 128; d++) {
            float4 q4 = *(const float4*)&QsT[d * 68 + ty * 4];
            float4 k4 = *(const float4*)&KsT[d * 68 + tx * 4];
            float qa[4] = {q4.x, q4.y, q4.z, q4.w};
            float ka[4] = {k4.x, k4.y, k4.z, k4.w};
#pragma unroll
            for (int i = 0; i < 4; i++)
#pragma unroll
                for (int j = 0; j < 4; j++)
                    s[i][j] += qa[i] * ka[j];
        }

#pragma unroll
        for (int i = 0; i < 4; i++) {
            const int ig = qt * 64 + ty * 4 + i;
#pragma unroll
            for (int j = 0; j < 4; j++) {
                const int jg = kt * 64 + tx * 4 + j;
                float v = s[i][j] * scale;
                if (jg > ig) v -= 1e7f;
                s[i][j] = v;
            }
        }

#pragma unroll
        for (int i = 0; i < 4; i++) {
            float mx = fmaxf(fmaxf(s[i][0], s[i][1]), fmaxf(s[i][2], s[i][3]));
            mx = fmaxf(mx, __shfl_xor_sync(0xffffffffu, mx, 8));
            mx = fmaxf(mx, __shfl_xor_sync(0xffffffffu, mx, 4));
            mx = fmaxf(mx, __shfl_xor_sync(0xffffffffu, mx, 2));
            mx = fmaxf(mx, __shfl_xor_sync(0xffffffffu, mx, 1));
            const float nm = fmaxf(m_i[i], mx);
            const float alpha = __expf(m_i[i] - nm);
            m_i[i] = nm;
            float sum = 0.f;
#pragma unroll
            for (int j = 0; j < 4; j++) {
                float p = __expf(s[i][j] - nm);
                s[i][j] = p;
                sum += p;
            }
            sum += __shfl_xor_sync(0xffffffffu, sum, 8);
            sum += __shfl_xor_sync(0xffffffffu, sum, 4);
            sum += __shfl_xor_sync(0xffffffffu, sum, 2);
            sum += __shfl_xor_sync(0xffffffffu, sum, 1);
            l_i[i] = l_i[i] * alpha + sum;
#pragma unroll
            for (int c = 0; c < 8; c++) o[i][c] *= alpha;
        }

#pragma unroll
        for (int i = 0; i < 4; i++) {
            *(float4*)&Ps[(ty * 4 + i) * 68 + tx * 4] =
                make_float4(s[i][0], s[i][1], s[i][2], s[i][3]);
        }
        __syncthreads();

#pragma unroll 2
        for (int j = 0; j < 64; j++) {
            float4 v0 = *(const float4*)&Vs[j * 132 + tx * 8];
            float4 v1 = *(const float4*)&Vs[j * 132 + tx * 8 + 4];
            float va[8] = {v0.x, v0.y, v0.z, v0.w, v1.x, v1.y, v1.z, v1.w};
#pragma unroll
            for (int i = 0; i < 4; i++) {
                const float p = Ps[(ty * 4 + i) * 68 + j];
#pragma unroll
                for (int c = 0; c < 8; c++)
                    o[i][c] += p * va[c];
            }
        }
    }

#pragma unroll
    for (int i = 0; i < 4; i++) {
        const float inv = 1.0f / l_i[i];
        const int row = b * LSEQ + qt * 64 + ty * 4 + i;
        float* dst = O + (size_t)row * DMODEL + h * DH + tx * 8;
        *(float4*)(dst) =
            make_float4(o[i][0] * inv, o[i][1] * inv, o[i][2] * inv, o[i][3] * inv);
        *(float4*)(dst + 4) =
            make_float4(o[i][4] * inv, o[i][5] * inv, o[i][6] * inv, o[i][7] * inv);
    }
}

// ---------------------------------------------------------------------------
extern "C" void kernel_launch(void* const* d_in, const int* in_sizes, int n_in,
                              void* d_out, int out_size)
{
    (void)in_sizes; (void)n_in; (void)out_size;
    const float* q  = (const float*)d_in[0];
    const float* k  = (const float*)d_in[1];
    const float* v  = (const float*)d_in[2];
    const float* Wq = (const float*)d_in[3];
    const float* bq = (const float*)d_in[4];
    const float* Wk = (const float*)d_in[5];
    const float* bk = (const float*)d_in[6];
    const float* Wv = (const float*)d_in[7];
    const float* bv = (const float*)d_in[8];
    const float* Wo = (const float*)d_in[9];
    const float* bo = (const float*)d_in[10];
    float* out = (float*)d_out;

    float *qh, *kh, *vh, *ao;
    __nv_bfloat16 *sq, *sk, *sv, *sa, *swq, *swk, *swv, *swo;
    cudaGetSymbolAddress((void**)&qh, g_qh);
    cudaGetSymbolAddress((void**)&kh, g_kh);
    cudaGetSymbolAddress((void**)&vh, g_vh);
    cudaGetSymbolAddress((void**)&ao, g_ao);
    cudaGetSymbolAddress((void**)&sq, g_sq);
    cudaGetSymbolAddress((void**)&sk, g_sk);
    cudaGetSymbolAddress((void**)&sv, g_sv);
    cudaGetSymbolAddress((void**)&sa, g_sa);
    cudaGetSymbolAddress((void**)&swq, g_swq);
    cudaGetSymbolAddress((void**)&swk, g_swk);
    cudaGetSymbolAddress((void**)&swv, g_swv);
    cudaGetSymbolAddress((void**)&swo, g_swo);

    const size_t fa_smem = FA_SMEM_FLOATS * sizeof(float);
    cudaFuncSetAttribute(flash_attn, cudaFuncAttributeMaxDynamicSharedMemorySize,
                         (int)fa_smem);
    cudaFuncSetAttribute(gemm_mma<0>, cudaFuncAttributeMaxDynamicSharedMemorySize,
                         GSMEM_B);
    cudaFuncSetAttribute(gemm_mma<1>, cudaFuncAttributeMaxDynamicSharedMemorySize,
                         GSMEM_B);

    const int actN = (int)ACT_ELEMS, wN = (int)W_ELEMS;
    split_hilo<<<(actN / 4 + 255) / 256, 256>>>(q, sq, actN / 4, actN);
    split_hilo<<<(actN / 4 + 255) / 256, 256>>>(k, sk, actN / 4, actN);
    split_hilo<<<(actN / 4 + 255) / 256, 256>>>(v, sv, actN / 4, actN);
    split_hilo<<<(wN / 4 + 255) / 256, 256>>>(Wq, swq, wN / 4, wN);
    split_hilo<<<(wN / 4 + 255) / 256, 256>>>(Wk, swk, wN / 4, wN);
    split_hilo<<<(wN / 4 + 255) / 256, 256>>>(Wv, swv, wN / 4, wN);
    split_hilo<<<(wN / 4 + 255) / 256, 256>>>(Wo, swo, wN / 4, wN);

    dim3 ggrid(DMODEL / 128, MTOK / 128);   // (16, 32)
    gemm_mma<1><<<ggrid, 256, GSMEM_B>>>(sq, sq + ACT_ELEMS, swq, swq + W_ELEMS, bq, qh);
    gemm_mma<1><<<ggrid, 256, GSMEM_B>>>(sk, sk + ACT_ELEMS, swk, swk + W_ELEMS, bk, kh);
    gemm_mma<1><<<ggrid, 256, GSMEM_B>>>(sv, sv + ACT_ELEMS, swv, swv + W_ELEMS, bv, vh);

    flash_attn<<<dim3(LSEQ / 64, NH, BATCH), 256, fa_smem>>>(qh, kh, vh, ao);

    split_hilo<<<(actN / 4 + 255) / 256, 256>>>(ao, sa, actN / 4, actN);
    gemm_mma<0><<<ggrid, 256, GSMEM_B>>>(sa, sa + ACT_ELEMS, swo, swo + W_ELEMS, bo, out);
}

// round 4
// speedup vs baseline: 3.1829x; 1.9011x over previous
#include <cuda_runtime.h>
#include <cuda_bf16.h>
#include <cstdint>

#define LSEQ 2048
#define DMODEL 2048
#define NH 16
#define DH 128
#define BATCH 2
#define MTOK (BATCH * LSEQ)                 // 4096
#define ACT_ELEMS ((size_t)MTOK * DMODEL)   // 8388608
#define W_ELEMS ((size_t)DMODEL * DMODEL)   // 4194304

// ---------------- scratch (static device arrays; no allocs) ----------------
// hi/lo bf16 splits: [0..N) = hi, [N..2N) = lo
__device__ __nv_bfloat16 g_sq[2 * ACT_ELEMS];   // split of input q
__device__ __nv_bfloat16 g_sk[2 * ACT_ELEMS];
__device__ __nv_bfloat16 g_sv[2 * ACT_ELEMS];
__device__ __nv_bfloat16 g_sa[2 * ACT_ELEMS];   // attention out (flash writes)
__device__ __nv_bfloat16 g_qh2[2 * ACT_ELEMS];  // projected Q  [b,h,l,d]
__device__ __nv_bfloat16 g_kh2[2 * ACT_ELEMS];
__device__ __nv_bfloat16 g_vh2[2 * ACT_ELEMS];
__device__ __nv_bfloat16 g_swq[2 * W_ELEMS];
__device__ __nv_bfloat16 g_swk[2 * W_ELEMS];
__device__ __nv_bfloat16 g_swv[2 * W_ELEMS];
__device__ __nv_bfloat16 g_swo[2 * W_ELEMS];

// ---------------------------- PTX helpers ----------------------------------
__device__ __forceinline__ uint32_t smem_u32(const void* p) {
    uint32_t a;
    asm("{ .reg .u64 t; cvta.to.shared.u64 t, %1; cvt.u32.u64 %0, t; }"
        : "=r"(a) : "l"(p));
    return a;
}

__device__ __forceinline__ void cp16(uint32_t saddr, const void* g) {
    asm volatile("cp.async.cg.shared.global [%0], [%1], 16;"
                 :: "r"(saddr), "l"(g) : "memory");
}
#define CP_COMMIT() asm volatile("cp.async.commit_group;" ::: "memory")
#define CP_WAIT(n)  asm volatile("cp.async.wait_group %0;" :: "n"(n) : "memory")

__device__ __forceinline__ void ldsm_x4(uint32_t* r, uint32_t a) {
    asm volatile("ldmatrix.sync.aligned.m8n8.x4.shared.b16 {%0,%1,%2,%3}, [%4];"
                 : "=r"(r[0]), "=r"(r[1]), "=r"(r[2]), "=r"(r[3]) : "r"(a));
}
__device__ __forceinline__ void ldsm_x2(uint32_t* r, uint32_t a) {
    asm volatile("ldmatrix.sync.aligned.m8n8.x2.shared.b16 {%0,%1}, [%2];"
                 : "=r"(r[0]), "=r"(r[1]) : "r"(a));
}
__device__ __forceinline__ void ldsm_x2t(uint32_t* r, uint32_t a) {
    asm volatile("ldmatrix.sync.aligned.m8n8.x2.trans.shared.b16 {%0,%1}, [%2];"
                 : "=r"(r[0]), "=r"(r[1]) : "r"(a));
}
__device__ __forceinline__ void mma_bf16(float* d, const uint32_t* a,
                                         const uint32_t* b) {
    asm volatile(
        "mma.sync.aligned.m16n8k16.row.col.f32.bf16.bf16.f32 "
        "{%0,%1,%2,%3}, {%4,%5,%6,%7}, {%8,%9}, {%0,%1,%2,%3};"
        : "+f"(d[0]), "+f"(d[1]), "+f"(d[2]), "+f"(d[3])
        : "r"(a[0]), "r"(a[1]), "r"(a[2]), "r"(a[3]), "r"(b[0]), "r"(b[1]));
}

// pack two floats -> (hi bf16x2, lo bf16x2 residual)
__device__ __forceinline__ void split2(float x, float y,
                                       uint32_t& hi, uint32_t& lo) {
    __nv_bfloat16 hx = __float2bfloat16(x);
    __nv_bfloat16 hy = __float2bfloat16(y);
    __nv_bfloat162 h2; h2.x = hx; h2.y = hy;
    hi = *reinterpret_cast<uint32_t*>(&h2);
    __nv_bfloat162 l2;
    l2.x = __float2bfloat16(x - __bfloat162float(hx));
    l2.y = __float2bfloat16(y - __bfloat162float(hy));
    lo = *reinterpret_cast<uint32_t*>(&l2);
}

// swizzled offset in a 256B-row tile (16 segs of 16B per row)
__device__ __forceinline__ uint32_t sw256(int r, int q) {
    return (uint32_t)(r * 256 + ((q ^ (r & 7)) << 4));
}

// ---------------------------------------------------------------------------
// split: x (fp32) -> hi bf16 at out[0..n), lo bf16 at out[n..2n)
// ---------------------------------------------------------------------------
__global__ __launch_bounds__(256)
void split_hilo(const float* __restrict__ x, __nv_bfloat16* __restrict__ out,
                int n4, int n)
{
    int i = blockIdx.x * blockDim.x + threadIdx.x;
    if (i >= n4) return;
    float4 v = ((const float4*)x)[i];
    uint32_t h0, l0, h1, l1;
    split2(v.x, v.y, h0, l0);
    split2(v.z, v.w, h1, l1);
    uint32_t* hp = (uint32_t*)out;
    uint32_t* lp = (uint32_t*)(out + n);
    hp[2 * i] = h0; hp[2 * i + 1] = h1;
    lp[2 * i] = l0; lp[2 * i + 1] = l1;
}

// ---------------------------------------------------------------------------
// mma.sync GEMM: C[4096, 2048] = (Ahi+Alo)[M,K] @ (Bhi+Blo)[N,K]^T + bias
// MODE 0: fp32 C row-major [M, N].
// MODE 1: bf16 hi/lo C as [b, h, l, d]  (for flash consumption).
// ---------------------------------------------------------------------------
#define TILE_B  8192                 // 128 rows * 64 B
#define STAGE_B (4 * TILE_B)         // Ahi, Alo, Bhi, Blo = 32 KB
#define NSTAGE  3
#define GSMEM_B (NSTAGE * STAGE_B)   // 96 KB
#define NCHUNK  (DMODEL / 32)        // 64

template <int MODE>
__global__ __launch_bounds__(256)
void gemm_mma(const __nv_bfloat16* __restrict__ Ahi,
              const __nv_bfloat16* __restrict__ Alo,
              const __nv_bfloat16* __restrict__ Bhi,
              const __nv_bfloat16* __restrict__ Blo,
              const float* __restrict__ bias, float* __restrict__ C,
              __nv_bfloat16* __restrict__ Ch, __nv_bfloat16* __restrict__ Cl)
{
    extern __shared__ char smb[];
    const uint32_t sbase = smem_u32(smb);

    const int tid = threadIdx.x;
    const int lane = tid & 31;
    const int wid = tid >> 5;
    const int wm = wid & 1;
    const int wn = wid >> 1;
    const int bn = blockIdx.x * 128;
    const int bm = blockIdx.y * 128;

    const int r = tid >> 2;
    const int q = tid & 3;

    auto load_stage = [&](int kc, int s) {
        const int k0 = kc * 32;
        const uint32_t st = sbase + (uint32_t)s * STAGE_B;
        const __nv_bfloat16* srcs[4] = {Ahi, Alo, Bhi, Blo};
        const int row0[4] = {bm, bm, bn, bn};
#pragma unroll
        for (int t = 0; t < 4; t++) {
            const __nv_bfloat16* g0 =
                srcs[t] + (size_t)(row0[t] + r) * DMODEL + k0 + q * 8;
#pragma unroll
            for (int half = 0; half < 2; half++) {
                const int rr = r + half * 64;
                const uint32_t soff = (uint32_t)t * TILE_B + rr * 64 +
                                      ((q ^ ((rr >> 1) & 3)) * 16);
                cp16(st + soff, g0 + (size_t)half * 64 * DMODEL);
            }
        }
    };

    float acc[4][4][4];
#pragma unroll
    for (int i = 0; i < 4; i++)
#pragma unroll
        for (int j = 0; j < 4; j++)
#pragma unroll
            for (int c = 0; c < 4; c++) acc[i][j][c] = 0.f;

    load_stage(0, 0); CP_COMMIT();
    load_stage(1, 1); CP_COMMIT();

    for (int kc = 0; kc < NCHUNK; kc++) {
        const int s = kc % NSTAGE;
        CP_WAIT(1);
        __syncthreads();
        if (kc + 2 < NCHUNK) load_stage(kc + 2, (kc + 2) % NSTAGE);
        CP_COMMIT();

        const uint32_t st = sbase + (uint32_t)s * STAGE_B;
        const uint32_t sAh = st;
        const uint32_t sAl = st + TILE_B;
        const uint32_t sBh = st + 2 * TILE_B;
        const uint32_t sBl = st + 3 * TILE_B;

#pragma unroll
        for (int ks = 0; ks < 2; ks++) {
            uint32_t ah[4][4], al[4][4], bh[4][2], bl[4][2];
#pragma unroll
            for (int mt = 0; mt < 4; mt++) {
                const int row = wm * 64 + mt * 16 + (lane & 15);
                const int kseg = ks * 2 + (lane >> 4);
                const uint32_t off =
                    row * 64 + ((kseg ^ ((row >> 1) & 3)) * 16);
                ldsm_x4(ah[mt], sAh + off);
                ldsm_x4(al[mt], sAl + off);
            }
#pragma unroll
            for (int nt = 0; nt < 4; nt++) {
                const int nrow = wn * 32 + nt * 8 + (lane & 7);
                const int kseg = ks * 2 + ((lane >> 3) & 1);
                const uint32_t off =
                    nrow * 64 + ((kseg ^ ((nrow >> 1) & 3)) * 16);
                ldsm_x2(bh[nt], sBh + off);
                ldsm_x2(bl[nt], sBl + off);
            }
#pragma unroll
            for (int mt = 0; mt < 4; mt++)
#pragma unroll
                for (int nt = 0; nt < 4; nt++) {
                    mma_bf16(acc[mt][nt], ah[mt], bh[nt]);
                    mma_bf16(acc[mt][nt], ah[mt], bl[nt]);
                    mma_bf16(acc[mt][nt], al[mt], bh[nt]);
                }
        }
    }

    // ---- epilogue ----
#pragma unroll
    for (int mt = 0; mt < 4; mt++) {
#pragma unroll
        for (int nt = 0; nt < 4; nt++) {
            const int m0 = bm + wm * 64 + mt * 16 + (lane >> 2);
            const int n0 = bn + wn * 32 + nt * 8 + (lane & 3) * 2;
            const float bia0 = __ldg(&bias[n0]);
            const float bia1 = __ldg(&bias[n0 + 1]);
#pragma unroll
            for (int half = 0; half < 2; half++) {
                const int m = m0 + half * 8;
                const float x0 = acc[mt][nt][half * 2] + bia0;
                const float x1 = acc[mt][nt][half * 2 + 1] + bia1;
                if (MODE == 0) {
                    *(float2*)(C + (size_t)m * DMODEL + n0) =
                        make_float2(x0, x1);
                } else {
                    const int h = bn >> 7;
                    const int b = m >> 11;
                    const int l = m & (LSEQ - 1);
                    const size_t idx =
                        (((size_t)(b * NH + h) * LSEQ + l) * DH) + (n0 & 127);
                    uint32_t hi, lo;
                    split2(x0, x1, hi, lo);
                    *(uint32_t*)(Ch + idx) = hi;
                    *(uint32_t*)(Cl + idx) = lo;
                }
            }
        }
    }
}

// ---------------------------------------------------------------------------
// Flash attention (causal) with mma.sync, hi/lo split numerics.
// CTA = 128 q-rows of one (b,h). 8 warps x m16. ktile = 32 rows.
// Q frags in registers; K/V hi/lo in 3-stage cp.async pipeline.
// Writes output pre-split (hi/lo bf16) in [b, l, D] layout for the Wo GEMM.
// ---------------------------------------------------------------------------
#define NQT (LSEQ / 128)             // 16
#define FQ_B  (128 * 256 * 2)        // Q hi+lo smem: 64 KB (wait, 128*256=32KB ea)
#define FST_B (4 * 32 * 256)         // K hi/lo + V hi/lo per stage: 32 KB
#define FSMEM_B (128 * 256 * 2 + 3 * FST_B)   // 64 KB + 96 KB = 160 KB
#define FSCALE 11.31370849898476f    // sqrt(128)

__global__ __launch_bounds__(256, 1)
void flash_mma(const __nv_bfloat16* __restrict__ Qhi,
               const __nv_bfloat16* __restrict__ Qlo,
               const __nv_bfloat16* __restrict__ Khi,
               const __nv_bfloat16* __restrict__ Klo,
               const __nv_bfloat16* __restrict__ Vhi,
               const __nv_bfloat16* __restrict__ Vlo,
               __nv_bfloat16* __restrict__ Oh,
               __nv_bfloat16* __restrict__ Ol)
{
    extern __shared__ char smb[];
    const uint32_t sbase = smem_u32(smb);
    const uint32_t qlo_s = sbase + 128 * 256;        // Q lo region
    const uint32_t stage0 = sbase + 2 * 128 * 256;   // stages

    const int tid = threadIdx.x;
    const int lane = tid & 31;
    const int w = tid >> 5;

    const int bx = blockIdx.x;
    const int qt = (NQT - 1) - (bx >> 5);   // heavy tiles first
    const int hb = bx & 31;
    const int h = hb & 15;
    const int b = hb >> 4;
    const int bh = b * NH + h;
    const int NKT = 4 * (qt + 1);

    const __nv_bfloat16* qh_g = Qhi + (size_t)bh * LSEQ * DH;
    const __nv_bfloat16* ql_g = Qlo + (size_t)bh * LSEQ * DH;
    const __nv_bfloat16* kh_g = Khi + (size_t)bh * LSEQ * DH;
    const __nv_bfloat16* kl_g = Klo + (size_t)bh * LSEQ * DH;
    const __nv_bfloat16* vh_g = Vhi + (size_t)bh * LSEQ * DH;
    const __nv_bfloat16* vl_g = Vlo + (size_t)bh * LSEQ * DH;

    // ---- Q load (hi+lo, 64 KB): 4096 16B chunks / 256 thr = 16 each ----
    {
#pragma unroll
        for (int j = 0; j < 16; j++) {
            const int c = tid + 256 * j;
            const int t = c >> 11;           // 0 hi, 1 lo
            const int u = c & 2047;
            const int r = u >> 4;
            const int q = u & 15;
            const __nv_bfloat16* src = (t ? ql_g : qh_g) +
                (size_t)(qt * 128 + r) * DH + q * 8;
            cp16(sbase + (uint32_t)t * (128 * 256) + sw256(r, q), src);
        }
        CP_COMMIT();
    }

    // ---- stage loader: K hi/lo + V hi/lo, 32 rows x 128 cols ----
    auto load_stage = [&](int kt, int s) {
        const uint32_t st = stage0 + (uint32_t)s * FST_B;
        const __nv_bfloat16* srcs[4] = {kh_g, kl_g, vh_g, vl_g};
#pragma unroll
        for (int j = 0; j < 8; j++) {
            const int c = tid + 256 * j;
            const int t = c >> 9;
            const int u = c & 511;
            const int r = u >> 4;
            const int q = u & 15;
            const __nv_bfloat16* src =
                srcs[t] + (size_t)(kt * 32 + r) * DH + q * 8;
            cp16(st + (uint32_t)t * (32 * 256) + sw256(r, q), src);
        }
        CP_COMMIT();
    };

    load_stage(0, 0);
    if (NKT > 1) load_stage(1, 1);

    CP_WAIT(2);                      // Q group complete (<=2 stage groups pending)
    __syncthreads();

    // ---- Q frags to registers: 8 ksteps x (hi,lo) x4 ----
    uint32_t qfh[8][4], qfl[8][4];
#pragma unroll
    for (int ks = 0; ks < 8; ks++) {
        const int row = w * 16 + (lane & 15);
        const int q = ks * 2 + (lane >> 4);
        ldsm_x4(qfh[ks], sbase + sw256(row, q));
        ldsm_x4(qfl[ks], qlo_s + sw256(row, q));
    }

    // ---- state ----
    float O[16][4];
#pragma unroll
    for (int nd = 0; nd < 16; nd++)
#pragma unroll
        for (int c = 0; c < 4; c++) O[nd][c] = 0.f;
    float m0 = -3.0e38f, m1 = -3.0e38f, l0 = 0.f, l1 = 0.f;

    const int iq0 = qt * 128 + w * 16 + (lane >> 2);  // row of c0,c1
    const int jcol = (lane & 3) * 2;

    for (int kt = 0; kt < NKT; kt++) {
        if (kt + 1 < NKT) { CP_WAIT(1); } else { CP_WAIT(0); }
        __syncthreads();
        if (kt + 2 < NKT) load_stage(kt + 2, (kt + 2) % 3);

        const uint32_t st = stage0 + (uint32_t)(kt % 3) * FST_B;
        const uint32_t sKh = st;
        const uint32_t sKl = st + 32 * 256;
        const uint32_t sVh = st + 2 * 32 * 256;
        const uint32_t sVl = st + 3 * 32 * 256;

        // ---- S = Q K^T ----
        float S[4][4];
#pragma unroll
        for (int nt = 0; nt < 4; nt++)
#pragma unroll
            for (int c = 0; c < 4; c++) S[nt][c] = 0.f;

#pragma unroll
        for (int ks = 0; ks < 8; ks++) {
            uint32_t kh[4][2], kl[4][2];
#pragma unroll
            for (int nt = 0; nt < 4; nt++) {
                const int row = nt * 8 + (lane & 7);
                const int q = ks * 2 + ((lane >> 3) & 1);
                ldsm_x2(kh[nt], sKh + sw256(row, q));
                ldsm_x2(kl[nt], sKl + sw256(row, q));
            }
#pragma unroll
            for (int nt = 0; nt < 4; nt++) {
                mma_bf16(S[nt], qfh[ks], kh[nt]);
                mma_bf16(S[nt], qfh[ks], kl[nt]);
                mma_bf16(S[nt], qfl[ks], kh[nt]);
            }
        }

        // ---- scale + mask ----
        const bool tilemask = (kt * 32 + 31) > (qt * 128 + w * 16);
#pragma unroll
        for (int nt = 0; nt < 4; nt++) {
#pragma unroll
            for (int c = 0; c < 4; c++) {
                float s = S[nt][c] * FSCALE;
                if (tilemask) {
                    const int i = iq0 + ((c & 2) ? 8 : 0);
                    const int j = kt * 32 + nt * 8 + jcol + (c & 1);
                    if (j > i) s -= 1e7f;
                }
                S[nt][c] = s;
            }
        }

        // ---- online softmax ----
        float tm0 = -3.0e38f, tm1 = -3.0e38f;
#pragma unroll
        for (int nt = 0; nt < 4; nt++) {
            tm0 = fmaxf(tm0, fmaxf(S[nt][0], S[nt][1]));
            tm1 = fmaxf(tm1, fmaxf(S[nt][2], S[nt][3]));
        }
        tm0 = fmaxf(tm0, __shfl_xor_sync(0xffffffffu, tm0, 1));
        tm0 = fmaxf(tm0, __shfl_xor_sync(0xffffffffu, tm0, 2));
        tm1 = fmaxf(tm1, __shfl_xor_sync(0xffffffffu, tm1, 1));
        tm1 = fmaxf(tm1, __shfl_xor_sync(0xffffffffu, tm1, 2));
        const float nm0 = fmaxf(m0, tm0);
        const float nm1 = fmaxf(m1, tm1);
        const float a0 = __expf(m0 - nm0);
        const float a1 = __expf(m1 - nm1);
        m0 = nm0; m1 = nm1;

        float s0 = 0.f, s1 = 0.f;
#pragma unroll
        for (int nt = 0; nt < 4; nt++) {
            S[nt][0] = __expf(S[nt][0] - nm0);
            S[nt][1] = __expf(S[nt][1] - nm0);
            S[nt][2] = __expf(S[nt][2] - nm1);
            S[nt][3] = __expf(S[nt][3] - nm1);
            s0 += S[nt][0] + S[nt][1];
            s1 += S[nt][2] + S[nt][3];
        }
        s0 += __shfl_xor_sync(0xffffffffu, s0, 1);
        s0 += __shfl_xor_sync(0xffffffffu, s0, 2);
        s1 += __shfl_xor_sync(0xffffffffu, s1, 1);
        s1 += __shfl_xor_sync(0xffffffffu, s1, 2);
        l0 = l0 * a0 + s0;
        l1 = l1 * a1 + s1;

#pragma unroll
        for (int nd = 0; nd < 16; nd++) {
            O[nd][0] *= a0; O[nd][1] *= a0;
            O[nd][2] *= a1; O[nd][3] *= a1;
        }

        // ---- O += P V  (P = S frags, hi/lo split) ----
#pragma unroll
        for (int ks2 = 0; ks2 < 2; ks2++) {
            const int nt0 = 2 * ks2, nt1 = nt0 + 1;
            uint32_t ph[4], pl[4];
            split2(S[nt0][0], S[nt0][1], ph[0], pl[0]);
            split2(S[nt0][2], S[nt0][3], ph[1], pl[1]);
            split2(S[nt1][0], S[nt1][1], ph[2], pl[2]);
            split2(S[nt1][2], S[nt1][3], ph[3], pl[3]);
#pragma unroll
            for (int nd = 0; nd < 16; nd++) {
                uint32_t vh[2], vl[2];
                const int row = ks2 * 16 + (lane & 15);
                ldsm_x2t(vh, sVh + sw256(row, nd));
                ldsm_x2t(vl, sVl + sw256(row, nd));
                mma_bf16(O[nd], ph, vh);
                mma_bf16(O[nd], ph, vl);
                mma_bf16(O[nd], pl, vh);
            }
        }
    }

    // ---- epilogue: normalize, split hi/lo, write [b, l, D] ----
    const float inv0 = 1.0f / l0;
    const float inv1 = 1.0f / l1;
    const size_t tok0 = (size_t)b * LSEQ + qt * 128 + w * 16 + (lane >> 2);
    const size_t tok1 = tok0 + 8;
    const int col = h * DH + jcol;
#pragma unroll
    for (int nd = 0; nd < 16; nd++) {
        const int cc = col + nd * 8;
        uint32_t hi, lo;
        split2(O[nd][0] * inv0, O[nd][1] * inv0, hi, lo);
        *(uint32_t*)(Oh + tok0 * DMODEL + cc) = hi;
        *(uint32_t*)(Ol + tok0 * DMODEL + cc) = lo;
        split2(O[nd][2] * inv1, O[nd][3] * inv1, hi, lo);
        *(uint32_t*)(Oh + tok1 * DMODEL + cc) = hi;
        *(uint32_t*)(Ol + tok1 * DMODEL + cc) = lo;
    }
}

// ---------------------------------------------------------------------------
extern "C" void kernel_launch(void* const* d_in, const int* in_sizes, int n_in,
                              void* d_out, int out_size)
{
    (void)in_sizes; (void)n_in; (void)out_size;
    const float* q  = (const float*)d_in[0];
    const float* k  = (const float*)d_in[1];
    const float* v  = (const float*)d_in[2];
    const float* Wq = (const float*)d_in[3];
    const float* bq = (const float*)d_in[4];
    const float* Wk = (const float*)d_in[5];
    const float* bk = (const float*)d_in[6];
    const float* Wv = (const float*)d_in[7];
    const float* bv = (const float*)d_in[8];
    const float* Wo = (const float*)d_in[9];
    const float* bo = (const float*)d_in[10];
    float* out = (float*)d_out;

    __nv_bfloat16 *sq, *sk, *sv, *sa, *qh2, *kh2, *vh2, *swq, *swk, *swv, *swo;
    cudaGetSymbolAddress((void**)&sq, g_sq);
    cudaGetSymbolAddress((void**)&sk, g_sk);
    cudaGetSymbolAddress((void**)&sv, g_sv);
    cudaGetSymbolAddress((void**)&sa, g_sa);
    cudaGetSymbolAddress((void**)&qh2, g_qh2);
    cudaGetSymbolAddress((void**)&kh2, g_kh2);
    cudaGetSymbolAddress((void**)&vh2, g_vh2);
    cudaGetSymbolAddress((void**)&swq, g_swq);
    cudaGetSymbolAddress((void**)&swk, g_swk);
    cudaGetSymbolAddress((void**)&swv, g_swv);
    cudaGetSymbolAddress((void**)&swo, g_swo);

    cudaFuncSetAttribute(gemm_mma<0>, cudaFuncAttributeMaxDynamicSharedMemorySize,
                         GSMEM_B);
    cudaFuncSetAttribute(gemm_mma<1>, cudaFuncAttributeMaxDynamicSharedMemorySize,
                         GSMEM_B);
    cudaFuncSetAttribute(flash_mma, cudaFuncAttributeMaxDynamicSharedMemorySize,
                         FSMEM_B);

    const int actN = (int)ACT_ELEMS, wN = (int)W_ELEMS;
    split_hilo<<<(actN / 4 + 255) / 256, 256>>>(q, sq, actN / 4, actN);
    split_hilo<<<(actN / 4 + 255) / 256, 256>>>(k, sk, actN / 4, actN);
    split_hilo<<<(actN / 4 + 255) / 256, 256>>>(v, sv, actN / 4, actN);
    split_hilo<<<(wN / 4 + 255) / 256, 256>>>(Wq, swq, wN / 4, wN);
    split_hilo<<<(wN / 4 + 255) / 256, 256>>>(Wk, swk, wN / 4, wN);
    split_hilo<<<(wN / 4 + 255) / 256, 256>>>(Wv, swv, wN / 4, wN);
    split_hilo<<<(wN / 4 + 255) / 256, 256>>>(Wo, swo, wN / 4, wN);

    dim3 ggrid(DMODEL / 128, MTOK / 128);   // (16, 32)
    gemm_mma<1><<<ggrid, 256, GSMEM_B>>>(sq, sq + ACT_ELEMS, swq, swq + W_ELEMS,
                                         bq, nullptr, qh2, qh2 + ACT_ELEMS);
    gemm_mma<1><<<ggrid, 256, GSMEM_B>>>(sk, sk + ACT_ELEMS, swk, swk + W_ELEMS,
                                         bk, nullptr, kh2, kh2 + ACT_ELEMS);
    gemm_mma<1><<<ggrid, 256, GSMEM_B>>>(sv, sv + ACT_ELEMS, swv, swv + W_ELEMS,
                                         bv, nullptr, vh2, vh2 + ACT_ELEMS);

    flash_mma<<<NQT * NH * BATCH, 256, FSMEM_B>>>(
        qh2, qh2 + ACT_ELEMS, kh2, kh2 + ACT_ELEMS, vh2, vh2 + ACT_ELEMS,
        sa, sa + ACT_ELEMS);

    gemm_mma<0><<<ggrid, 256, GSMEM_B>>>(sa, sa + ACT_ELEMS, swo, swo + W_ELEMS,
                                         bo, out, nullptr, nullptr);
}

// round 5
// speedup vs baseline: 3.4573x; 1.0862x over previous
#include <cuda_runtime.h>
#include <cuda_bf16.h>
#include <cstdint>

#define LSEQ 2048
#define DMODEL 2048
#define NH 16
#define DH 128
#define BATCH 2
#define MTOK (BATCH * LSEQ)                 // 4096
#define ACT_ELEMS ((size_t)MTOK * DMODEL)   // 8388608
#define W_ELEMS ((size_t)DMODEL * DMODEL)   // 4194304

// ---------------- scratch (static device arrays; no allocs) ----------------
__device__ __nv_bfloat16 g_sq[2 * ACT_ELEMS];
__device__ __nv_bfloat16 g_sk[2 * ACT_ELEMS];
__device__ __nv_bfloat16 g_sv[2 * ACT_ELEMS];
__device__ __nv_bfloat16 g_sa[2 * ACT_ELEMS];
__device__ __nv_bfloat16 g_qh2[2 * ACT_ELEMS];
__device__ __nv_bfloat16 g_kh2[2 * ACT_ELEMS];
__device__ __nv_bfloat16 g_vh2[2 * ACT_ELEMS];
__device__ __nv_bfloat16 g_swq[2 * W_ELEMS];
__device__ __nv_bfloat16 g_swk[2 * W_ELEMS];
__device__ __nv_bfloat16 g_swv[2 * W_ELEMS];
__device__ __nv_bfloat16 g_swo[2 * W_ELEMS];

// ---------------------------- PTX helpers ----------------------------------
__device__ __forceinline__ uint32_t smem_u32(const void* p) {
    uint32_t a;
    asm("{ .reg .u64 t; cvta.to.shared.u64 t, %1; cvt.u32.u64 %0, t; }"
        : "=r"(a) : "l"(p));
    return a;
}

__device__ __forceinline__ void cp16(uint32_t saddr, const void* g) {
    asm volatile("cp.async.cg.shared.global [%0], [%1], 16;"
                 :: "r"(saddr), "l"(g) : "memory");
}
#define CP_COMMIT() asm volatile("cp.async.commit_group;" ::: "memory")
#define CP_WAIT(n)  asm volatile("cp.async.wait_group %0;" :: "n"(n) : "memory")

__device__ __forceinline__ void ldsm_x4(uint32_t* r, uint32_t a) {
    asm volatile("ldmatrix.sync.aligned.m8n8.x4.shared.b16 {%0,%1,%2,%3}, [%4];"
                 : "=r"(r[0]), "=r"(r[1]), "=r"(r[2]), "=r"(r[3]) : "r"(a));
}
__device__ __forceinline__ void ldsm_x4t(uint32_t* r, uint32_t a) {
    asm volatile("ldmatrix.sync.aligned.m8n8.x4.trans.shared.b16 {%0,%1,%2,%3}, [%4];"
                 : "=r"(r[0]), "=r"(r[1]), "=r"(r[2]), "=r"(r[3]) : "r"(a));
}
__device__ __forceinline__ void mma_bf16(float* d, const uint32_t* a,
                                         const uint32_t* b) {
    asm volatile(
        "mma.sync.aligned.m16n8k16.row.col.f32.bf16.bf16.f32 "
        "{%0,%1,%2,%3}, {%4,%5,%6,%7}, {%8,%9}, {%0,%1,%2,%3};"
        : "+f"(d[0]), "+f"(d[1]), "+f"(d[2]), "+f"(d[3])
        : "r"(a[0]), "r"(a[1]), "r"(a[2]), "r"(a[3]), "r"(b[0]), "r"(b[1]));
}

__device__ __forceinline__ void split2(float x, float y,
                                       uint32_t& hi, uint32_t& lo) {
    __nv_bfloat16 hx = __float2bfloat16(x);
    __nv_bfloat16 hy = __float2bfloat16(y);
    __nv_bfloat162 h2; h2.x = hx; h2.y = hy;
    hi = *reinterpret_cast<uint32_t*>(&h2);
    __nv_bfloat162 l2;
    l2.x = __float2bfloat16(x - __bfloat162float(hx));
    l2.y = __float2bfloat16(y - __bfloat162float(hy));
    lo = *reinterpret_cast<uint32_t*>(&l2);
}
__device__ __forceinline__ uint32_t pack2(float x, float y) {
    __nv_bfloat162 h2; h2.x = __float2bfloat16(x); h2.y = __float2bfloat16(y);
    return *reinterpret_cast<uint32_t*>(&h2);
}

__device__ __forceinline__ uint32_t sw256(int r, int q) {
    return (uint32_t)(r * 256 + ((q ^ (r & 7)) << 4));
}

// ---------------------------------------------------------------------------
__global__ __launch_bounds__(256)
void split_hilo(const float* __restrict__ x, __nv_bfloat16* __restrict__ out,
                int n4, int n)
{
    int i = blockIdx.x * blockDim.x + threadIdx.x;
    if (i >= n4) return;
    float4 v = ((const float4*)x)[i];
    uint32_t h0, l0, h1, l1;
    split2(v.x, v.y, h0, l0);
    split2(v.z, v.w, h1, l1);
    uint32_t* hp = (uint32_t*)out;
    uint32_t* lp = (uint32_t*)(out + n);
    hp[2 * i] = h0; hp[2 * i + 1] = h1;
    lp[2 * i] = l0; lp[2 * i + 1] = l1;
}

// ---------------------------------------------------------------------------
// Shared GEMM mainloop pieces (128x128 CTA tile, BK=32, 3-stage cp.async)
// ---------------------------------------------------------------------------
#define TILE_B  8192
#define STAGE_B (4 * TILE_B)
#define NSTAGE  3
#define GSMEM_B (NSTAGE * STAGE_B)
#define NCHUNK  (DMODEL / 32)

struct QKVArgs {
    const __nv_bfloat16* Ah[3];
    const __nv_bfloat16* Al[3];
    const __nv_bfloat16* Bh[3];
    const __nv_bfloat16* Bl[3];
    const float* bias[3];
    __nv_bfloat16* Ch[3];
    __nv_bfloat16* Cl[3];
};

// mainloop macro-ish device function: computes acc[4][4][4] for this CTA
__device__ __forceinline__ void gemm_mainloop(
    const __nv_bfloat16* Ahi, const __nv_bfloat16* Alo,
    const __nv_bfloat16* Bhi, const __nv_bfloat16* Blo,
    int bm, int bn, uint32_t sbase, float acc[4][4][4])
{
    const int tid = threadIdx.x;
    const int lane = tid & 31;
    const int wid = tid >> 5;
    const int wm = wid & 1;
    const int wn = wid >> 1;
    const int r = tid >> 2;
    const int q = tid & 3;

    auto load_stage = [&](int kc, int s) {
        const int k0 = kc * 32;
        const uint32_t st = sbase + (uint32_t)s * STAGE_B;
        const __nv_bfloat16* srcs[4] = {Ahi, Alo, Bhi, Blo};
        const int row0[4] = {bm, bm, bn, bn};
#pragma unroll
        for (int t = 0; t < 4; t++) {
            const __nv_bfloat16* g0 =
                srcs[t] + (size_t)(row0[t] + r) * DMODEL + k0 + q * 8;
#pragma unroll
            for (int half = 0; half < 2; half++) {
                const int rr = r + half * 64;
                const uint32_t soff = (uint32_t)t * TILE_B + rr * 64 +
                                      ((q ^ ((rr >> 1) & 3)) * 16);
                cp16(st + soff, g0 + (size_t)half * 64 * DMODEL);
            }
        }
    };

    load_stage(0, 0); CP_COMMIT();
    load_stage(1, 1); CP_COMMIT();

    for (int kc = 0; kc < NCHUNK; kc++) {
        const int s = kc % NSTAGE;
        CP_WAIT(1);
        __syncthreads();
        if (kc + 2 < NCHUNK) load_stage(kc + 2, (kc + 2) % NSTAGE);
        CP_COMMIT();

        const uint32_t st = sbase + (uint32_t)s * STAGE_B;
        const uint32_t sAh = st;
        const uint32_t sAl = st + TILE_B;
        const uint32_t sBh = st + 2 * TILE_B;
        const uint32_t sBl = st + 3 * TILE_B;

#pragma unroll
        for (int ks = 0; ks < 2; ks++) {
            uint32_t ah[4][4], al[4][4], bh4[2][4], bl4[2][4];
#pragma unroll
            for (int mt = 0; mt < 4; mt++) {
                const int row = wm * 64 + mt * 16 + (lane & 15);
                const int kseg = ks * 2 + (lane >> 4);
                const uint32_t off =
                    row * 64 + ((kseg ^ ((row >> 1) & 3)) * 16);
                ldsm_x4(ah[mt], sAh + off);
                ldsm_x4(al[mt], sAl + off);
            }
#pragma unroll
            for (int p = 0; p < 2; p++) {
                const int nrow = wn * 32 + p * 16 + ((lane >> 4) & 1) * 8 +
                                 (lane & 7);
                const int kseg = ks * 2 + ((lane >> 3) & 1);
                const uint32_t off =
                    nrow * 64 + ((kseg ^ ((nrow >> 1) & 3)) * 16);
                ldsm_x4(bh4[p], sBh + off);
                ldsm_x4(bl4[p], sBl + off);
            }
#pragma unroll
            for (int mt = 0; mt < 4; mt++)
#pragma unroll
                for (int nt = 0; nt < 4; nt++) {
                    const uint32_t* bh = &bh4[nt >> 1][(nt & 1) * 2];
                    const uint32_t* bl = &bl4[nt >> 1][(nt & 1) * 2];
                    mma_bf16(acc[mt][nt], ah[mt], bh);
                    mma_bf16(acc[mt][nt], ah[mt], bl);
                    mma_bf16(acc[mt][nt], al[mt], bh);
                }
        }
    }
}

// fused Q/K/V projection GEMM (blockIdx.z selects tensor); bf16 hi/lo out
__global__ __launch_bounds__(256)
void gemm_qkv(QKVArgs args)
{
    extern __shared__ char smb[];
    const uint32_t sbase = smem_u32(smb);
    const int sel = blockIdx.z;
    const int bn = blockIdx.x * 128;
    const int bm = blockIdx.y * 128;
    const int lane = threadIdx.x & 31;
    const int wid = threadIdx.x >> 5;
    const int wm = wid & 1;
    const int wn = wid >> 1;

    float acc[4][4][4];
#pragma unroll
    for (int i = 0; i < 4; i++)
#pragma unroll
        for (int j = 0; j < 4; j++)
#pragma unroll
            for (int c = 0; c < 4; c++) acc[i][j][c] = 0.f;

    gemm_mainloop(args.Ah[sel], args.Al[sel], args.Bh[sel], args.Bl[sel],
                  bm, bn, sbase, acc);

    const float* bias = args.bias[sel];
    __nv_bfloat16* Ch = args.Ch[sel];
    __nv_bfloat16* Cl = args.Cl[sel];
#pragma unroll
    for (int mt = 0; mt < 4; mt++) {
#pragma unroll
        for (int nt = 0; nt < 4; nt++) {
            const int m0 = bm + wm * 64 + mt * 16 + (lane >> 2);
            const int n0 = bn + wn * 32 + nt * 8 + (lane & 3) * 2;
            const float bia0 = __ldg(&bias[n0]);
            const float bia1 = __ldg(&bias[n0 + 1]);
#pragma unroll
            for (int half = 0; half < 2; half++) {
                const int m = m0 + half * 8;
                const float x0 = acc[mt][nt][half * 2] + bia0;
                const float x1 = acc[mt][nt][half * 2 + 1] + bia1;
                const int h = bn >> 7;
                const int b = m >> 11;
                const int l = m & (LSEQ - 1);
                const size_t idx =
                    (((size_t)(b * NH + h) * LSEQ + l) * DH) + (n0 & 127);
                uint32_t hi, lo;
                split2(x0, x1, hi, lo);
                *(uint32_t*)(Ch + idx) = hi;
                *(uint32_t*)(Cl + idx) = lo;
            }
        }
    }
}

// output projection GEMM: fp32 C row-major
__global__ __launch_bounds__(256)
void gemm_wo(const __nv_bfloat16* __restrict__ Ahi,
             const __nv_bfloat16* __restrict__ Alo,
             const __nv_bfloat16* __restrict__ Bhi,
             const __nv_bfloat16* __restrict__ Blo,
             const float* __restrict__ bias, float* __restrict__ C)
{
    extern __shared__ char smb[];
    const uint32_t sbase = smem_u32(smb);
    const int bn = blockIdx.x * 128;
    const int bm = blockIdx.y * 128;
    const int lane = threadIdx.x & 31;
    const int wid = threadIdx.x >> 5;
    const int wm = wid & 1;
    const int wn = wid >> 1;

    float acc[4][4][4];
#pragma unroll
    for (int i = 0; i < 4; i++)
#pragma unroll
        for (int j = 0; j < 4; j++)
#pragma unroll
            for (int c = 0; c < 4; c++) acc[i][j][c] = 0.f;

    gemm_mainloop(Ahi, Alo, Bhi, Blo, bm, bn, sbase, acc);

#pragma unroll
    for (int mt = 0; mt < 4; mt++) {
#pragma unroll
        for (int nt = 0; nt < 4; nt++) {
            const int m0 = bm + wm * 64 + mt * 16 + (lane >> 2);
            const int n0 = bn + wn * 32 + nt * 8 + (lane & 3) * 2;
            const float bia0 = __ldg(&bias[n0]);
            const float bia1 = __ldg(&bias[n0 + 1]);
#pragma unroll
            for (int half = 0; half < 2; half++) {
                const int m = m0 + half * 8;
                *(float2*)(C + (size_t)m * DMODEL + n0) =
                    make_float2(acc[mt][nt][half * 2] + bia0,
                                acc[mt][nt][half * 2 + 1] + bia1);
            }
        }
    }
}

// ---------------------------------------------------------------------------
// Flash attention (causal), mma.sync. QK: 3-product hi/lo. PV: rounded-P
// single product vs V hi/lo (renormalization cancels P rounding).
// ---------------------------------------------------------------------------
#define NQT (LSEQ / 128)
#define FST_B (4 * 32 * 256)
#define FSMEM_B (128 * 256 * 2 + 3 * FST_B)   // 160 KB
#define FSCALE 11.31370849898476f

__global__ __launch_bounds__(256, 1)
void flash_mma(const __nv_bfloat16* __restrict__ Qhi,
               const __nv_bfloat16* __restrict__ Qlo,
               const __nv_bfloat16* __restrict__ Khi,
               const __nv_bfloat16* __restrict__ Klo,
               const __nv_bfloat16* __restrict__ Vhi,
               const __nv_bfloat16* __restrict__ Vlo,
               __nv_bfloat16* __restrict__ Oh,
               __nv_bfloat16* __restrict__ Ol)
{
    extern __shared__ char smb[];
    const uint32_t sbase = smem_u32(smb);
    const uint32_t qlo_s = sbase + 128 * 256;
    const uint32_t stage0 = sbase + 2 * 128 * 256;

    const int tid = threadIdx.x;
    const int lane = tid & 31;
    const int w = tid >> 5;

    const int bx = blockIdx.x;
    const int qt = (NQT - 1) - (bx >> 5);
    const int hb = bx & 31;
    const int h = hb & 15;
    const int b = hb >> 4;
    const int bh = b * NH + h;
    const int NKT = 4 * (qt + 1);

    const __nv_bfloat16* qh_g = Qhi + (size_t)bh * LSEQ * DH;
    const __nv_bfloat16* ql_g = Qlo + (size_t)bh * LSEQ * DH;
    const __nv_bfloat16* kh_g = Khi + (size_t)bh * LSEQ * DH;
    const __nv_bfloat16* kl_g = Klo + (size_t)bh * LSEQ * DH;
    const __nv_bfloat16* vh_g = Vhi + (size_t)bh * LSEQ * DH;
    const __nv_bfloat16* vl_g = Vlo + (size_t)bh * LSEQ * DH;

    {
#pragma unroll
        for (int j = 0; j < 16; j++) {
            const int c = tid + 256 * j;
            const int t = c >> 11;
            const int u = c & 2047;
            const int r = u >> 4;
            const int q = u & 15;
            const __nv_bfloat16* src = (t ? ql_g : qh_g) +
                (size_t)(qt * 128 + r) * DH + q * 8;
            cp16(sbase + (uint32_t)t * (128 * 256) + sw256(r, q), src);
        }
        CP_COMMIT();
    }

    auto load_stage = [&](int kt, int s) {
        const uint32_t st = stage0 + (uint32_t)s * FST_B;
        const __nv_bfloat16* srcs[4] = {kh_g, kl_g, vh_g, vl_g};
#pragma unroll
        for (int j = 0; j < 8; j++) {
            const int c = tid + 256 * j;
            const int t = c >> 9;
            const int u = c & 511;
            const int r = u >> 4;
            const int q = u & 15;
            const __nv_bfloat16* src =
                srcs[t] + (size_t)(kt * 32 + r) * DH + q * 8;
            cp16(st + (uint32_t)t * (32 * 256) + sw256(r, q), src);
        }
        CP_COMMIT();
    };

    load_stage(0, 0);
    if (NKT > 1) load_stage(1, 1);

    CP_WAIT(2);
    __syncthreads();

    uint32_t qfh[8][4], qfl[8][4];
#pragma unroll
    for (int ks = 0; ks < 8; ks++) {
        const int row = w * 16 + (lane & 15);
        const int q = ks * 2 + (lane >> 4);
        ldsm_x4(qfh[ks], sbase + sw256(row, q));
        ldsm_x4(qfl[ks], qlo_s + sw256(row, q));
    }

    float O[16][4];
#pragma unroll
    for (int nd = 0; nd < 16; nd++)
#pragma unroll
        for (int c = 0; c < 4; c++) O[nd][c] = 0.f;
    float m0 = -3.0e38f, m1 = -3.0e38f, l0 = 0.f, l1 = 0.f;

    const int iq0 = qt * 128 + w * 16 + (lane >> 2);
    const int jcol = (lane & 3) * 2;

    for (int kt = 0; kt < NKT; kt++) {
        if (kt + 1 < NKT) { CP_WAIT(1); } else { CP_WAIT(0); }
        __syncthreads();
        if (kt + 2 < NKT) load_stage(kt + 2, (kt + 2) % 3);

        const uint32_t st = stage0 + (uint32_t)(kt % 3) * FST_B;
        const uint32_t sKh = st;
        const uint32_t sKl = st + 32 * 256;
        const uint32_t sVh = st + 2 * 32 * 256;
        const uint32_t sVl = st + 3 * 32 * 256;

        // ---- S = Q K^T ----
        float S[4][4];
#pragma unroll
        for (int nt = 0; nt < 4; nt++)
#pragma unroll
            for (int c = 0; c < 4; c++) S[nt][c] = 0.f;

#pragma unroll
        for (int ks = 0; ks < 8; ks++) {
            uint32_t kh4[2][4], kl4[2][4];
#pragma unroll
            for (int p = 0; p < 2; p++) {
                const int row = p * 16 + ((lane >> 4) & 1) * 8 + (lane & 7);
                const int q = ks * 2 + ((lane >> 3) & 1);
                ldsm_x4(kh4[p], sKh + sw256(row, q));
                ldsm_x4(kl4[p], sKl + sw256(row, q));
            }
#pragma unroll
            for (int nt = 0; nt < 4; nt++) {
                const uint32_t* kh = &kh4[nt >> 1][(nt & 1) * 2];
                const uint32_t* kl = &kl4[nt >> 1][(nt & 1) * 2];
                mma_bf16(S[nt], qfh[ks], kh);
                mma_bf16(S[nt], qfh[ks], kl);
                mma_bf16(S[nt], qfl[ks], kh);
            }
        }

        // ---- scale + mask ----
        const bool tilemask = (kt * 32 + 31) > (qt * 128 + w * 16);
#pragma unroll
        for (int nt = 0; nt < 4; nt++) {
#pragma unroll
            for (int c = 0; c < 4; c++) {
                float s = S[nt][c] * FSCALE;
                if (tilemask) {
                    const int i = iq0 + ((c & 2) ? 8 : 0);
                    const int j = kt * 32 + nt * 8 + jcol + (c & 1);
                    if (j > i) s -= 1e7f;
                }
                S[nt][c] = s;
            }
        }

        // ---- online softmax (rounded-P bookkeeping) ----
        float tm0 = -3.0e38f, tm1 = -3.0e38f;
#pragma unroll
        for (int nt = 0; nt < 4; nt++) {
            tm0 = fmaxf(tm0, fmaxf(S[nt][0], S[nt][1]));
            tm1 = fmaxf(tm1, fmaxf(S[nt][2], S[nt][3]));
        }
        tm0 = fmaxf(tm0, __shfl_xor_sync(0xffffffffu, tm0, 1));
        tm0 = fmaxf(tm0, __shfl_xor_sync(0xffffffffu, tm0, 2));
        tm1 = fmaxf(tm1, __shfl_xor_sync(0xffffffffu, tm1, 1));
        tm1 = fmaxf(tm1, __shfl_xor_sync(0xffffffffu, tm1, 2));
        const float nm0 = fmaxf(m0, tm0);
        const float nm1 = fmaxf(m1, tm1);
        const float a0 = __expf(m0 - nm0);
        const float a1 = __expf(m1 - nm1);
        m0 = nm0; m1 = nm1;

        float s0 = 0.f, s1 = 0.f;
#pragma unroll
        for (int nt = 0; nt < 4; nt++) {
            // exp, round to bf16, keep ROUNDED values (so l matches P exactly)
            S[nt][0] = __bfloat162float(__float2bfloat16(__expf(S[nt][0] - nm0)));
            S[nt][1] = __bfloat162float(__float2bfloat16(__expf(S[nt][1] - nm0)));
            S[nt][2] = __bfloat162float(__float2bfloat16(__expf(S[nt][2] - nm1)));
            S[nt][3] = __bfloat162float(__float2bfloat16(__expf(S[nt][3] - nm1)));
            s0 += S[nt][0] + S[nt][1];
            s1 += S[nt][2] + S[nt][3];
        }
        s0 += __shfl_xor_sync(0xffffffffu, s0, 1);
        s0 += __shfl_xor_sync(0xffffffffu, s0, 2);
        s1 += __shfl_xor_sync(0xffffffffu, s1, 1);
        s1 += __shfl_xor_sync(0xffffffffu, s1, 2);
        l0 = l0 * a0 + s0;
        l1 = l1 * a1 + s1;

#pragma unroll
        for (int nd = 0; nd < 16; nd++) {
            O[nd][0] *= a0; O[nd][1] *= a0;
            O[nd][2] *= a1; O[nd][3] *= a1;
        }

        // ---- O += P V  (single-product P, V hi/lo) ----
#pragma unroll
        for (int ks2 = 0; ks2 < 2; ks2++) {
            const int nt0 = 2 * ks2, nt1 = nt0 + 1;
            uint32_t ph[4];
            ph[0] = pack2(S[nt0][0], S[nt0][1]);
            ph[1] = pack2(S[nt0][2], S[nt0][3]);
            ph[2] = pack2(S[nt1][0], S[nt1][1]);
            ph[3] = pack2(S[nt1][2], S[nt1][3]);
            const int vrow = ks2 * 16 + (lane & 15);
#pragma unroll
            for (int np = 0; np < 8; np++) {
                uint32_t vh[4], vl[4];
                const int seg = np * 2 + (lane >> 4);
                ldsm_x4t(vh, sVh + sw256(vrow, seg));
                ldsm_x4t(vl, sVl + sw256(vrow, seg));
                mma_bf16(O[2 * np],     ph, vh);
                mma_bf16(O[2 * np],     ph, vl);
                mma_bf16(O[2 * np + 1], ph, vh + 2);
                mma_bf16(O[2 * np + 1], ph, vl + 2);
            }
        }
    }

    // ---- epilogue ----
    const float inv0 = 1.0f / l0;
    const float inv1 = 1.0f / l1;
    const size_t tok0 = (size_t)b * LSEQ + qt * 128 + w * 16 + (lane >> 2);
    const size_t tok1 = tok0 + 8;
    const int col = h * DH + jcol;
#pragma unroll
    for (int nd = 0; nd < 16; nd++) {
        const int cc = col + nd * 8;
        uint32_t hi, lo;
        split2(O[nd][0] * inv0, O[nd][1] * inv0, hi, lo);
        *(uint32_t*)(Oh + tok0 * DMODEL + cc) = hi;
        *(uint32_t*)(Ol + tok0 * DMODEL + cc) = lo;
        split2(O[nd][2] * inv1, O[nd][3] * inv1, hi, lo);
        *(uint32_t*)(Oh + tok1 * DMODEL + cc) = hi;
        *(uint32_t*)(Ol + tok1 * DMODEL + cc) = lo;
    }
}

// ---------------------------------------------------------------------------
extern "C" void kernel_launch(void* const* d_in, const int* in_sizes, int n_in,
                              void* d_out, int out_size)
{
    (void)in_sizes; (void)n_in; (void)out_size;
    const float* q  = (const float*)d_in[0];
    const float* k  = (const float*)d_in[1];
    const float* v  = (const float*)d_in[2];
    const float* Wq = (const float*)d_in[3];
    const float* bq = (const float*)d_in[4];
    const float* Wk = (const float*)d_in[5];
    const float* bk = (const float*)d_in[6];
    const float* Wv = (const float*)d_in[7];
    const float* bv = (const float*)d_in[8];
    const float* Wo = (const float*)d_in[9];
    const float* bo = (const float*)d_in[10];
    float* out = (float*)d_out;

    __nv_bfloat16 *sq, *sk, *sv, *sa, *qh2, *kh2, *vh2, *swq, *swk, *swv, *swo;
    cudaGetSymbolAddress((void**)&sq, g_sq);
    cudaGetSymbolAddress((void**)&sk, g_sk);
    cudaGetSymbolAddress((void**)&sv, g_sv);
    cudaGetSymbolAddress((void**)&sa, g_sa);
    cudaGetSymbolAddress((void**)&qh2, g_qh2);
    cudaGetSymbolAddress((void**)&kh2, g_kh2);
    cudaGetSymbolAddress((void**)&vh2, g_vh2);
    cudaGetSymbolAddress((void**)&swq, g_swq);
    cudaGetSymbolAddress((void**)&swk, g_swk);
    cudaGetSymbolAddress((void**)&swv, g_swv);
    cudaGetSymbolAddress((void**)&swo, g_swo);

    cudaFuncSetAttribute(gemm_qkv, cudaFuncAttributeMaxDynamicSharedMemorySize,
                         GSMEM_B);
    cudaFuncSetAttribute(gemm_wo, cudaFuncAttributeMaxDynamicSharedMemorySize,
                         GSMEM_B);
    cudaFuncSetAttribute(flash_mma, cudaFuncAttributeMaxDynamicSharedMemorySize,
                         FSMEM_B);

    const int actN = (int)ACT_ELEMS, wN = (int)W_ELEMS;
    split_hilo<<<(actN / 4 + 255) / 256, 256>>>(q, sq, actN / 4, actN);
    split_hilo<<<(actN / 4 + 255) / 256, 256>>>(k, sk, actN / 4, actN);
    split_hilo<<<(actN / 4 + 255) / 256, 256>>>(v, sv, actN / 4, actN);
    split_hilo<<<(wN / 4 + 255) / 256, 256>>>(Wq, swq, wN / 4, wN);
    split_hilo<<<(wN / 4 + 255) / 256, 256>>>(Wk, swk, wN / 4, wN);
    split_hilo<<<(wN / 4 + 255) / 256, 256>>>(Wv, swv, wN / 4, wN);
    split_hilo<<<(wN / 4 + 255) / 256, 256>>>(Wo, swo, wN / 4, wN);

    QKVArgs args;
    args.Ah[0] = sq;  args.Al[0] = sq + ACT_ELEMS;
    args.Ah[1] = sk;  args.Al[1] = sk + ACT_ELEMS;
    args.Ah[2] = sv;  args.Al[2] = sv + ACT_ELEMS;
    args.Bh[0] = swq; args.Bl[0] = swq + W_ELEMS;
    args.Bh[1] = swk; args.Bl[1] = swk + W_ELEMS;
    args.Bh[2] = swv; args.Bl[2] = swv + W_ELEMS;
    args.bias[0] = bq; args.bias[1] = bk; args.bias[2] = bv;
    args.Ch[0] = qh2; args.Cl[0] = qh2 + ACT_ELEMS;
    args.Ch[1] = kh2; args.Cl[1] = kh2 + ACT_ELEMS;
    args.Ch[2] = vh2; args.Cl[2] = vh2 + ACT_ELEMS;

    dim3 qkvgrid(DMODEL / 128, MTOK / 128, 3);   // (16, 32, 3)
    gemm_qkv<<<qkvgrid, 256, GSMEM_B>>>(args);

    flash_mma<<<NQT * NH * BATCH, 256, FSMEM_B>>>(
        qh2, qh2 + ACT_ELEMS, kh2, kh2 + ACT_ELEMS, vh2, vh2 + ACT_ELEMS,
        sa, sa + ACT_ELEMS);

    dim3 ggrid(DMODEL / 128, MTOK / 128);
    gemm_wo<<<ggrid, 256, GSMEM_B>>>(sa, sa + ACT_ELEMS, swo, swo + W_ELEMS,
                                     bo, out);
}

// round 6
// speedup vs baseline: 4.3018x; 1.2443x over previous
#include <cuda_runtime.h>
#include <cuda_bf16.h>
#include <cuda_fp16.h>
#include <cstdint>

#define LSEQ 2048
#define DMODEL 2048
#define NH 16
#define DH 128
#define BATCH 2
#define MTOK (BATCH * LSEQ)                 // 4096
#define ACT_ELEMS ((size_t)MTOK * DMODEL)   // 8388608
#define W_ELEMS ((size_t)DMODEL * DMODEL)   // 4194304

// ---------------- scratch (static device arrays; no allocs) ----------------
__device__ __nv_bfloat16 g_sq[2 * ACT_ELEMS];   // q input bf16 hi/lo
__device__ __nv_bfloat16 g_sk[2 * ACT_ELEMS];   // k input bf16 hi/lo
__device__ __half        g_sv[2 * ACT_ELEMS];   // v input fp16 hi/lo
__device__ __half        g_sa[2 * ACT_ELEMS];   // attention out fp16 hi/lo
__device__ __nv_bfloat16 g_qh2[2 * ACT_ELEMS];  // projected Q bf16 hi/lo [b,h,l,d]
__device__ __nv_bfloat16 g_kh2[2 * ACT_ELEMS];  // projected K bf16 hi/lo
__device__ __half        g_vh2[ACT_ELEMS];      // projected V fp16 single
__device__ __nv_bfloat16 g_swq[2 * W_ELEMS];
__device__ __nv_bfloat16 g_swk[2 * W_ELEMS];
__device__ __half        g_swv[W_ELEMS];        // Wv fp16 single
__device__ __half        g_swo[W_ELEMS];        // Wo fp16 single

// ---------------------------- PTX helpers ----------------------------------
__device__ __forceinline__ uint32_t smem_u32(const void* p) {
    uint32_t a;
    asm("{ .reg .u64 t; cvta.to.shared.u64 t, %1; cvt.u32.u64 %0, t; }"
        : "=r"(a) : "l"(p));
    return a;
}

__device__ __forceinline__ void cp16(uint32_t saddr, const void* g) {
    asm volatile("cp.async.cg.shared.global [%0], [%1], 16;"
                 :: "r"(saddr), "l"(g) : "memory");
}
#define CP_COMMIT() asm volatile("cp.async.commit_group;" ::: "memory")
#define CP_WAIT(n)  asm volatile("cp.async.wait_group %0;" :: "n"(n) : "memory")

__device__ __forceinline__ void ldsm_x4(uint32_t* r, uint32_t a) {
    asm volatile("ldmatrix.sync.aligned.m8n8.x4.shared.b16 {%0,%1,%2,%3}, [%4];"
                 : "=r"(r[0]), "=r"(r[1]), "=r"(r[2]), "=r"(r[3]) : "r"(a));
}
__device__ __forceinline__ void ldsm_x4t(uint32_t* r, uint32_t a) {
    asm volatile("ldmatrix.sync.aligned.m8n8.x4.trans.shared.b16 {%0,%1,%2,%3}, [%4];"
                 : "=r"(r[0]), "=r"(r[1]), "=r"(r[2]), "=r"(r[3]) : "r"(a));
}
__device__ __forceinline__ void mma_bf16(float* d, const uint32_t* a,
                                         const uint32_t* b) {
    asm volatile(
        "mma.sync.aligned.m16n8k16.row.col.f32.bf16.bf16.f32 "
        "{%0,%1,%2,%3}, {%4,%5,%6,%7}, {%8,%9}, {%0,%1,%2,%3};"
        : "+f"(d[0]), "+f"(d[1]), "+f"(d[2]), "+f"(d[3])
        : "r"(a[0]), "r"(a[1]), "r"(a[2]), "r"(a[3]), "r"(b[0]), "r"(b[1]));
}
__device__ __forceinline__ void mma_f16(float* d, const uint32_t* a,
                                        const uint32_t* b) {
    asm volatile(
        "mma.sync.aligned.m16n8k16.row.col.f32.f16.f16.f32 "
        "{%0,%1,%2,%3}, {%4,%5,%6,%7}, {%8,%9}, {%0,%1,%2,%3};"
        : "+f"(d[0]), "+f"(d[1]), "+f"(d[2]), "+f"(d[3])
        : "r"(a[0]), "r"(a[1]), "r"(a[2]), "r"(a[3]), "r"(b[0]), "r"(b[1]));
}

__device__ __forceinline__ void split2(float x, float y,
                                       uint32_t& hi, uint32_t& lo) {
    __nv_bfloat16 hx = __float2bfloat16(x);
    __nv_bfloat16 hy = __float2bfloat16(y);
    __nv_bfloat162 h2; h2.x = hx; h2.y = hy;
    hi = *reinterpret_cast<uint32_t*>(&h2);
    __nv_bfloat162 l2;
    l2.x = __float2bfloat16(x - __bfloat162float(hx));
    l2.y = __float2bfloat16(y - __bfloat162float(hy));
    lo = *reinterpret_cast<uint32_t*>(&l2);
}
__device__ __forceinline__ void split2h(float x, float y,
                                        uint32_t& hi, uint32_t& lo) {
    __half hx = __float2half_rn(x);
    __half hy = __float2half_rn(y);
    __half2 h2 = __halves2half2(hx, hy);
    hi = *reinterpret_cast<uint32_t*>(&h2);
    __half2 l2 = __floats2half2_rn(x - __half2float(hx), y - __half2float(hy));
    lo = *reinterpret_cast<uint32_t*>(&l2);
}
__device__ __forceinline__ uint32_t pack2h(float x, float y) {
    __half2 h2 = __floats2half2_rn(x, y);
    return *reinterpret_cast<uint32_t*>(&h2);
}

__device__ __forceinline__ uint32_t sw256(int r, int q) {
    return (uint32_t)(r * 256 + ((q ^ (r & 7)) << 4));
}

// ---------------------------------------------------------------------------
// prep: all 7 input conversions in one launch (blockIdx.z selects job)
// type 0: bf16 hi/lo   type 1: fp16 hi/lo   type 2: fp16 single
// ---------------------------------------------------------------------------
struct PrepArgs {
    const float* src[7];
    void* dst[7];
    int n4[7];
    int n[7];
    int type[7];
};

__global__ __launch_bounds__(256)
void prep(PrepArgs a)
{
    const int z = blockIdx.z;
    const int i = blockIdx.x * 256 + threadIdx.x;
    if (i >= a.n4[z]) return;
    const float4 v = ((const float4*)a.src[z])[i];
    const int n = a.n[z];
    const int ty = a.type[z];
    if (ty == 0) {
        uint32_t h0, l0, h1, l1;
        split2(v.x, v.y, h0, l0);
        split2(v.z, v.w, h1, l1);
        uint32_t* hp = (uint32_t*)a.dst[z];
        uint32_t* lp = (uint32_t*)((__nv_bfloat16*)a.dst[z] + n);
        hp[2 * i] = h0; hp[2 * i + 1] = h1;
        lp[2 * i] = l0; lp[2 * i + 1] = l1;
    } else if (ty == 1) {
        uint32_t h0, l0, h1, l1;
        split2h(v.x, v.y, h0, l0);
        split2h(v.z, v.w, h1, l1);
        uint32_t* hp = (uint32_t*)a.dst[z];
        uint32_t* lp = (uint32_t*)((__half*)a.dst[z] + n);
        hp[2 * i] = h0; hp[2 * i + 1] = h1;
        lp[2 * i] = l0; lp[2 * i + 1] = l1;
    } else {
        uint32_t* hp = (uint32_t*)a.dst[z];
        hp[2 * i]     = pack2h(v.x, v.y);
        hp[2 * i + 1] = pack2h(v.z, v.w);
    }
}

// ---------------------------------------------------------------------------
// GEMM common geometry: 128x128 CTA tile, BK=32, 3-stage cp.async, 8 warps.
// ---------------------------------------------------------------------------
#define TILE_B   8192
#define NSTAGE   3
#define NCHUNK   (DMODEL / 32)
#define STAGE4_B (4 * TILE_B)
#define GS4_B    (NSTAGE * STAGE4_B)       // 96 KB (bf16 3-product)
#define STAGE3_B (3 * TILE_B)
#define GS3_B    (NSTAGE * STAGE3_B)       // 72 KB (fp16 2-product)

// bf16 3-product mainloop: (Ah+Al) x (Bh+Bl), drop Al*Bl
__device__ __forceinline__ void mainloop_bf3(
    const __nv_bfloat16* Ahi, const __nv_bfloat16* Alo,
    const __nv_bfloat16* Bhi, const __nv_bfloat16* Blo,
    int bm, int bn, uint32_t sbase, float acc[4][4][4])
{
    const int tid = threadIdx.x;
    const int lane = tid & 31;
    const int wid = tid >> 5;
    const int wm = wid & 1;
    const int wn = wid >> 1;
    const int r = tid >> 2;
    const int q = tid & 3;

    auto load_stage = [&](int kc, int s) {
        const int k0 = kc * 32;
        const uint32_t st = sbase + (uint32_t)s * STAGE4_B;
        const __nv_bfloat16* srcs[4] = {Ahi, Alo, Bhi, Blo};
        const int row0[4] = {bm, bm, bn, bn};
#pragma unroll
        for (int t = 0; t < 4; t++) {
            const __nv_bfloat16* g0 =
                srcs[t] + (size_t)(row0[t] + r) * DMODEL + k0 + q * 8;
#pragma unroll
            for (int half = 0; half < 2; half++) {
                const int rr = r + half * 64;
                const uint32_t soff = (uint32_t)t * TILE_B + rr * 64 +
                                      ((q ^ ((rr >> 1) & 3)) * 16);
                cp16(st + soff, g0 + (size_t)half * 64 * DMODEL);
            }
        }
    };

    load_stage(0, 0); CP_COMMIT();
    load_stage(1, 1); CP_COMMIT();

    for (int kc = 0; kc < NCHUNK; kc++) {
        const int s = kc % NSTAGE;
        CP_WAIT(1);
        __syncthreads();
        if (kc + 2 < NCHUNK) load_stage(kc + 2, (kc + 2) % NSTAGE);
        CP_COMMIT();

        const uint32_t st = sbase + (uint32_t)s * STAGE4_B;
        const uint32_t sAh = st;
        const uint32_t sAl = st + TILE_B;
        const uint32_t sBh = st + 2 * TILE_B;
        const uint32_t sBl = st + 3 * TILE_B;

#pragma unroll
        for (int ks = 0; ks < 2; ks++) {
            uint32_t ah[4][4], al[4][4], bh4[2][4], bl4[2][4];
#pragma unroll
            for (int mt = 0; mt < 4; mt++) {
                const int row = wm * 64 + mt * 16 + (lane & 15);
                const int kseg = ks * 2 + (lane >> 4);
                const uint32_t off =
                    row * 64 + ((kseg ^ ((row >> 1) & 3)) * 16);
                ldsm_x4(ah[mt], sAh + off);
                ldsm_x4(al[mt], sAl + off);
            }
#pragma unroll
            for (int p = 0; p < 2; p++) {
                const int nrow = wn * 32 + p * 16 + ((lane >> 4) & 1) * 8 +
                                 (lane & 7);
                const int kseg = ks * 2 + ((lane >> 3) & 1);
                const uint32_t off =
                    nrow * 64 + ((kseg ^ ((nrow >> 1) & 3)) * 16);
                ldsm_x4(bh4[p], sBh + off);
                ldsm_x4(bl4[p], sBl + off);
            }
#pragma unroll
            for (int mt = 0; mt < 4; mt++)
#pragma unroll
                for (int nt = 0; nt < 4; nt++) {
                    const uint32_t* bh = &bh4[nt >> 1][(nt & 1) * 2];
                    const uint32_t* bl = &bl4[nt >> 1][(nt & 1) * 2];
                    mma_bf16(acc[mt][nt], ah[mt], bh);
                    mma_bf16(acc[mt][nt], ah[mt], bl);
                    mma_bf16(acc[mt][nt], al[mt], bh);
                }
        }
    }
}

// fp16 2-product mainloop: (Ah+Al) x B   (error = A x (B - fp16(B)))
__device__ __forceinline__ void mainloop_h2(
    const __half* Ahi, const __half* Alo, const __half* B,
    int bm, int bn, uint32_t sbase, float acc[4][4][4])
{
    const int tid = threadIdx.x;
    const int lane = tid & 31;
    const int wid = tid >> 5;
    const int wm = wid & 1;
    const int wn = wid >> 1;
    const int r = tid >> 2;
    const int q = tid & 3;

    auto load_stage = [&](int kc, int s) {
        const int k0 = kc * 32;
        const uint32_t st = sbase + (uint32_t)s * STAGE3_B;
        const __half* srcs[3] = {Ahi, Alo, B};
        const int row0[3] = {bm, bm, bn};
#pragma unroll
        for (int t = 0; t < 3; t++) {
            const __half* g0 =
                srcs[t] + (size_t)(row0[t] + r) * DMODEL + k0 + q * 8;
#pragma unroll
            for (int half = 0; half < 2; half++) {
                const int rr = r + half * 64;
                const uint32_t soff = (uint32_t)t * TILE_B + rr * 64 +
                                      ((q ^ ((rr >> 1) & 3)) * 16);
                cp16(st + soff, g0 + (size_t)half * 64 * DMODEL);
            }
        }
    };

    load_stage(0, 0); CP_COMMIT();
    load_stage(1, 1); CP_COMMIT();

    for (int kc = 0; kc < NCHUNK; kc++) {
        const int s = kc % NSTAGE;
        CP_WAIT(1);
        __syncthreads();
        if (kc + 2 < NCHUNK) load_stage(kc + 2, (kc + 2) % NSTAGE);
        CP_COMMIT();

        const uint32_t st = sbase + (uint32_t)s * STAGE3_B;
        const uint32_t sAh = st;
        const uint32_t sAl = st + TILE_B;
        const uint32_t sB  = st + 2 * TILE_B;

#pragma unroll
        for (int ks = 0; ks < 2; ks++) {
            uint32_t ah[4][4], al[4][4], b4[2][4];
#pragma unroll
            for (int mt = 0; mt < 4; mt++) {
                const int row = wm * 64 + mt * 16 + (lane & 15);
                const int kseg = ks * 2 + (lane >> 4);
                const uint32_t off =
                    row * 64 + ((kseg ^ ((row >> 1) & 3)) * 16);
                ldsm_x4(ah[mt], sAh + off);
                ldsm_x4(al[mt], sAl + off);
            }
#pragma unroll
            for (int p = 0; p < 2; p++) {
                const int nrow = wn * 32 + p * 16 + ((lane >> 4) & 1) * 8 +
                                 (lane & 7);
                const int kseg = ks * 2 + ((lane >> 3) & 1);
                const uint32_t off =
                    nrow * 64 + ((kseg ^ ((nrow >> 1) & 3)) * 16);
                ldsm_x4(b4[p], sB + off);
            }
#pragma unroll
            for (int mt = 0; mt < 4; mt++)
#pragma unroll
                for (int nt = 0; nt < 4; nt++) {
                    const uint32_t* b = &b4[nt >> 1][(nt & 1) * 2];
                    mma_f16(acc[mt][nt], ah[mt], b);
                    mma_f16(acc[mt][nt], al[mt], b);
                }
        }
    }
}

// ---------------------------------------------------------------------------
// Q/K projection GEMM (fused, blockIdx.z selects); bf16 hi/lo out [b,h,l,d]
// ---------------------------------------------------------------------------
struct QKArgs {
    const __nv_bfloat16* Ah[2];
    const __nv_bfloat16* Al[2];
    const __nv_bfloat16* Bh[2];
    const __nv_bfloat16* Bl[2];
    const float* bias[2];
    __nv_bfloat16* Ch[2];
    __nv_bfloat16* Cl[2];
};

__global__ __launch_bounds__(256)
void gemm_qk(QKArgs args)
{
    extern __shared__ char smb[];
    const uint32_t sbase = smem_u32(smb);
    const int sel = blockIdx.z;
    const int bn = blockIdx.x * 128;
    const int bm = blockIdx.y * 128;
    const int lane = threadIdx.x & 31;
    const int wid = threadIdx.x >> 5;
    const int wm = wid & 1;
    const int wn = wid >> 1;

    float acc[4][4][4];
#pragma unroll
    for (int i = 0; i < 4; i++)
#pragma unroll
        for (int j = 0; j < 4; j++)
#pragma unroll
            for (int c = 0; c < 4; c++) acc[i][j][c] = 0.f;

    mainloop_bf3(args.Ah[sel], args.Al[sel], args.Bh[sel], args.Bl[sel],
                 bm, bn, sbase, acc);

    const float* bias = args.bias[sel];
    __nv_bfloat16* Ch = args.Ch[sel];
    __nv_bfloat16* Cl = args.Cl[sel];
#pragma unroll
    for (int mt = 0; mt < 4; mt++) {
#pragma unroll
        for (int nt = 0; nt < 4; nt++) {
            const int m0 = bm + wm * 64 + mt * 16 + (lane >> 2);
            const int n0 = bn + wn * 32 + nt * 8 + (lane & 3) * 2;
            const float bia0 = __ldg(&bias[n0]);
            const float bia1 = __ldg(&bias[n0 + 1]);
#pragma unroll
            for (int half = 0; half < 2; half++) {
                const int m = m0 + half * 8;
                const float x0 = acc[mt][nt][half * 2] + bia0;
                const float x1 = acc[mt][nt][half * 2 + 1] + bia1;
                const int h = bn >> 7;
                const int b = m >> 11;
                const int l = m & (LSEQ - 1);
                const size_t idx =
                    (((size_t)(b * NH + h) * LSEQ + l) * DH) + (n0 & 127);
                uint32_t hi, lo;
                split2(x0, x1, hi, lo);
                *(uint32_t*)(Ch + idx) = hi;
                *(uint32_t*)(Cl + idx) = lo;
            }
        }
    }
}

// ---------------------------------------------------------------------------
// V projection: A fp16 hi/lo x Wv fp16, 2-product; fp16 single out [b,h,l,d]
// ---------------------------------------------------------------------------
__global__ __launch_bounds__(256)
void gemm_v(const __half* __restrict__ Ahi, const __half* __restrict__ Alo,
            const __half* __restrict__ B, const float* __restrict__ bias,
            __half* __restrict__ C)
{
    extern __shared__ char smb[];
    const uint32_t sbase = smem_u32(smb);
    const int bn = blockIdx.x * 128;
    const int bm = blockIdx.y * 128;
    const int lane = threadIdx.x & 31;
    const int wid = threadIdx.x >> 5;
    const int wm = wid & 1;
    const int wn = wid >> 1;

    float acc[4][4][4];
#pragma unroll
    for (int i = 0; i < 4; i++)
#pragma unroll
        for (int j = 0; j < 4; j++)
#pragma unroll
            for (int c = 0; c < 4; c++) acc[i][j][c] = 0.f;

    mainloop_h2(Ahi, Alo, B, bm, bn, sbase, acc);

#pragma unroll
    for (int mt = 0; mt < 4; mt++) {
#pragma unroll
        for (int nt = 0; nt < 4; nt++) {
            const int m0 = bm + wm * 64 + mt * 16 + (lane >> 2);
            const int n0 = bn + wn * 32 + nt * 8 + (lane & 3) * 2;
            const float bia0 = __ldg(&bias[n0]);
            const float bia1 = __ldg(&bias[n0 + 1]);
#pragma unroll
            for (int half = 0; half < 2; half++) {
                const int m = m0 + half * 8;
                const int h = bn >> 7;
                const int b = m >> 11;
                const int l = m & (LSEQ - 1);
                const size_t idx =
                    (((size_t)(b * NH + h) * LSEQ + l) * DH) + (n0 & 127);
                *(uint32_t*)(C + idx) =
                    pack2h(acc[mt][nt][half * 2] + bia0,
                           acc[mt][nt][half * 2 + 1] + bia1);
            }
        }
    }
}

// ---------------------------------------------------------------------------
// Output projection: A (attn out) fp16 hi/lo x Wo fp16, 2-product; fp32 out
// ---------------------------------------------------------------------------
__global__ __launch_bounds__(256)
void gemm_wo(const __half* __restrict__ Ahi, const __half* __restrict__ Alo,
             const __half* __restrict__ B, const float* __restrict__ bias,
             float* __restrict__ C)
{
    extern __shared__ char smb[];
    const uint32_t sbase = smem_u32(smb);
    const int bn = blockIdx.x * 128;
    const int bm = blockIdx.y * 128;
    const int lane = threadIdx.x & 31;
    const int wid = threadIdx.x >> 5;
    const int wm = wid & 1;
    const int wn = wid >> 1;

    float acc[4][4][4];
#pragma unroll
    for (int i = 0; i < 4; i++)
#pragma unroll
        for (int j = 0; j < 4; j++)
#pragma unroll
            for (int c = 0; c < 4; c++) acc[i][j][c] = 0.f;

    mainloop_h2(Ahi, Alo, B, bm, bn, sbase, acc);

#pragma unroll
    for (int mt = 0; mt < 4; mt++) {
#pragma unroll
        for (int nt = 0; nt < 4; nt++) {
            const int m0 = bm + wm * 64 + mt * 16 + (lane >> 2);
            const int n0 = bn + wn * 32 + nt * 8 + (lane & 3) * 2;
            const float bia0 = __ldg(&bias[n0]);
            const float bia1 = __ldg(&bias[n0 + 1]);
#pragma unroll
            for (int half = 0; half < 2; half++) {
                const int m = m0 + half * 8;
                *(float2*)(C + (size_t)m * DMODEL + n0) =
                    make_float2(acc[mt][nt][half * 2] + bia0,
                                acc[mt][nt][half * 2 + 1] + bia1);
            }
        }
    }
}

// ---------------------------------------------------------------------------
// Flash attention (causal). QK: bf16 hi/lo 3-product. PV: fp16 P x fp16 V,
// single product (l summed from rounded P cancels common-mode rounding).
// Stage = Kh, Kl (bf16) + V (fp16) = 24 KB; 4-stage pipeline.
// Output: fp16 hi/lo [b, l, D] for the Wo GEMM.
// ---------------------------------------------------------------------------
#define NQT (LSEQ / 128)
#define FST_B (3 * 32 * 256)                     // 24 KB
#define FSMEM_B (2 * 128 * 256 + 4 * FST_B)      // 64 + 96 = 160 KB
#define FSCALE 11.31370849898476f

__global__ __launch_bounds__(256, 1)
void flash_mma(const __nv_bfloat16* __restrict__ Qhi,
               const __nv_bfloat16* __restrict__ Qlo,
               const __nv_bfloat16* __restrict__ Khi,
               const __nv_bfloat16* __restrict__ Klo,
               const __half* __restrict__ V,
               __half* __restrict__ Oh,
               __half* __restrict__ Ol)
{
    extern __shared__ char smb[];
    const uint32_t sbase = smem_u32(smb);
    const uint32_t qlo_s = sbase + 128 * 256;
    const uint32_t stage0 = sbase + 2 * 128 * 256;

    const int tid = threadIdx.x;
    const int lane = tid & 31;
    const int w = tid >> 5;

    const int bx = blockIdx.x;
    const int qt = (NQT - 1) - (bx >> 5);
    const int hb = bx & 31;
    const int h = hb & 15;
    const int b = hb >> 4;
    const int bh = b * NH + h;
    const int NKT = 4 * (qt + 1);              // >= 4

    const __nv_bfloat16* qh_g = Qhi + (size_t)bh * LSEQ * DH;
    const __nv_bfloat16* ql_g = Qlo + (size_t)bh * LSEQ * DH;
    const __nv_bfloat16* kh_g = Khi + (size_t)bh * LSEQ * DH;
    const __nv_bfloat16* kl_g = Klo + (size_t)bh * LSEQ * DH;
    const __half*        v_g  = V   + (size_t)bh * LSEQ * DH;

    // ---- Q load (bf16 hi/lo, 64 KB) ----
    {
#pragma unroll
        for (int j = 0; j < 16; j++) {
            const int c = tid + 256 * j;
            const int t = c >> 11;
            const int u = c & 2047;
            const int r = u >> 4;
            const int q = u & 15;
            const __nv_bfloat16* src = (t ? ql_g : qh_g) +
                (size_t)(qt * 128 + r) * DH + q * 8;
            cp16(sbase + (uint32_t)t * (128 * 256) + sw256(r, q), src);
        }
        CP_COMMIT();
    }

    // ---- stage loader: Kh, Kl, V (32 rows x 128 cols each) ----
    auto load_stage = [&](int kt, int s) {
        const uint32_t st = stage0 + (uint32_t)s * FST_B;
#pragma unroll
        for (int j = 0; j < 6; j++) {
            const int c = tid + 256 * j;       // 0..1535
            const int t = c >> 9;              // 0 Kh, 1 Kl, 2 V
            const int u = c & 511;
            const int r = u >> 4;
            const int q = u & 15;
            const char* src =
                (t == 0 ? (const char*)kh_g :
                 t == 1 ? (const char*)kl_g : (const char*)v_g) +
                ((size_t)(kt * 32 + r) * DH + q * 8) * 2;
            cp16(st + (uint32_t)t * 8192 + sw256(r, q), src);
        }
        CP_COMMIT();
    };

    load_stage(0, 0);
    load_stage(1, 1);
    load_stage(2, 2);

    CP_WAIT(2);                  // Q + stage0 complete
    __syncthreads();

    uint32_t qfh[8][4], qfl[8][4];
#pragma unroll
    for (int ks = 0; ks < 8; ks++) {
        const int row = w * 16 + (lane & 15);
        const int q = ks * 2 + (lane >> 4);
        ldsm_x4(qfh[ks], sbase + sw256(row, q));
        ldsm_x4(qfl[ks], qlo_s + sw256(row, q));
    }

    float O[16][4];
#pragma unroll
    for (int nd = 0; nd < 16; nd++)
#pragma unroll
        for (int c = 0; c < 4; c++) O[nd][c] = 0.f;
    float m0 = -3.0e38f, m1 = -3.0e38f, l0 = 0.f, l1 = 0.f;

    const int iq0 = qt * 128 + w * 16 + (lane >> 2);
    const int jcol = (lane & 3) * 2;

    for (int kt = 0; kt < NKT; kt++) {
        if (kt + 2 < NKT) { CP_WAIT(2); }
        else if (kt + 1 < NKT) { CP_WAIT(1); }
        else { CP_WAIT(0); }
        __syncthreads();
        if (kt + 3 < NKT) load_stage(kt + 3, (kt + 3) & 3);

        const uint32_t st = stage0 + (uint32_t)(kt & 3) * FST_B;
        const uint32_t sKh = st;
        const uint32_t sKl = st + 8192;
        const uint32_t sV  = st + 16384;

        // ---- S = Q K^T (3-product bf16) ----
        float S[4][4];
#pragma unroll
        for (int nt = 0; nt < 4; nt++)
#pragma unroll
            for (int c = 0; c < 4; c++) S[nt][c] = 0.f;

#pragma unroll
        for (int ks = 0; ks < 8; ks++) {
            uint32_t kh4[2][4], kl4[2][4];
#pragma unroll
            for (int p = 0; p < 2; p++) {
                const int row = p * 16 + ((lane >> 4) & 1) * 8 + (lane & 7);
                const int q = ks * 2 + ((lane >> 3) & 1);
                ldsm_x4(kh4[p], sKh + sw256(row, q));
                ldsm_x4(kl4[p], sKl + sw256(row, q));
            }
#pragma unroll
            for (int nt = 0; nt < 4; nt++) {
                const uint32_t* kh = &kh4[nt >> 1][(nt & 1) * 2];
                const uint32_t* kl = &kl4[nt >> 1][(nt & 1) * 2];
                mma_bf16(S[nt], qfh[ks], kh);
                mma_bf16(S[nt], qfh[ks], kl);
                mma_bf16(S[nt], qfl[ks], kh);
            }
        }

        // ---- scale + mask ----
        const bool tilemask = (kt * 32 + 31) > (qt * 128 + w * 16);
#pragma unroll
        for (int nt = 0; nt < 4; nt++) {
#pragma unroll
            for (int c = 0; c < 4; c++) {
                float s = S[nt][c] * FSCALE;
                if (tilemask) {
                    const int i = iq0 + ((c & 2) ? 8 : 0);
                    const int j = kt * 32 + nt * 8 + jcol + (c & 1);
                    if (j > i) s -= 1e7f;
                }
                S[nt][c] = s;
            }
        }

        // ---- online softmax (fp16-rounded P bookkeeping) ----
        float tm0 = -3.0e38f, tm1 = -3.0e38f;
#pragma unroll
        for (int nt = 0; nt < 4; nt++) {
            tm0 = fmaxf(tm0, fmaxf(S[nt][0], S[nt][1]));
            tm1 = fmaxf(tm1, fmaxf(S[nt][2], S[nt][3]));
        }
        tm0 = fmaxf(tm0, __shfl_xor_sync(0xffffffffu, tm0, 1));
        tm0 = fmaxf(tm0, __shfl_xor_sync(0xffffffffu, tm0, 2));
        tm1 = fmaxf(tm1, __shfl_xor_sync(0xffffffffu, tm1, 1));
        tm1 = fmaxf(tm1, __shfl_xor_sync(0xffffffffu, tm1, 2));
        const float nm0 = fmaxf(m0, tm0);
        const float nm1 = fmaxf(m1, tm1);
        const float a0 = __expf(m0 - nm0);
        const float a1 = __expf(m1 - nm1);
        m0 = nm0; m1 = nm1;

        float s0 = 0.f, s1 = 0.f;
#pragma unroll
        for (int nt = 0; nt < 4; nt++) {
            S[nt][0] = __half2float(__float2half_rn(__expf(S[nt][0] - nm0)));
            S[nt][1] = __half2float(__float2half_rn(__expf(S[nt][1] - nm0)));
            S[nt][2] = __half2float(__float2half_rn(__expf(S[nt][2] - nm1)));
            S[nt][3] = __half2float(__float2half_rn(__expf(S[nt][3] - nm1)));
            s0 += S[nt][0] + S[nt][1];
            s1 += S[nt][2] + S[nt][3];
        }
        s0 += __shfl_xor_sync(0xffffffffu, s0, 1);
        s0 += __shfl_xor_sync(0xffffffffu, s0, 2);
        s1 += __shfl_xor_sync(0xffffffffu, s1, 1);
        s1 += __shfl_xor_sync(0xffffffffu, s1, 2);
        l0 = l0 * a0 + s0;
        l1 = l1 * a1 + s1;

#pragma unroll
        for (int nd = 0; nd < 16; nd++) {
            O[nd][0] *= a0; O[nd][1] *= a0;
            O[nd][2] *= a1; O[nd][3] *= a1;
        }

        // ---- O += P V  (single fp16 product) ----
#pragma unroll
        for (int ks2 = 0; ks2 < 2; ks2++) {
            const int nt0 = 2 * ks2, nt1 = nt0 + 1;
            uint32_t ph[4];
            ph[0] = pack2h(S[nt0][0], S[nt0][1]);
            ph[1] = pack2h(S[nt0][2], S[nt0][3]);
            ph[2] = pack2h(S[nt1][0], S[nt1][1]);
            ph[3] = pack2h(S[nt1][2], S[nt1][3]);
            const int vrow = ks2 * 16 + (lane & 15);
#pragma unroll
            for (int np = 0; np < 8; np++) {
                uint32_t vv[4];
                const int seg = np * 2 + (lane >> 4);
                ldsm_x4t(vv, sV + sw256(vrow, seg));
                mma_f16(O[2 * np],     ph, vv);
                mma_f16(O[2 * np + 1], ph, vv + 2);
            }
        }
    }

    // ---- epilogue: normalize, fp16 hi/lo split, write [b, l, D] ----
    const float inv0 = 1.0f / l0;
    const float inv1 = 1.0f / l1;
    const size_t tok0 = (size_t)b * LSEQ + qt * 128 + w * 16 + (lane >> 2);
    const size_t tok1 = tok0 + 8;
    const int col = h * DH + jcol;
#pragma unroll
    for (int nd = 0; nd < 16; nd++) {
        const int cc = col + nd * 8;
        uint32_t hi, lo;
        split2h(O[nd][0] * inv0, O[nd][1] * inv0, hi, lo);
        *(uint32_t*)(Oh + tok0 * DMODEL + cc) = hi;
        *(uint32_t*)(Ol + tok0 * DMODEL + cc) = lo;
        split2h(O[nd][2] * inv1, O[nd][3] * inv1, hi, lo);
        *(uint32_t*)(Oh + tok1 * DMODEL + cc) = hi;
        *(uint32_t*)(Ol + tok1 * DMODEL + cc) = lo;
    }
}

// ---------------------------------------------------------------------------
extern "C" void kernel_launch(void* const* d_in, const int* in_sizes, int n_in,
                              void* d_out, int out_size)
{
    (void)in_sizes; (void)n_in; (void)out_size;
    const float* q  = (const float*)d_in[0];
    const float* k  = (const float*)d_in[1];
    const float* v  = (const float*)d_in[2];
    const float* Wq = (const float*)d_in[3];
    const float* bq = (const float*)d_in[4];
    const float* Wk = (const float*)d_in[5];
    const float* bk = (const float*)d_in[6];
    const float* Wv = (const float*)d_in[7];
    const float* bv = (const float*)d_in[8];
    const float* Wo = (const float*)d_in[9];
    const float* bo = (const float*)d_in[10];
    float* out = (float*)d_out;

    __nv_bfloat16 *sq, *sk, *qh2, *kh2, *swq, *swk;
    __half *sv, *sa, *vh2, *swv, *swo;
    cudaGetSymbolAddress((void**)&sq, g_sq);
    cudaGetSymbolAddress((void**)&sk, g_sk);
    cudaGetSymbolAddress((void**)&sv, g_sv);
    cudaGetSymbolAddress((void**)&sa, g_sa);
    cudaGetSymbolAddress((void**)&qh2, g_qh2);
    cudaGetSymbolAddress((void**)&kh2, g_kh2);
    cudaGetSymbolAddress((void**)&vh2, g_vh2);
    cudaGetSymbolAddress((void**)&swq, g_swq);
    cudaGetSymbolAddress((void**)&swk, g_swk);
    cudaGetSymbolAddress((void**)&swv, g_swv);
    cudaGetSymbolAddress((void**)&swo, g_swo);

    cudaFuncSetAttribute(gemm_qk, cudaFuncAttributeMaxDynamicSharedMemorySize,
                         GS4_B);
    cudaFuncSetAttribute(gemm_v, cudaFuncAttributeMaxDynamicSharedMemorySize,
                         GS3_B);
    cudaFuncSetAttribute(gemm_wo, cudaFuncAttributeMaxDynamicSharedMemorySize,
                         GS3_B);
    cudaFuncSetAttribute(flash_mma, cudaFuncAttributeMaxDynamicSharedMemorySize,
                         FSMEM_B);

    // ---- prep: all conversions in one launch ----
    PrepArgs pa;
    pa.src[0] = q;  pa.dst[0] = sq;  pa.n[0] = (int)ACT_ELEMS; pa.type[0] = 0;
    pa.src[1] = k;  pa.dst[1] = sk;  pa.n[1] = (int)ACT_ELEMS; pa.type[1] = 0;
    pa.src[2] = v;  pa.dst[2] = sv;  pa.n[2] = (int)ACT_ELEMS; pa.type[2] = 1;
    pa.src[3] = Wq; pa.dst[3] = swq; pa.n[3] = (int)W_ELEMS;   pa.type[3] = 0;
    pa.src[4] = Wk; pa.dst[4] = swk; pa.n[4] = (int)W_ELEMS;   pa.type[4] = 0;
    pa.src[5] = Wv; pa.dst[5] = swv; pa.n[5] = (int)W_ELEMS;   pa.type[5] = 2;
    pa.src[6] = Wo; pa.dst[6] = swo; pa.n[6] = (int)W_ELEMS;   pa.type[6] = 2;
    for (int i = 0; i < 7; i++) pa.n4[i] = pa.n[i] / 4;
    prep<<<dim3((int)(ACT_ELEMS / 4 / 256), 1, 7), 256>>>(pa);

    // ---- Q/K projections (bf16 3-product) ----
    QKArgs qa;
    qa.Ah[0] = sq;  qa.Al[0] = sq + ACT_ELEMS;
    qa.Ah[1] = sk;  qa.Al[1] = sk + ACT_ELEMS;
    qa.Bh[0] = swq; qa.Bl[0] = swq + W_ELEMS;
    qa.Bh[1] = swk; qa.Bl[1] = swk + W_ELEMS;
    qa.bias[0] = bq; qa.bias[1] = bk;
    qa.Ch[0] = qh2; qa.Cl[0] = qh2 + ACT_ELEMS;
    qa.Ch[1] = kh2; qa.Cl[1] = kh2 + ACT_ELEMS;
    gemm_qk<<<dim3(DMODEL / 128, MTOK / 128, 2), 256, GS4_B>>>(qa);

    // ---- V projection (fp16 2-product) ----
    gemm_v<<<dim3(DMODEL / 128, MTOK / 128), 256, GS3_B>>>(
        sv, sv + ACT_ELEMS, swv, bv, vh2);

    // ---- attention ----
    flash_mma<<<NQT * NH * BATCH, 256, FSMEM_B>>>(
        qh2, qh2 + ACT_ELEMS, kh2, kh2 + ACT_ELEMS, vh2,
        sa, sa + ACT_ELEMS);

    // ---- output projection (fp16 2-product) ----
    gemm_wo<<<dim3(DMODEL / 128, MTOK / 128), 256, GS3_B>>>(
        sa, sa + ACT_ELEMS, swo, bo, out);
}

// round 7
// speedup vs baseline: 5.0017x; 1.1627x over previous
#include <cuda_runtime.h>
#include <cuda_bf16.h>
#include <cuda_fp16.h>
#include <cstdint>

#define LSEQ 2048
#define DMODEL 2048
#define NH 16
#define DH 128
#define BATCH 2
#define MTOK (BATCH * LSEQ)                 // 4096
#define ACT_ELEMS ((size_t)MTOK * DMODEL)   // 8388608
#define W_ELEMS ((size_t)DMODEL * DMODEL)   // 4194304

// ---------------- scratch (static device arrays; no allocs) ----------------
__device__ __nv_bfloat16 g_sq[2 * ACT_ELEMS];   // q input bf16 hi/lo
__device__ __nv_bfloat16 g_sk[2 * ACT_ELEMS];   // k input bf16 hi/lo
__device__ __half        g_sv[ACT_ELEMS];       // v input fp16 single
__device__ __half        g_sa[ACT_ELEMS];       // attention out fp16 single
__device__ __nv_bfloat16 g_qh2[2 * ACT_ELEMS];  // projected Q bf16 hi/lo [b,h,l,d]
__device__ __nv_bfloat16 g_kh2[2 * ACT_ELEMS];  // projected K bf16 hi/lo
__device__ __half        g_vh2[ACT_ELEMS];      // projected V fp16 single
__device__ __nv_bfloat16 g_swq[2 * W_ELEMS];
__device__ __nv_bfloat16 g_swk[2 * W_ELEMS];
__device__ __half        g_swv[W_ELEMS];        // Wv fp16 single
__device__ __half        g_swo[W_ELEMS];        // Wo fp16 single

// ---------------------------- PTX helpers ----------------------------------
__device__ __forceinline__ uint32_t smem_u32(const void* p) {
    uint32_t a;
    asm("{ .reg .u64 t; cvta.to.shared.u64 t, %1; cvt.u32.u64 %0, t; }"
        : "=r"(a) : "l"(p));
    return a;
}

__device__ __forceinline__ void cp16(uint32_t saddr, const void* g) {
    asm volatile("cp.async.cg.shared.global [%0], [%1], 16;"
                 :: "r"(saddr), "l"(g) : "memory");
}
#define CP_COMMIT() asm volatile("cp.async.commit_group;" ::: "memory")
#define CP_WAIT(n)  asm volatile("cp.async.wait_group %0;" :: "n"(n) : "memory")

__device__ __forceinline__ void ldsm_x4(uint32_t* r, uint32_t a) {
    asm volatile("ldmatrix.sync.aligned.m8n8.x4.shared.b16 {%0,%1,%2,%3}, [%4];"
                 : "=r"(r[0]), "=r"(r[1]), "=r"(r[2]), "=r"(r[3]) : "r"(a));
}
__device__ __forceinline__ void ldsm_x4t(uint32_t* r, uint32_t a) {
    asm volatile("ldmatrix.sync.aligned.m8n8.x4.trans.shared.b16 {%0,%1,%2,%3}, [%4];"
                 : "=r"(r[0]), "=r"(r[1]), "=r"(r[2]), "=r"(r[3]) : "r"(a));
}
__device__ __forceinline__ void mma_bf16(float* d, const uint32_t* a,
                                         const uint32_t* b) {
    asm volatile(
        "mma.sync.aligned.m16n8k16.row.col.f32.bf16.bf16.f32 "
        "{%0,%1,%2,%3}, {%4,%5,%6,%7}, {%8,%9}, {%0,%1,%2,%3};"
        : "+f"(d[0]), "+f"(d[1]), "+f"(d[2]), "+f"(d[3])
        : "r"(a[0]), "r"(a[1]), "r"(a[2]), "r"(a[3]), "r"(b[0]), "r"(b[1]));
}
__device__ __forceinline__ void mma_f16(float* d, const uint32_t* a,
                                        const uint32_t* b) {
    asm volatile(
        "mma.sync.aligned.m16n8k16.row.col.f32.f16.f16.f32 "
        "{%0,%1,%2,%3}, {%4,%5,%6,%7}, {%8,%9}, {%0,%1,%2,%3};"
        : "+f"(d[0]), "+f"(d[1]), "+f"(d[2]), "+f"(d[3])
        : "r"(a[0]), "r"(a[1]), "r"(a[2]), "r"(a[3]), "r"(b[0]), "r"(b[1]));
}

__device__ __forceinline__ void split2(float x, float y,
                                       uint32_t& hi, uint32_t& lo) {
    __nv_bfloat16 hx = __float2bfloat16(x);
    __nv_bfloat16 hy = __float2bfloat16(y);
    __nv_bfloat162 h2; h2.x = hx; h2.y = hy;
    hi = *reinterpret_cast<uint32_t*>(&h2);
    __nv_bfloat162 l2;
    l2.x = __float2bfloat16(x - __bfloat162float(hx));
    l2.y = __float2bfloat16(y - __bfloat162float(hy));
    lo = *reinterpret_cast<uint32_t*>(&l2);
}
__device__ __forceinline__ uint32_t pack2h(float x, float y) {
    __half2 h2 = __floats2half2_rn(x, y);
    return *reinterpret_cast<uint32_t*>(&h2);
}

__device__ __forceinline__ uint32_t sw256(int r, int q) {
    return (uint32_t)(r * 256 + ((q ^ (r & 7)) << 4));
}

// ---------------------------------------------------------------------------
// prep: all 7 input conversions in one launch (blockIdx.z selects job)
// type 0: bf16 hi/lo   type 2: fp16 single
// ---------------------------------------------------------------------------
struct PrepArgs {
    const float* src[7];
    void* dst[7];
    int n4[7];
    int n[7];
    int type[7];
};

__global__ __launch_bounds__(256)
void prep(PrepArgs a)
{
    const int z = blockIdx.z;
    const int i = blockIdx.x * 256 + threadIdx.x;
    if (i >= a.n4[z]) return;
    const float4 v = ((const float4*)a.src[z])[i];
    const int n = a.n[z];
    if (a.type[z] == 0) {
        uint32_t h0, l0, h1, l1;
        split2(v.x, v.y, h0, l0);
        split2(v.z, v.w, h1, l1);
        uint32_t* hp = (uint32_t*)a.dst[z];
        uint32_t* lp = (uint32_t*)((__nv_bfloat16*)a.dst[z] + n);
        hp[2 * i] = h0; hp[2 * i + 1] = h1;
        lp[2 * i] = l0; lp[2 * i + 1] = l1;
    } else {
        uint32_t* hp = (uint32_t*)a.dst[z];
        hp[2 * i]     = pack2h(v.x, v.y);
        hp[2 * i + 1] = pack2h(v.z, v.w);
    }
}

// ---------------------------------------------------------------------------
// GEMM common geometry: 128x128 CTA tile, BK=32, 3-stage cp.async, 8 warps.
// ---------------------------------------------------------------------------
#define TILE_B   8192
#define NSTAGE   3
#define NCHUNK   (DMODEL / 32)
#define STAGE4_B (4 * TILE_B)
#define GS4_B    (NSTAGE * STAGE4_B)       // 96 KB (bf16 3-product)
#define STAGE2_B (2 * TILE_B)
#define GS2_B    (NSTAGE * STAGE2_B)       // 48 KB (fp16 1-product)

// bf16 3-product mainloop: (Ah+Al) x (Bh+Bl), drop Al*Bl
__device__ __forceinline__ void mainloop_bf3(
    const __nv_bfloat16* Ahi, const __nv_bfloat16* Alo,
    const __nv_bfloat16* Bhi, const __nv_bfloat16* Blo,
    int bm, int bn, uint32_t sbase, float acc[4][4][4])
{
    const int tid = threadIdx.x;
    const int lane = tid & 31;
    const int wid = tid >> 5;
    const int wm = wid & 1;
    const int wn = wid >> 1;
    const int r = tid >> 2;
    const int q = tid & 3;

    auto load_stage = [&](int kc, int s) {
        const int k0 = kc * 32;
        const uint32_t st = sbase + (uint32_t)s * STAGE4_B;
        const __nv_bfloat16* srcs[4] = {Ahi, Alo, Bhi, Blo};
        const int row0[4] = {bm, bm, bn, bn};
#pragma unroll
        for (int t = 0; t < 4; t++) {
            const __nv_bfloat16* g0 =
                srcs[t] + (size_t)(row0[t] + r) * DMODEL + k0 + q * 8;
#pragma unroll
            for (int half = 0; half < 2; half++) {
                const int rr = r + half * 64;
                const uint32_t soff = (uint32_t)t * TILE_B + rr * 64 +
                                      ((q ^ ((rr >> 1) & 3)) * 16);
                cp16(st + soff, g0 + (size_t)half * 64 * DMODEL);
            }
        }
    };

    load_stage(0, 0); CP_COMMIT();
    load_stage(1, 1); CP_COMMIT();

    for (int kc = 0; kc < NCHUNK; kc++) {
        const int s = kc % NSTAGE;
        CP_WAIT(1);
        __syncthreads();
        if (kc + 2 < NCHUNK) load_stage(kc + 2, (kc + 2) % NSTAGE);
        CP_COMMIT();

        const uint32_t st = sbase + (uint32_t)s * STAGE4_B;
        const uint32_t sAh = st;
        const uint32_t sAl = st + TILE_B;
        const uint32_t sBh = st + 2 * TILE_B;
        const uint32_t sBl = st + 3 * TILE_B;

#pragma unroll
        for (int ks = 0; ks < 2; ks++) {
            uint32_t ah[4][4], al[4][4], bh4[2][4], bl4[2][4];
#pragma unroll
            for (int mt = 0; mt < 4; mt++) {
                const int row = wm * 64 + mt * 16 + (lane & 15);
                const int kseg = ks * 2 + (lane >> 4);
                const uint32_t off =
                    row * 64 + ((kseg ^ ((row >> 1) & 3)) * 16);
                ldsm_x4(ah[mt], sAh + off);
                ldsm_x4(al[mt], sAl + off);
            }
#pragma unroll
            for (int p = 0; p < 2; p++) {
                const int nrow = wn * 32 + p * 16 + ((lane >> 4) & 1) * 8 +
                                 (lane & 7);
                const int kseg = ks * 2 + ((lane >> 3) & 1);
                const uint32_t off =
                    nrow * 64 + ((kseg ^ ((nrow >> 1) & 3)) * 16);
                ldsm_x4(bh4[p], sBh + off);
                ldsm_x4(bl4[p], sBl + off);
            }
#pragma unroll
            for (int mt = 0; mt < 4; mt++)
#pragma unroll
                for (int nt = 0; nt < 4; nt++) {
                    const uint32_t* bh = &bh4[nt >> 1][(nt & 1) * 2];
                    const uint32_t* bl = &bl4[nt >> 1][(nt & 1) * 2];
                    mma_bf16(acc[mt][nt], ah[mt], bh);
                    mma_bf16(acc[mt][nt], ah[mt], bl);
                    mma_bf16(acc[mt][nt], al[mt], bh);
                }
        }
    }
}

// fp16 1-product mainloop: A x B (both single fp16)
__device__ __forceinline__ void mainloop_h1(
    const __half* A, const __half* B,
    int bm, int bn, uint32_t sbase, float acc[4][4][4])
{
    const int tid = threadIdx.x;
    const int lane = tid & 31;
    const int wid = tid >> 5;
    const int wm = wid & 1;
    const int wn = wid >> 1;
    const int r = tid >> 2;
    const int q = tid & 3;

    auto load_stage = [&](int kc, int s) {
        const int k0 = kc * 32;
        const uint32_t st = sbase + (uint32_t)s * STAGE2_B;
        const __half* srcs[2] = {A, B};
        const int row0[2] = {bm, bn};
#pragma unroll
        for (int t = 0; t < 2; t++) {
            const __half* g0 =
                srcs[t] + (size_t)(row0[t] + r) * DMODEL + k0 + q * 8;
#pragma unroll
            for (int half = 0; half < 2; half++) {
                const int rr = r + half * 64;
                const uint32_t soff = (uint32_t)t * TILE_B + rr * 64 +
                                      ((q ^ ((rr >> 1) & 3)) * 16);
                cp16(st + soff, g0 + (size_t)half * 64 * DMODEL);
            }
        }
    };

    load_stage(0, 0); CP_COMMIT();
    load_stage(1, 1); CP_COMMIT();

    for (int kc = 0; kc < NCHUNK; kc++) {
        const int s = kc % NSTAGE;
        CP_WAIT(1);
        __syncthreads();
        if (kc + 2 < NCHUNK) load_stage(kc + 2, (kc + 2) % NSTAGE);
        CP_COMMIT();

        const uint32_t st = sbase + (uint32_t)s * STAGE2_B;
        const uint32_t sA = st;
        const uint32_t sB = st + TILE_B;

#pragma unroll
        for (int ks = 0; ks < 2; ks++) {
            uint32_t ah[4][4], b4[2][4];
#pragma unroll
            for (int mt = 0; mt < 4; mt++) {
                const int row = wm * 64 + mt * 16 + (lane & 15);
                const int kseg = ks * 2 + (lane >> 4);
                const uint32_t off =
                    row * 64 + ((kseg ^ ((row >> 1) & 3)) * 16);
                ldsm_x4(ah[mt], sA + off);
            }
#pragma unroll
            for (int p = 0; p < 2; p++) {
                const int nrow = wn * 32 + p * 16 + ((lane >> 4) & 1) * 8 +
                                 (lane & 7);
                const int kseg = ks * 2 + ((lane >> 3) & 1);
                const uint32_t off =
                    nrow * 64 + ((kseg ^ ((nrow >> 1) & 3)) * 16);
                ldsm_x4(b4[p], sB + off);
            }
#pragma unroll
            for (int mt = 0; mt < 4; mt++)
#pragma unroll
                for (int nt = 0; nt < 4; nt++)
                    mma_f16(acc[mt][nt], ah[mt], &b4[nt >> 1][(nt & 1) * 2]);
        }
    }
}

// ---------------------------------------------------------------------------
// Fused Q/K/V projection GEMM. z=0: Q, z=1: K (bf16 3-product, bf16 hi/lo
// out).  z=2: V (fp16 1-product, fp16 single out). All [b,h,l,d].
// ---------------------------------------------------------------------------
struct QKVArgs {
    const __nv_bfloat16* Ah[2];
    const __nv_bfloat16* Al[2];
    const __nv_bfloat16* Bh[2];
    const __nv_bfloat16* Bl[2];
    const float* bias[2];
    __nv_bfloat16* Ch[2];
    __nv_bfloat16* Cl[2];
    const __half* vA;
    const __half* vB;
    const float* vbias;
    __half* vC;
};

__global__ __launch_bounds__(256)
void gemm_qkv(QKVArgs args)
{
    extern __shared__ char smb[];
    const uint32_t sbase = smem_u32(smb);
    const int sel = blockIdx.z;
    const int bn = blockIdx.x * 128;
    const int bm = blockIdx.y * 128;
    const int lane = threadIdx.x & 31;
    const int wid = threadIdx.x >> 5;
    const int wm = wid & 1;
    const int wn = wid >> 1;

    float acc[4][4][4];
#pragma unroll
    for (int i = 0; i < 4; i++)
#pragma unroll
        for (int j = 0; j < 4; j++)
#pragma unroll
            for (int c = 0; c < 4; c++) acc[i][j][c] = 0.f;

    if (sel < 2) {
        mainloop_bf3(args.Ah[sel], args.Al[sel], args.Bh[sel], args.Bl[sel],
                     bm, bn, sbase, acc);
        const float* bias = args.bias[sel];
        __nv_bfloat16* Ch = args.Ch[sel];
        __nv_bfloat16* Cl = args.Cl[sel];
#pragma unroll
        for (int mt = 0; mt < 4; mt++) {
#pragma unroll
            for (int nt = 0; nt < 4; nt++) {
                const int m0 = bm + wm * 64 + mt * 16 + (lane >> 2);
                const int n0 = bn + wn * 32 + nt * 8 + (lane & 3) * 2;
                const float bia0 = __ldg(&bias[n0]);
                const float bia1 = __ldg(&bias[n0 + 1]);
#pragma unroll
                for (int half = 0; half < 2; half++) {
                    const int m = m0 + half * 8;
                    const float x0 = acc[mt][nt][half * 2] + bia0;
                    const float x1 = acc[mt][nt][half * 2 + 1] + bia1;
                    const int h = bn >> 7;
                    const int b = m >> 11;
                    const int l = m & (LSEQ - 1);
                    const size_t idx =
                        (((size_t)(b * NH + h) * LSEQ + l) * DH) + (n0 & 127);
                    uint32_t hi, lo;
                    split2(x0, x1, hi, lo);
                    *(uint32_t*)(Ch + idx) = hi;
                    *(uint32_t*)(Cl + idx) = lo;
                }
            }
        }
    } else {
        mainloop_h1(args.vA, args.vB, bm, bn, sbase, acc);
        const float* bias = args.vbias;
        __half* C = args.vC;
#pragma unroll
        for (int mt = 0; mt < 4; mt++) {
#pragma unroll
            for (int nt = 0; nt < 4; nt++) {
                const int m0 = bm + wm * 64 + mt * 16 + (lane >> 2);
                const int n0 = bn + wn * 32 + nt * 8 + (lane & 3) * 2;
                const float bia0 = __ldg(&bias[n0]);
                const float bia1 = __ldg(&bias[n0 + 1]);
#pragma unroll
                for (int half = 0; half < 2; half++) {
                    const int m = m0 + half * 8;
                    const int h = bn >> 7;
                    const int b = m >> 11;
                    const int l = m & (LSEQ - 1);
                    const size_t idx =
                        (((size_t)(b * NH + h) * LSEQ + l) * DH) + (n0 & 127);
                    *(uint32_t*)(C + idx) =
                        pack2h(acc[mt][nt][half * 2] + bia0,
                               acc[mt][nt][half * 2 + 1] + bia1);
                }
            }
        }
    }
}

// ---------------------------------------------------------------------------
// Output projection: A (attn out fp16) x Wo fp16, 1-product; fp32 out
// ---------------------------------------------------------------------------
__global__ __launch_bounds__(256)
void gemm_wo(const __half* __restrict__ A, const __half* __restrict__ B,
             const float* __restrict__ bias, float* __restrict__ C)
{
    extern __shared__ char smb[];
    const uint32_t sbase = smem_u32(smb);
    const int bn = blockIdx.x * 128;
    const int bm = blockIdx.y * 128;
    const int lane = threadIdx.x & 31;
    const int wid = threadIdx.x >> 5;
    const int wm = wid & 1;
    const int wn = wid >> 1;

    float acc[4][4][4];
#pragma unroll
    for (int i = 0; i < 4; i++)
#pragma unroll
        for (int j = 0; j < 4; j++)
#pragma unroll
            for (int c = 0; c < 4; c++) acc[i][j][c] = 0.f;

    mainloop_h1(A, B, bm, bn, sbase, acc);

#pragma unroll
    for (int mt = 0; mt < 4; mt++) {
#pragma unroll
        for (int nt = 0; nt < 4; nt++) {
            const int m0 = bm + wm * 64 + mt * 16 + (lane >> 2);
            const int n0 = bn + wn * 32 + nt * 8 + (lane & 3) * 2;
            const float bia0 = __ldg(&bias[n0]);
            const float bia1 = __ldg(&bias[n0 + 1]);
#pragma unroll
            for (int half = 0; half < 2; half++) {
                const int m = m0 + half * 8;
                *(float2*)(C + (size_t)m * DMODEL + n0) =
                    make_float2(acc[mt][nt][half * 2] + bia0,
                                acc[mt][nt][half * 2 + 1] + bia1);
            }
        }
    }
}

// ---------------------------------------------------------------------------
// Flash attention (causal). QK: bf16 hi/lo 3-product. PV: fp16 P x fp16 V,
// single product (l summed from rounded P cancels common-mode rounding).
// Stage = Kh, Kl (bf16) + V (fp16) = 24 KB; 4-stage pipeline.
// Output: fp16 single [b, l, D] for the Wo GEMM.
// ---------------------------------------------------------------------------
#define NQT (LSEQ / 128)
#define FST_B (3 * 32 * 256)                     // 24 KB
#define FSMEM_B (2 * 128 * 256 + 4 * FST_B)      // 64 + 96 = 160 KB
#define FSCALE 11.31370849898476f

__global__ __launch_bounds__(256, 1)
void flash_mma(const __nv_bfloat16* __restrict__ Qhi,
               const __nv_bfloat16* __restrict__ Qlo,
               const __nv_bfloat16* __restrict__ Khi,
               const __nv_bfloat16* __restrict__ Klo,
               const __half* __restrict__ V,
               __half* __restrict__ O)
{
    extern __shared__ char smb[];
    const uint32_t sbase = smem_u32(smb);
    const uint32_t qlo_s = sbase + 128 * 256;
    const uint32_t stage0 = sbase + 2 * 128 * 256;

    const int tid = threadIdx.x;
    const int lane = tid & 31;
    const int w = tid >> 5;

    const int bx = blockIdx.x;
    const int qt = (NQT - 1) - (bx >> 5);
    const int hb = bx & 31;
    const int h = hb & 15;
    const int b = hb >> 4;
    const int bh = b * NH + h;
    const int NKT = 4 * (qt + 1);

    const __nv_bfloat16* qh_g = Qhi + (size_t)bh * LSEQ * DH;
    const __nv_bfloat16* ql_g = Qlo + (size_t)bh * LSEQ * DH;
    const __nv_bfloat16* kh_g = Khi + (size_t)bh * LSEQ * DH;
    const __nv_bfloat16* kl_g = Klo + (size_t)bh * LSEQ * DH;
    const __half*        v_g  = V   + (size_t)bh * LSEQ * DH;

    // ---- Q load (bf16 hi/lo, 64 KB) ----
    {
#pragma unroll
        for (int j = 0; j < 16; j++) {
            const int c = tid + 256 * j;
            const int t = c >> 11;
            const int u = c & 2047;
            const int r = u >> 4;
            const int q = u & 15;
            const __nv_bfloat16* src = (t ? ql_g : qh_g) +
                (size_t)(qt * 128 + r) * DH + q * 8;
            cp16(sbase + (uint32_t)t * (128 * 256) + sw256(r, q), src);
        }
        CP_COMMIT();
    }

    // ---- stage loader: Kh, Kl, V ----
    auto load_stage = [&](int kt, int s) {
        const uint32_t st = stage0 + (uint32_t)s * FST_B;
#pragma unroll
        for (int j = 0; j < 6; j++) {
            const int c = tid + 256 * j;
            const int t = c >> 9;
            const int u = c & 511;
            const int r = u >> 4;
            const int q = u & 15;
            const char* src =
                (t == 0 ? (const char*)kh_g :
                 t == 1 ? (const char*)kl_g : (const char*)v_g) +
                ((size_t)(kt * 32 + r) * DH + q * 8) * 2;
            cp16(st + (uint32_t)t * 8192 + sw256(r, q), src);
        }
        CP_COMMIT();
    };

    load_stage(0, 0);
    load_stage(1, 1);
    load_stage(2, 2);

    CP_WAIT(2);
    __syncthreads();

    uint32_t qfh[8][4], qfl[8][4];
#pragma unroll
    for (int ks = 0; ks < 8; ks++) {
        const int row = w * 16 + (lane & 15);
        const int q = ks * 2 + (lane >> 4);
        ldsm_x4(qfh[ks], sbase + sw256(row, q));
        ldsm_x4(qfl[ks], qlo_s + sw256(row, q));
    }

    float O_acc[16][4];
#pragma unroll
    for (int nd = 0; nd < 16; nd++)
#pragma unroll
        for (int c = 0; c < 4; c++) O_acc[nd][c] = 0.f;
    float m0 = -3.0e38f, m1 = -3.0e38f, l0 = 0.f, l1 = 0.f;

    const int iq0 = qt * 128 + w * 16 + (lane >> 2);
    const int jcol = (lane & 3) * 2;

    for (int kt = 0; kt < NKT; kt++) {
        if (kt + 2 < NKT) { CP_WAIT(2); }
        else if (kt + 1 < NKT) { CP_WAIT(1); }
        else { CP_WAIT(0); }
        __syncthreads();
        if (kt + 3 < NKT) load_stage(kt + 3, (kt + 3) & 3);

        const uint32_t st = stage0 + (uint32_t)(kt & 3) * FST_B;
        const uint32_t sKh = st;
        const uint32_t sKl = st + 8192;
        const uint32_t sV  = st + 16384;

        float S[4][4];
#pragma unroll
        for (int nt = 0; nt < 4; nt++)
#pragma unroll
            for (int c = 0; c < 4; c++) S[nt][c] = 0.f;

#pragma unroll
        for (int ks = 0; ks < 8; ks++) {
            uint32_t kh4[2][4], kl4[2][4];
#pragma unroll
            for (int p = 0; p < 2; p++) {
                const int row = p * 16 + ((lane >> 4) & 1) * 8 + (lane & 7);
                const int q = ks * 2 + ((lane >> 3) & 1);
                ldsm_x4(kh4[p], sKh + sw256(row, q));
                ldsm_x4(kl4[p], sKl + sw256(row, q));
            }
#pragma unroll
            for (int nt = 0; nt < 4; nt++) {
                const uint32_t* kh = &kh4[nt >> 1][(nt & 1) * 2];
                const uint32_t* kl = &kl4[nt >> 1][(nt & 1) * 2];
                mma_bf16(S[nt], qfh[ks], kh);
                mma_bf16(S[nt], qfh[ks], kl);
                mma_bf16(S[nt], qfl[ks], kh);
            }
        }

        const bool tilemask = (kt * 32 + 31) > (qt * 128 + w * 16);
#pragma unroll
        for (int nt = 0; nt < 4; nt++) {
#pragma unroll
            for (int c = 0; c < 4; c++) {
                float s = S[nt][c] * FSCALE;
                if (tilemask) {
                    const int i = iq0 + ((c & 2) ? 8 : 0);
                    const int j = kt * 32 + nt * 8 + jcol + (c & 1);
                    if (j > i) s -= 1e7f;
                }
                S[nt][c] = s;
            }
        }

        float tm0 = -3.0e38f, tm1 = -3.0e38f;
#pragma unroll
        for (int nt = 0; nt < 4; nt++) {
            tm0 = fmaxf(tm0, fmaxf(S[nt][0], S[nt][1]));
            tm1 = fmaxf(tm1, fmaxf(S[nt][2], S[nt][3]));
        }
        tm0 = fmaxf(tm0, __shfl_xor_sync(0xffffffffu, tm0, 1));
        tm0 = fmaxf(tm0, __shfl_xor_sync(0xffffffffu, tm0, 2));
        tm1 = fmaxf(tm1, __shfl_xor_sync(0xffffffffu, tm1, 1));
        tm1 = fmaxf(tm1, __shfl_xor_sync(0xffffffffu, tm1, 2));
        const float nm0 = fmaxf(m0, tm0);
        const float nm1 = fmaxf(m1, tm1);
        const float a0 = __expf(m0 - nm0);
        const float a1 = __expf(m1 - nm1);
        m0 = nm0; m1 = nm1;

        float s0 = 0.f, s1 = 0.f;
#pragma unroll
        for (int nt = 0; nt < 4; nt++) {
            S[nt][0] = __half2float(__float2half_rn(__expf(S[nt][0] - nm0)));
            S[nt][1] = __half2float(__float2half_rn(__expf(S[nt][1] - nm0)));
            S[nt][2] = __half2float(__float2half_rn(__expf(S[nt][2] - nm1)));
            S[nt][3] = __half2float(__float2half_rn(__expf(S[nt][3] - nm1)));
            s0 += S[nt][0] + S[nt][1];
            s1 += S[nt][2] + S[nt][3];
        }
        s0 += __shfl_xor_sync(0xffffffffu, s0, 1);
        s0 += __shfl_xor_sync(0xffffffffu, s0, 2);
        s1 += __shfl_xor_sync(0xffffffffu, s1, 1);
        s1 += __shfl_xor_sync(0xffffffffu, s1, 2);
        l0 = l0 * a0 + s0;
        l1 = l1 * a1 + s1;

#pragma unroll
        for (int nd = 0; nd < 16; nd++) {
            O_acc[nd][0] *= a0; O_acc[nd][1] *= a0;
            O_acc[nd][2] *= a1; O_acc[nd][3] *= a1;
        }

#pragma unroll
        for (int ks2 = 0; ks2 < 2; ks2++) {
            const int nt0 = 2 * ks2, nt1 = nt0 + 1;
            uint32_t ph[4];
            ph[0] = pack2h(S[nt0][0], S[nt0][1]);
            ph[1] = pack2h(S[nt0][2], S[nt0][3]);
            ph[2] = pack2h(S[nt1][0], S[nt1][1]);
            ph[3] = pack2h(S[nt1][2], S[nt1][3]);
            const int vrow = ks2 * 16 + (lane & 15);
#pragma unroll
            for (int np = 0; np < 8; np++) {
                uint32_t vv[4];
                const int seg = np * 2 + (lane >> 4);
                ldsm_x4t(vv, sV + sw256(vrow, seg));
                mma_f16(O_acc[2 * np],     ph, vv);
                mma_f16(O_acc[2 * np + 1], ph, vv + 2);
            }
        }
    }

    // ---- epilogue: normalize, fp16 single, write [b, l, D] ----
    const float inv0 = 1.0f / l0;
    const float inv1 = 1.0f / l1;
    const size_t tok0 = (size_t)b * LSEQ + qt * 128 + w * 16 + (lane >> 2);
    const size_t tok1 = tok0 + 8;
    const int col = h * DH + jcol;
#pragma unroll
    for (int nd = 0; nd < 16; nd++) {
        const int cc = col + nd * 8;
        *(uint32_t*)(O + tok0 * DMODEL + cc) =
            pack2h(O_acc[nd][0] * inv0, O_acc[nd][1] * inv0);
        *(uint32_t*)(O + tok1 * DMODEL + cc) =
            pack2h(O_acc[nd][2] * inv1, O_acc[nd][3] * inv1);
    }
}

// ---------------------------------------------------------------------------
extern "C" void kernel_launch(void* const* d_in, const int* in_sizes, int n_in,
                              void* d_out, int out_size)
{
    (void)in_sizes; (void)n_in; (void)out_size;
    const float* q  = (const float*)d_in[0];
    const float* k  = (const float*)d_in[1];
    const float* v  = (const float*)d_in[2];
    const float* Wq = (const float*)d_in[3];
    const float* bq = (const float*)d_in[4];
    const float* Wk = (const float*)d_in[5];
    const float* bk = (const float*)d_in[6];
    const float* Wv = (const float*)d_in[7];
    const float* bv = (const float*)d_in[8];
    const float* Wo = (const float*)d_in[9];
    const float* bo = (const float*)d_in[10];
    float* out = (float*)d_out;

    __nv_bfloat16 *sq, *sk, *qh2, *kh2, *swq, *swk;
    __half *sv, *sa, *vh2, *swv, *swo;
    cudaGetSymbolAddress((void**)&sq, g_sq);
    cudaGetSymbolAddress((void**)&sk, g_sk);
    cudaGetSymbolAddress((void**)&sv, g_sv);
    cudaGetSymbolAddress((void**)&sa, g_sa);
    cudaGetSymbolAddress((void**)&qh2, g_qh2);
    cudaGetSymbolAddress((void**)&kh2, g_kh2);
    cudaGetSymbolAddress((void**)&vh2, g_vh2);
    cudaGetSymbolAddress((void**)&swq, g_swq);
    cudaGetSymbolAddress((void**)&swk, g_swk);
    cudaGetSymbolAddress((void**)&swv, g_swv);
    cudaGetSymbolAddress((void**)&swo, g_swo);

    cudaFuncSetAttribute(gemm_qkv, cudaFuncAttributeMaxDynamicSharedMemorySize,
                         GS4_B);
    cudaFuncSetAttribute(gemm_wo, cudaFuncAttributeMaxDynamicSharedMemorySize,
                         GS2_B);
    cudaFuncSetAttribute(flash_mma, cudaFuncAttributeMaxDynamicSharedMemorySize,
                         FSMEM_B);

    // ---- prep: all conversions in one launch ----
    PrepArgs pa;
    pa.src[0] = q;  pa.dst[0] = sq;  pa.n[0] = (int)ACT_ELEMS; pa.type[0] = 0;
    pa.src[1] = k;  pa.dst[1] = sk;  pa.n[1] = (int)ACT_ELEMS; pa.type[1] = 0;
    pa.src[2] = v;  pa.dst[2] = sv;  pa.n[2] = (int)ACT_ELEMS; pa.type[2] = 2;
    pa.src[3] = Wq; pa.dst[3] = swq; pa.n[3] = (int)W_ELEMS;   pa.type[3] = 0;
    pa.src[4] = Wk; pa.dst[4] = swk; pa.n[4] = (int)W_ELEMS;   pa.type[4] = 0;
    pa.src[5] = Wv; pa.dst[5] = swv; pa.n[5] = (int)W_ELEMS;   pa.type[5] = 2;
    pa.src[6] = Wo; pa.dst[6] = swo; pa.n[6] = (int)W_ELEMS;   pa.type[6] = 2;
    for (int i = 0; i < 7; i++) pa.n4[i] = pa.n[i] / 4;
    prep<<<dim3((int)(ACT_ELEMS / 4 / 256), 1, 7), 256>>>(pa);

    // ---- fused Q/K/V projections ----
    QKVArgs qa;
    qa.Ah[0] = sq;  qa.Al[0] = sq + ACT_ELEMS;
    qa.Ah[1] = sk;  qa.Al[1] = sk + ACT_ELEMS;
    qa.Bh[0] = swq; qa.Bl[0] = swq + W_ELEMS;
    qa.Bh[1] = swk; qa.Bl[1] = swk + W_ELEMS;
    qa.bias[0] = bq; qa.bias[1] = bk;
    qa.Ch[0] = qh2; qa.Cl[0] = qh2 + ACT_ELEMS;
    qa.Ch[1] = kh2; qa.Cl[1] = kh2 + ACT_ELEMS;
    qa.vA = sv; qa.vB = swv; qa.vbias = bv; qa.vC = vh2;
    gemm_qkv<<<dim3(DMODEL / 128, MTOK / 128, 3), 256, GS4_B>>>(qa);

    // ---- attention ----
    flash_mma<<<NQT * NH * BATCH, 256, FSMEM_B>>>(
        qh2, qh2 + ACT_ELEMS, kh2, kh2 + ACT_ELEMS, vh2, sa);

    // ---- output projection (fp16 1-product) ----
    gemm_wo<<<dim3(DMODEL / 128, MTOK / 128), 256, GS2_B>>>(sa, swo, bo, out);
}

// round 8
// speedup vs baseline: 5.2132x; 1.0423x over previous
#include <cuda_runtime.h>
#include <cuda_bf16.h>
#include <cuda_fp16.h>
#include <cstdint>

#define LSEQ 2048
#define DMODEL 2048
#define NH 16
#define DH 128
#define BATCH 2
#define MTOK (BATCH * LSEQ)                 // 4096
#define ACT_ELEMS ((size_t)MTOK * DMODEL)   // 8388608
#define W_ELEMS ((size_t)DMODEL * DMODEL)   // 4194304

// ---------------- scratch (static device arrays; no allocs) ----------------
__device__ __nv_bfloat16 g_sq[2 * ACT_ELEMS];   // q input bf16 hi/lo
__device__ __nv_bfloat16 g_sk[2 * ACT_ELEMS];   // k input bf16 hi/lo
__device__ __half        g_sv[ACT_ELEMS];       // v input fp16 single
__device__ __half        g_sa[ACT_ELEMS];       // attention out fp16 single
__device__ __nv_bfloat16 g_qh2[2 * ACT_ELEMS];  // projected Q bf16 hi/lo [b,h,l,d]
__device__ __nv_bfloat16 g_kh2[2 * ACT_ELEMS];  // projected K bf16 hi/lo
__device__ __half        g_vh2[ACT_ELEMS];      // projected V fp16 single
__device__ __nv_bfloat16 g_swq[2 * W_ELEMS];
__device__ __nv_bfloat16 g_swk[2 * W_ELEMS];
__device__ __half        g_swv[W_ELEMS];        // Wv fp16 single
__device__ __half        g_swo[W_ELEMS];        // Wo fp16 single

// ---------------------------- PTX helpers ----------------------------------
__device__ __forceinline__ uint32_t smem_u32(const void* p) {
    uint32_t a;
    asm("{ .reg .u64 t; cvta.to.shared.u64 t, %1; cvt.u32.u64 %0, t; }"
        : "=r"(a) : "l"(p));
    return a;
}

__device__ __forceinline__ void cp16(uint32_t saddr, const void* g) {
    asm volatile("cp.async.cg.shared.global [%0], [%1], 16;"
                 :: "r"(saddr), "l"(g) : "memory");
}
#define CP_COMMIT() asm volatile("cp.async.commit_group;" ::: "memory")
#define CP_WAIT(n)  asm volatile("cp.async.wait_group %0;" :: "n"(n) : "memory")

__device__ __forceinline__ void ldsm_x4(uint32_t* r, uint32_t a) {
    asm volatile("ldmatrix.sync.aligned.m8n8.x4.shared.b16 {%0,%1,%2,%3}, [%4];"
                 : "=r"(r[0]), "=r"(r[1]), "=r"(r[2]), "=r"(r[3]) : "r"(a));
}
__device__ __forceinline__ void ldsm_x4t(uint32_t* r, uint32_t a) {
    asm volatile("ldmatrix.sync.aligned.m8n8.x4.trans.shared.b16 {%0,%1,%2,%3}, [%4];"
                 : "=r"(r[0]), "=r"(r[1]), "=r"(r[2]), "=r"(r[3]) : "r"(a));
}
__device__ __forceinline__ void mma_bf16(float* d, const uint32_t* a,
                                         const uint32_t* b) {
    asm volatile(
        "mma.sync.aligned.m16n8k16.row.col.f32.bf16.bf16.f32 "
        "{%0,%1,%2,%3}, {%4,%5,%6,%7}, {%8,%9}, {%0,%1,%2,%3};"
        : "+f"(d[0]), "+f"(d[1]), "+f"(d[2]), "+f"(d[3])
        : "r"(a[0]), "r"(a[1]), "r"(a[2]), "r"(a[3]), "r"(b[0]), "r"(b[1]));
}
__device__ __forceinline__ void mma_f16(float* d, const uint32_t* a,
                                        const uint32_t* b) {
    asm volatile(
        "mma.sync.aligned.m16n8k16.row.col.f32.f16.f16.f32 "
        "{%0,%1,%2,%3}, {%4,%5,%6,%7}, {%8,%9}, {%0,%1,%2,%3};"
        : "+f"(d[0]), "+f"(d[1]), "+f"(d[2]), "+f"(d[3])
        : "r"(a[0]), "r"(a[1]), "r"(a[2]), "r"(a[3]), "r"(b[0]), "r"(b[1]));
}

__device__ __forceinline__ void split2(float x, float y,
                                       uint32_t& hi, uint32_t& lo) {
    __nv_bfloat16 hx = __float2bfloat16(x);
    __nv_bfloat16 hy = __float2bfloat16(y);
    __nv_bfloat162 h2; h2.x = hx; h2.y = hy;
    hi = *reinterpret_cast<uint32_t*>(&h2);
    __nv_bfloat162 l2;
    l2.x = __float2bfloat16(x - __bfloat162float(hx));
    l2.y = __float2bfloat16(y - __bfloat162float(hy));
    lo = *reinterpret_cast<uint32_t*>(&l2);
}
__device__ __forceinline__ uint32_t pack2h(float x, float y) {
    __half2 h2 = __floats2half2_rn(x, y);
    return *reinterpret_cast<uint32_t*>(&h2);
}

__device__ __forceinline__ uint32_t sw256(int r, int q) {
    return (uint32_t)(r * 256 + ((q ^ (r & 7)) << 4));
}

// ---------------------------------------------------------------------------
// prep: all 7 input conversions in one launch; 2 float4 per thread
// type 0: bf16 hi/lo   type 2: fp16 single
// ---------------------------------------------------------------------------
struct PrepArgs {
    const float* src[7];
    void* dst[7];
    int n4[7];
    int n[7];
    int type[7];
};

__device__ __forceinline__ void prep_one(const PrepArgs& a, int z, int i) {
    const float4 v = ((const float4*)a.src[z])[i];
    const int n = a.n[z];
    if (a.type[z] == 0) {
        uint32_t h0, l0, h1, l1;
        split2(v.x, v.y, h0, l0);
        split2(v.z, v.w, h1, l1);
        uint32_t* hp = (uint32_t*)a.dst[z];
        uint32_t* lp = (uint32_t*)((__nv_bfloat16*)a.dst[z] + n);
        hp[2 * i] = h0; hp[2 * i + 1] = h1;
        lp[2 * i] = l0; lp[2 * i + 1] = l1;
    } else {
        uint32_t* hp = (uint32_t*)a.dst[z];
        hp[2 * i]     = pack2h(v.x, v.y);
        hp[2 * i + 1] = pack2h(v.z, v.w);
    }
}

__global__ __launch_bounds__(256)
void prep(PrepArgs a)
{
    const int z = blockIdx.z;
    const int half = a.n4[z] >> 1;
    const int i = blockIdx.x * 256 + threadIdx.x;
    if (i >= half) return;
    prep_one(a, z, i);
    prep_one(a, z, i + half);
}

// ---------------------------------------------------------------------------
// GEMM geometry
// bf3: 128x128 CTA tile, BK=32, 3-stage, 64B rows.
// h1 : 128x128 CTA tile, BK=64, 3-stage, 128B rows.
// ---------------------------------------------------------------------------
#define TILE_B   8192                  // 128 rows * 64 B   (bf3)
#define NSTAGE   3
#define NCHUNK   (DMODEL / 32)         // 64  (bf3)
#define STAGE4_B (4 * TILE_B)
#define GS4_B    (NSTAGE * STAGE4_B)   // 96 KB

#define TILEH_B  16384                 // 128 rows * 128 B  (h1)
#define STAGEH_B (2 * TILEH_B)         // 32 KB
#define GSH_B    (NSTAGE * STAGEH_B)   // 96 KB
#define NCHUNK64 (DMODEL / 64)         // 32

// bf16 3-product mainloop: (Ah+Al) x (Bh+Bl), drop Al*Bl
__device__ __forceinline__ void mainloop_bf3(
    const __nv_bfloat16* Ahi, const __nv_bfloat16* Alo,
    const __nv_bfloat16* Bhi, const __nv_bfloat16* Blo,
    int bm, int bn, uint32_t sbase, float acc[4][4][4])
{
    const int tid = threadIdx.x;
    const int lane = tid & 31;
    const int wid = tid >> 5;
    const int wm = wid & 1;
    const int wn = wid >> 1;
    const int r = tid >> 2;
    const int q = tid & 3;

    auto load_stage = [&](int kc, int s) {
        const int k0 = kc * 32;
        const uint32_t st = sbase + (uint32_t)s * STAGE4_B;
        const __nv_bfloat16* srcs[4] = {Ahi, Alo, Bhi, Blo};
        const int row0[4] = {bm, bm, bn, bn};
#pragma unroll
        for (int t = 0; t < 4; t++) {
            const __nv_bfloat16* g0 =
                srcs[t] + (size_t)(row0[t] + r) * DMODEL + k0 + q * 8;
#pragma unroll
            for (int half = 0; half < 2; half++) {
                const int rr = r + half * 64;
                const uint32_t soff = (uint32_t)t * TILE_B + rr * 64 +
                                      ((q ^ ((rr >> 1) & 3)) * 16);
                cp16(st + soff, g0 + (size_t)half * 64 * DMODEL);
            }
        }
    };

    load_stage(0, 0); CP_COMMIT();
    load_stage(1, 1); CP_COMMIT();

    for (int kc = 0; kc < NCHUNK; kc++) {
        const int s = kc % NSTAGE;
        CP_WAIT(1);
        __syncthreads();
        if (kc + 2 < NCHUNK) load_stage(kc + 2, (kc + 2) % NSTAGE);
        CP_COMMIT();

        const uint32_t st = sbase + (uint32_t)s * STAGE4_B;
        const uint32_t sAh = st;
        const uint32_t sAl = st + TILE_B;
        const uint32_t sBh = st + 2 * TILE_B;
        const uint32_t sBl = st + 3 * TILE_B;

#pragma unroll
        for (int ks = 0; ks < 2; ks++) {
            uint32_t ah[4][4], al[4][4], bh4[2][4], bl4[2][4];
#pragma unroll
            for (int mt = 0; mt < 4; mt++) {
                const int row = wm * 64 + mt * 16 + (lane & 15);
                const int kseg = ks * 2 + (lane >> 4);
                const uint32_t off =
                    row * 64 + ((kseg ^ ((row >> 1) & 3)) * 16);
                ldsm_x4(ah[mt], sAh + off);
                ldsm_x4(al[mt], sAl + off);
            }
#pragma unroll
            for (int p = 0; p < 2; p++) {
                const int nrow = wn * 32 + p * 16 + ((lane >> 4) & 1) * 8 +
                                 (lane & 7);
                const int kseg = ks * 2 + ((lane >> 3) & 1);
                const uint32_t off =
                    nrow * 64 + ((kseg ^ ((nrow >> 1) & 3)) * 16);
                ldsm_x4(bh4[p], sBh + off);
                ldsm_x4(bl4[p], sBl + off);
            }
#pragma unroll
            for (int mt = 0; mt < 4; mt++)
#pragma unroll
                for (int nt = 0; nt < 4; nt++) {
                    const uint32_t* bh = &bh4[nt >> 1][(nt & 1) * 2];
                    const uint32_t* bl = &bl4[nt >> 1][(nt & 1) * 2];
                    mma_bf16(acc[mt][nt], ah[mt], bh);
                    mma_bf16(acc[mt][nt], ah[mt], bl);
                    mma_bf16(acc[mt][nt], al[mt], bh);
                }
        }
    }
}

// fp16 1-product mainloop, BK=64 (128B rows, Swizzle<3,4,3>)
__device__ __forceinline__ void mainloop_h1(
    const __half* A, const __half* B,
    int bm, int bn, uint32_t sbase, float acc[4][4][4])
{
    const int tid = threadIdx.x;
    const int lane = tid & 31;
    const int wid = tid >> 5;
    const int wm = wid & 1;
    const int wn = wid >> 1;

    auto load_stage = [&](int kc, int s) {
        const int k0 = kc * 64;
        const uint32_t st = sbase + (uint32_t)s * STAGEH_B;
#pragma unroll
        for (int j = 0; j < 8; j++) {
            const int c = tid + 256 * j;       // 0..2047 16B chunks
            const int t = c >> 10;             // 0 A, 1 B
            const int u = c & 1023;
            const int r = u >> 3;
            const int q = u & 7;
            const __half* g = (t ? B + (size_t)(bn + r) * DMODEL
                                 : A + (size_t)(bm + r) * DMODEL) + k0 + q * 8;
            cp16(st + (uint32_t)t * TILEH_B + r * 128 +
                 (((q ^ (r & 7)) << 4)), g);
        }
    };

    load_stage(0, 0); CP_COMMIT();
    load_stage(1, 1); CP_COMMIT();

    for (int kc = 0; kc < NCHUNK64; kc++) {
        const int s = kc % NSTAGE;
        CP_WAIT(1);
        __syncthreads();
        if (kc + 2 < NCHUNK64) load_stage(kc + 2, (kc + 2) % NSTAGE);
        CP_COMMIT();

        const uint32_t sA = sbase + (uint32_t)s * STAGEH_B;
        const uint32_t sB = sA + TILEH_B;

#pragma unroll
        for (int ks = 0; ks < 4; ks++) {
            uint32_t ah[4][4], b4[2][4];
#pragma unroll
            for (int mt = 0; mt < 4; mt++) {
                const int row = wm * 64 + mt * 16 + (lane & 15);
                const int kseg = ks * 2 + (lane >> 4);
                ldsm_x4(ah[mt], sA + row * 128 + ((kseg ^ (row & 7)) << 4));
            }
#pragma unroll
            for (int p = 0; p < 2; p++) {
                const int nrow = wn * 32 + p * 16 + ((lane >> 4) & 1) * 8 +
                                 (lane & 7);
                const int kseg = ks * 2 + ((lane >> 3) & 1);
                ldsm_x4(b4[p], sB + nrow * 128 + ((kseg ^ (nrow & 7)) << 4));
            }
#pragma unroll
            for (int mt = 0; mt < 4; mt++)
#pragma unroll
                for (int nt = 0; nt < 4; nt++)
                    mma_f16(acc[mt][nt], ah[mt], &b4[nt >> 1][(nt & 1) * 2]);
        }
    }
}

// ---------------------------------------------------------------------------
// Fused Q/K/V projection GEMM. z=0: Q, z=1: K (bf16 3-product, bf16 hi/lo
// out).  z=2: V (fp16 1-product BK=64, fp16 single out). All [b,h,l,d].
// ---------------------------------------------------------------------------
struct QKVArgs {
    const __nv_bfloat16* Ah[2];
    const __nv_bfloat16* Al[2];
    const __nv_bfloat16* Bh[2];
    const __nv_bfloat16* Bl[2];
    const float* bias[2];
    __nv_bfloat16* Ch[2];
    __nv_bfloat16* Cl[2];
    const __half* vA;
    const __half* vB;
    const float* vbias;
    __half* vC;
};

__global__ __launch_bounds__(256)
void gemm_qkv(QKVArgs args)
{
    extern __shared__ char smb[];
    const uint32_t sbase = smem_u32(smb);
    const int sel = blockIdx.z;
    const int bn = blockIdx.x * 128;
    const int bm = blockIdx.y * 128;
    const int lane = threadIdx.x & 31;
    const int wid = threadIdx.x >> 5;
    const int wm = wid & 1;
    const int wn = wid >> 1;

    float acc[4][4][4];
#pragma unroll
    for (int i = 0; i < 4; i++)
#pragma unroll
        for (int j = 0; j < 4; j++)
#pragma unroll
            for (int c = 0; c < 4; c++) acc[i][j][c] = 0.f;

    if (sel < 2) {
        mainloop_bf3(args.Ah[sel], args.Al[sel], args.Bh[sel], args.Bl[sel],
                     bm, bn, sbase, acc);
        const float* bias = args.bias[sel];
        __nv_bfloat16* Ch = args.Ch[sel];
        __nv_bfloat16* Cl = args.Cl[sel];
#pragma unroll
        for (int mt = 0; mt < 4; mt++) {
#pragma unroll
            for (int nt = 0; nt < 4; nt++) {
                const int m0 = bm + wm * 64 + mt * 16 + (lane >> 2);
                const int n0 = bn + wn * 32 + nt * 8 + (lane & 3) * 2;
                const float bia0 = __ldg(&bias[n0]);
                const float bia1 = __ldg(&bias[n0 + 1]);
#pragma unroll
                for (int half = 0; half < 2; half++) {
                    const int m = m0 + half * 8;
                    const float x0 = acc[mt][nt][half * 2] + bia0;
                    const float x1 = acc[mt][nt][half * 2 + 1] + bia1;
                    const int h = bn >> 7;
                    const int b = m >> 11;
                    const int l = m & (LSEQ - 1);
                    const size_t idx =
                        (((size_t)(b * NH + h) * LSEQ + l) * DH) + (n0 & 127);
                    uint32_t hi, lo;
                    split2(x0, x1, hi, lo);
                    *(uint32_t*)(Ch + idx) = hi;
                    *(uint32_t*)(Cl + idx) = lo;
                }
            }
        }
    } else {
        mainloop_h1(args.vA, args.vB, bm, bn, sbase, acc);
        const float* bias = args.vbias;
        __half* C = args.vC;
#pragma unroll
        for (int mt = 0; mt < 4; mt++) {
#pragma unroll
            for (int nt = 0; nt < 4; nt++) {
                const int m0 = bm + wm * 64 + mt * 16 + (lane >> 2);
                const int n0 = bn + wn * 32 + nt * 8 + (lane & 3) * 2;
                const float bia0 = __ldg(&bias[n0]);
                const float bia1 = __ldg(&bias[n0 + 1]);
#pragma unroll
                for (int half = 0; half < 2; half++) {
                    const int m = m0 + half * 8;
                    const int h = bn >> 7;
                    const int b = m >> 11;
                    const int l = m & (LSEQ - 1);
                    const size_t idx =
                        (((size_t)(b * NH + h) * LSEQ + l) * DH) + (n0 & 127);
                    *(uint32_t*)(C + idx) =
                        pack2h(acc[mt][nt][half * 2] + bia0,
                               acc[mt][nt][half * 2 + 1] + bia1);
                }
            }
        }
    }
}

// ---------------------------------------------------------------------------
// Output projection: A (attn out fp16) x Wo fp16, 1-product BK=64; fp32 out
// ---------------------------------------------------------------------------
__global__ __launch_bounds__(256)
void gemm_wo(const __half* __restrict__ A, const __half* __restrict__ B,
             const float* __restrict__ bias, float* __restrict__ C)
{
    extern __shared__ char smb[];
    const uint32_t sbase = smem_u32(smb);
    const int bn = blockIdx.x * 128;
    const int bm = blockIdx.y * 128;
    const int lane = threadIdx.x & 31;
    const int wid = threadIdx.x >> 5;
    const int wm = wid & 1;
    const int wn = wid >> 1;

    float acc[4][4][4];
#pragma unroll
    for (int i = 0; i < 4; i++)
#pragma unroll
        for (int j = 0; j < 4; j++)
#pragma unroll
            for (int c = 0; c < 4; c++) acc[i][j][c] = 0.f;

    mainloop_h1(A, B, bm, bn, sbase, acc);

#pragma unroll
    for (int mt = 0; mt < 4; mt++) {
#pragma unroll
        for (int nt = 0; nt < 4; nt++) {
            const int m0 = bm + wm * 64 + mt * 16 + (lane >> 2);
            const int n0 = bn + wn * 32 + nt * 8 + (lane & 3) * 2;
            const float bia0 = __ldg(&bias[n0]);
            const float bia1 = __ldg(&bias[n0 + 1]);
#pragma unroll
            for (int half = 0; half < 2; half++) {
                const int m = m0 + half * 8;
                *(float2*)(C + (size_t)m * DMODEL + n0) =
                    make_float2(acc[mt][nt][half * 2] + bia0,
                                acc[mt][nt][half * 2 + 1] + bia1);
            }
        }
    }
}

// ---------------------------------------------------------------------------
// Flash attention (causal). QK: bf16 hi/lo 3-product. PV: fp16 P x fp16 V.
// Warp-uniform rescale skip when no row in the warp saw a new max.
// ---------------------------------------------------------------------------
#define NQT (LSEQ / 128)
#define FST_B (3 * 32 * 256)                     // 24 KB
#define FSMEM_B (2 * 128 * 256 + 4 * FST_B)      // 160 KB
#define FSCALE 11.31370849898476f

__global__ __launch_bounds__(256, 1)
void flash_mma(const __nv_bfloat16* __restrict__ Qhi,
               const __nv_bfloat16* __restrict__ Qlo,
               const __nv_bfloat16* __restrict__ Khi,
               const __nv_bfloat16* __restrict__ Klo,
               const __half* __restrict__ V,
               __half* __restrict__ O)
{
    extern __shared__ char smb[];
    const uint32_t sbase = smem_u32(smb);
    const uint32_t qlo_s = sbase + 128 * 256;
    const uint32_t stage0 = sbase + 2 * 128 * 256;

    const int tid = threadIdx.x;
    const int lane = tid & 31;
    const int w = tid >> 5;

    const int bx = blockIdx.x;
    const int qt = (NQT - 1) - (bx >> 5);
    const int hb = bx & 31;
    const int h = hb & 15;
    const int b = hb >> 4;
    const int bh = b * NH + h;
    const int NKT = 4 * (qt + 1);

    const __nv_bfloat16* qh_g = Qhi + (size_t)bh * LSEQ * DH;
    const __nv_bfloat16* ql_g = Qlo + (size_t)bh * LSEQ * DH;
    const __nv_bfloat16* kh_g = Khi + (size_t)bh * LSEQ * DH;
    const __nv_bfloat16* kl_g = Klo + (size_t)bh * LSEQ * DH;
    const __half*        v_g  = V   + (size_t)bh * LSEQ * DH;

    // ---- Q load (bf16 hi/lo, 64 KB) ----
    {
#pragma unroll
        for (int j = 0; j < 16; j++) {
            const int c = tid + 256 * j;
            const int t = c >> 11;
            const int u = c & 2047;
            const int r = u >> 4;
            const int q = u & 15;
            const __nv_bfloat16* src = (t ? ql_g : qh_g) +
                (size_t)(qt * 128 + r) * DH + q * 8;
            cp16(sbase + (uint32_t)t * (128 * 256) + sw256(r, q), src);
        }
        CP_COMMIT();
    }

    // ---- stage loader: Kh, Kl, V ----
    auto load_stage = [&](int kt, int s) {
        const uint32_t st = stage0 + (uint32_t)s * FST_B;
#pragma unroll
        for (int j = 0; j < 6; j++) {
            const int c = tid + 256 * j;
            const int t = c >> 9;
            const int u = c & 511;
            const int r = u >> 4;
            const int q = u & 15;
            const char* src =
                (t == 0 ? (const char*)kh_g :
                 t == 1 ? (const char*)kl_g : (const char*)v_g) +
                ((size_t)(kt * 32 + r) * DH + q * 8) * 2;
            cp16(st + (uint32_t)t * 8192 + sw256(r, q), src);
        }
        CP_COMMIT();
    };

    load_stage(0, 0);
    load_stage(1, 1);
    load_stage(2, 2);

    CP_WAIT(2);
    __syncthreads();

    uint32_t qfh[8][4], qfl[8][4];
#pragma unroll
    for (int ks = 0; ks < 8; ks++) {
        const int row = w * 16 + (lane & 15);
        const int q = ks * 2 + (lane >> 4);
        ldsm_x4(qfh[ks], sbase + sw256(row, q));
        ldsm_x4(qfl[ks], qlo_s + sw256(row, q));
    }

    float O_acc[16][4];
#pragma unroll
    for (int nd = 0; nd < 16; nd++)
#pragma unroll
        for (int c = 0; c < 4; c++) O_acc[nd][c] = 0.f;
    float m0 = -3.0e38f, m1 = -3.0e38f, l0 = 0.f, l1 = 0.f;

    const int iq0 = qt * 128 + w * 16 + (lane >> 2);
    const int jcol = (lane & 3) * 2;

    for (int kt = 0; kt < NKT; kt++) {
        if (kt + 2 < NKT) { CP_WAIT(2); }
        else if (kt + 1 < NKT) { CP_WAIT(1); }
        else { CP_WAIT(0); }
        __syncthreads();
        if (kt + 3 < NKT) load_stage(kt + 3, (kt + 3) & 3);

        const uint32_t st = stage0 + (uint32_t)(kt & 3) * FST_B;
        const uint32_t sKh = st;
        const uint32_t sKl = st + 8192;
        const uint32_t sV  = st + 16384;

        float S[4][4];
#pragma unroll
        for (int nt = 0; nt < 4; nt++)
#pragma unroll
            for (int c = 0; c < 4; c++) S[nt][c] = 0.f;

#pragma unroll
        for (int ks = 0; ks < 8; ks++) {
            uint32_t kh4[2][4], kl4[2][4];
#pragma unroll
            for (int p = 0; p < 2; p++) {
                const int row = p * 16 + ((lane >> 4) & 1) * 8 + (lane & 7);
                const int q = ks * 2 + ((lane >> 3) & 1);
                ldsm_x4(kh4[p], sKh + sw256(row, q));
                ldsm_x4(kl4[p], sKl + sw256(row, q));
            }
#pragma unroll
            for (int nt = 0; nt < 4; nt++) {
                const uint32_t* kh = &kh4[nt >> 1][(nt & 1) * 2];
                const uint32_t* kl = &kl4[nt >> 1][(nt & 1) * 2];
                mma_bf16(S[nt], qfh[ks], kh);
                mma_bf16(S[nt], qfh[ks], kl);
                mma_bf16(S[nt], qfl[ks], kh);
            }
        }

        const bool tilemask = (kt * 32 + 31) > (qt * 128 + w * 16);
#pragma unroll
        for (int nt = 0; nt < 4; nt++) {
#pragma unroll
            for (int c = 0; c < 4; c++) {
                float s = S[nt][c] * FSCALE;
                if (tilemask) {
                    const int i = iq0 + ((c & 2) ? 8 : 0);
                    const int j = kt * 32 + nt * 8 + jcol + (c & 1);
                    if (j > i) s -= 1e7f;
                }
                S[nt][c] = s;
            }
        }

        float tm0 = -3.0e38f, tm1 = -3.0e38f;
#pragma unroll
        for (int nt = 0; nt < 4; nt++) {
            tm0 = fmaxf(tm0, fmaxf(S[nt][0], S[nt][1]));
            tm1 = fmaxf(tm1, fmaxf(S[nt][2], S[nt][3]));
        }
        tm0 = fmaxf(tm0, __shfl_xor_sync(0xffffffffu, tm0, 1));
        tm0 = fmaxf(tm0, __shfl_xor_sync(0xffffffffu, tm0, 2));
        tm1 = fmaxf(tm1, __shfl_xor_sync(0xffffffffu, tm1, 1));
        tm1 = fmaxf(tm1, __shfl_xor_sync(0xffffffffu, tm1, 2));
        const float nm0 = fmaxf(m0, tm0);
        const float nm1 = fmaxf(m1, tm1);

        // warp-uniform rescale skip: if no row in this warp saw a new max,
        // alpha == exp(0) == 1 exactly -> skipping is bit-identical.
        const unsigned skip =
            __all_sync(0xffffffffu, (nm0 == m0) && (nm1 == m1));
        if (!skip) {
            const float a0 = __expf(m0 - nm0);
            const float a1 = __expf(m1 - nm1);
            l0 *= a0; l1 *= a1;
#pragma unroll
            for (int nd = 0; nd < 16; nd++) {
                O_acc[nd][0] *= a0; O_acc[nd][1] *= a0;
                O_acc[nd][2] *= a1; O_acc[nd][3] *= a1;
            }
            m0 = nm0; m1 = nm1;
        }

        float s0 = 0.f, s1 = 0.f;
#pragma unroll
        for (int nt = 0; nt < 4; nt++) {
            S[nt][0] = __half2float(__float2half_rn(__expf(S[nt][0] - m0)));
            S[nt][1] = __half2float(__float2half_rn(__expf(S[nt][1] - m0)));
            S[nt][2] = __half2float(__float2half_rn(__expf(S[nt][2] - m1)));
            S[nt][3] = __half2float(__float2half_rn(__expf(S[nt][3] - m1)));
            s0 += S[nt][0] + S[nt][1];
            s1 += S[nt][2] + S[nt][3];
        }
        s0 += __shfl_xor_sync(0xffffffffu, s0, 1);
        s0 += __shfl_xor_sync(0xffffffffu, s0, 2);
        s1 += __shfl_xor_sync(0xffffffffu, s1, 1);
        s1 += __shfl_xor_sync(0xffffffffu, s1, 2);
        l0 += s0;
        l1 += s1;

#pragma unroll
        for (int ks2 = 0; ks2 < 2; ks2++) {
            const int nt0 = 2 * ks2, nt1 = nt0 + 1;
            uint32_t ph[4];
            ph[0] = pack2h(S[nt0][0], S[nt0][1]);
            ph[1] = pack2h(S[nt0][2], S[nt0][3]);
            ph[2] = pack2h(S[nt1][0], S[nt1][1]);
            ph[3] = pack2h(S[nt1][2], S[nt1][3]);
            const int vrow = ks2 * 16 + (lane & 15);
#pragma unroll
            for (int np = 0; np < 8; np++) {
                uint32_t vv[4];
                const int seg = np * 2 + (lane >> 4);
                ldsm_x4t(vv, sV + sw256(vrow, seg));
                mma_f16(O_acc[2 * np],     ph, vv);
                mma_f16(O_acc[2 * np + 1], ph, vv + 2);
            }
        }
    }

    // ---- epilogue: normalize, fp16 single, write [b, l, D] ----
    const float inv0 = 1.0f / l0;
    const float inv1 = 1.0f / l1;
    const size_t tok0 = (size_t)b * LSEQ + qt * 128 + w * 16 + (lane >> 2);
    const size_t tok1 = tok0 + 8;
    const int col = h * DH + jcol;
#pragma unroll
    for (int nd = 0; nd < 16; nd++) {
        const int cc = col + nd * 8;
        *(uint32_t*)(O + tok0 * DMODEL + cc) =
            pack2h(O_acc[nd][0] * inv0, O_acc[nd][1] * inv0);
        *(uint32_t*)(O + tok1 * DMODEL + cc) =
            pack2h(O_acc[nd][2] * inv1, O_acc[nd][3] * inv1);
    }
}

// ---------------------------------------------------------------------------
extern "C" void kernel_launch(void* const* d_in, const int* in_sizes, int n_in,
                              void* d_out, int out_size)
{
    (void)in_sizes; (void)n_in; (void)out_size;
    const float* q  = (const float*)d_in[0];
    const float* k  = (const float*)d_in[1];
    const float* v  = (const float*)d_in[2];
    const float* Wq = (const float*)d_in[3];
    const float* bq = (const float*)d_in[4];
    const float* Wk = (const float*)d_in[5];
    const float* bk = (const float*)d_in[6];
    const float* Wv = (const float*)d_in[7];
    const float* bv = (const float*)d_in[8];
    const float* Wo = (const float*)d_in[9];
    const float* bo = (const float*)d_in[10];
    float* out = (float*)d_out;

    __nv_bfloat16 *sq, *sk, *qh2, *kh2, *swq, *swk;
    __half *sv, *sa, *vh2, *swv, *swo;
    cudaGetSymbolAddress((void**)&sq, g_sq);
    cudaGetSymbolAddress((void**)&sk, g_sk);
    cudaGetSymbolAddress((void**)&sv, g_sv);
    cudaGetSymbolAddress((void**)&sa, g_sa);
    cudaGetSymbolAddress((void**)&qh2, g_qh2);
    cudaGetSymbolAddress((void**)&kh2, g_kh2);
    cudaGetSymbolAddress((void**)&vh2, g_vh2);
    cudaGetSymbolAddress((void**)&swq, g_swq);
    cudaGetSymbolAddress((void**)&swk, g_swk);
    cudaGetSymbolAddress((void**)&swv, g_swv);
    cudaGetSymbolAddress((void**)&swo, g_swo);

    cudaFuncSetAttribute(gemm_qkv, cudaFuncAttributeMaxDynamicSharedMemorySize,
                         GS4_B);
    cudaFuncSetAttribute(gemm_wo, cudaFuncAttributeMaxDynamicSharedMemorySize,
                         GSH_B);
    cudaFuncSetAttribute(flash_mma, cudaFuncAttributeMaxDynamicSharedMemorySize,
                         FSMEM_B);

    // ---- prep: all conversions in one launch ----
    PrepArgs pa;
    pa.src[0] = q;  pa.dst[0] = sq;  pa.n[0] = (int)ACT_ELEMS; pa.type[0] = 0;
    pa.src[1] = k;  pa.dst[1] = sk;  pa.n[1] = (int)ACT_ELEMS; pa.type[1] = 0;
    pa.src[2] = v;  pa.dst[2] = sv;  pa.n[2] = (int)ACT_ELEMS; pa.type[2] = 2;
    pa.src[3] = Wq; pa.dst[3] = swq; pa.n[3] = (int)W_ELEMS;   pa.type[3] = 0;
    pa.src[4] = Wk; pa.dst[4] = swk; pa.n[4] = (int)W_ELEMS;   pa.type[4] = 0;
    pa.src[5] = Wv; pa.dst[5] = swv; pa.n[5] = (int)W_ELEMS;   pa.type[5] = 2;
    pa.src[6] = Wo; pa.dst[6] = swo; pa.n[6] = (int)W_ELEMS;   pa.type[6] = 2;
    for (int i = 0; i < 7; i++) pa.n4[i] = pa.n[i] / 4;
    prep<<<dim3((int)(ACT_ELEMS / 8 / 256), 1, 7), 256>>>(pa);

    // ---- fused Q/K/V projections ----
    QKVArgs qa;
    qa.Ah[0] = sq;  qa.Al[0] = sq + ACT_ELEMS;
    qa.Ah[1] = sk;  qa.Al[1] = sk + ACT_ELEMS;
    qa.Bh[0] = swq; qa.Bl[0] = swq + W_ELEMS;
    qa.Bh[1] = swk; qa.Bl[1] = swk + W_ELEMS;
    qa.bias[0] = bq; qa.bias[1] = bk;
    qa.Ch[0] = qh2; qa.Cl[0] = qh2 + ACT_ELEMS;
    qa.Ch[1] = kh2; qa.Cl[1] = kh2 + ACT_ELEMS;
    qa.vA = sv; qa.vB = swv; qa.vbias = bv; qa.vC = vh2;
    gemm_qkv<<<dim3(DMODEL / 128, MTOK / 128, 3), 256, GS4_B>>>(qa);

    // ---- attention ----
    flash_mma<<<NQT * NH * BATCH, 256, FSMEM_B>>>(
        qh2, qh2 + ACT_ELEMS, kh2, kh2 + ACT_ELEMS, vh2, sa);

    // ---- output projection (fp16 1-product, BK=64) ----
    gemm_wo<<<dim3(DMODEL / 128, MTOK / 128), 256, GSH_B>>>(sa, swo, bo, out);
}

// round 9
// speedup vs baseline: 5.2946x; 1.0156x over previous
#include <cuda_runtime.h>
#include <cuda_bf16.h>
#include <cuda_fp16.h>
#include <cstdint>

#define LSEQ 2048
#define DMODEL 2048
#define NH 16
#define DH 128
#define BATCH 2
#define MTOK (BATCH * LSEQ)                 // 4096
#define ACT_ELEMS ((size_t)MTOK * DMODEL)   // 8388608
#define W_ELEMS ((size_t)DMODEL * DMODEL)   // 4194304

// ---------------- scratch (static device arrays; no allocs) ----------------
__device__ __nv_bfloat16 g_sq[2 * ACT_ELEMS];   // q input bf16 hi/lo
__device__ __nv_bfloat16 g_sk[2 * ACT_ELEMS];   // k input bf16 hi/lo
__device__ __half        g_sv[ACT_ELEMS];       // v input fp16 single
__device__ __half        g_sa[ACT_ELEMS];       // attention out fp16 single
__device__ __nv_bfloat16 g_qh2[2 * ACT_ELEMS];  // projected Q bf16 hi/lo [b,h,l,d]
__device__ __nv_bfloat16 g_kh2[2 * ACT_ELEMS];  // projected K bf16 hi/lo
__device__ __half        g_vh2[ACT_ELEMS];      // projected V fp16 single
__device__ __nv_bfloat16 g_swq[2 * W_ELEMS];
__device__ __nv_bfloat16 g_swk[2 * W_ELEMS];
__device__ __half        g_swv[W_ELEMS];        // Wv fp16 single
__device__ __half        g_swo[W_ELEMS];        // Wo fp16 single

// ---------------------------- PTX helpers ----------------------------------
__device__ __forceinline__ uint32_t smem_u32(const void* p) {
    uint32_t a;
    asm("{ .reg .u64 t; cvta.to.shared.u64 t, %1; cvt.u32.u64 %0, t; }"
        : "=r"(a) : "l"(p));
    return a;
}

__device__ __forceinline__ void cp16(uint32_t saddr, const void* g) {
    asm volatile("cp.async.cg.shared.global [%0], [%1], 16;"
                 :: "r"(saddr), "l"(g) : "memory");
}
#define CP_COMMIT() asm volatile("cp.async.commit_group;" ::: "memory")
#define CP_WAIT(n)  asm volatile("cp.async.wait_group %0;" :: "n"(n) : "memory")

__device__ __forceinline__ void ldsm_x4(uint32_t* r, uint32_t a) {
    asm volatile("ldmatrix.sync.aligned.m8n8.x4.shared.b16 {%0,%1,%2,%3}, [%4];"
                 : "=r"(r[0]), "=r"(r[1]), "=r"(r[2]), "=r"(r[3]) : "r"(a));
}
__device__ __forceinline__ void ldsm_x4t(uint32_t* r, uint32_t a) {
    asm volatile("ldmatrix.sync.aligned.m8n8.x4.trans.shared.b16 {%0,%1,%2,%3}, [%4];"
                 : "=r"(r[0]), "=r"(r[1]), "=r"(r[2]), "=r"(r[3]) : "r"(a));
}
__device__ __forceinline__ void mma_bf16(float* d, const uint32_t* a,
                                         const uint32_t* b) {
    asm volatile(
        "mma.sync.aligned.m16n8k16.row.col.f32.bf16.bf16.f32 "
        "{%0,%1,%2,%3}, {%4,%5,%6,%7}, {%8,%9}, {%0,%1,%2,%3};"
        : "+f"(d[0]), "+f"(d[1]), "+f"(d[2]), "+f"(d[3])
        : "r"(a[0]), "r"(a[1]), "r"(a[2]), "r"(a[3]), "r"(b[0]), "r"(b[1]));
}
__device__ __forceinline__ void mma_f16(float* d, const uint32_t* a,
                                        const uint32_t* b) {
    asm volatile(
        "mma.sync.aligned.m16n8k16.row.col.f32.f16.f16.f32 "
        "{%0,%1,%2,%3}, {%4,%5,%6,%7}, {%8,%9}, {%0,%1,%2,%3};"
        : "+f"(d[0]), "+f"(d[1]), "+f"(d[2]), "+f"(d[3])
        : "r"(a[0]), "r"(a[1]), "r"(a[2]), "r"(a[3]), "r"(b[0]), "r"(b[1]));
}

__device__ __forceinline__ void split2(float x, float y,
                                       uint32_t& hi, uint32_t& lo) {
    __nv_bfloat16 hx = __float2bfloat16(x);
    __nv_bfloat16 hy = __float2bfloat16(y);
    __nv_bfloat162 h2; h2.x = hx; h2.y = hy;
    hi = *reinterpret_cast<uint32_t*>(&h2);
    __nv_bfloat162 l2;
    l2.x = __float2bfloat16(x - __bfloat162float(hx));
    l2.y = __float2bfloat16(y - __bfloat162float(hy));
    lo = *reinterpret_cast<uint32_t*>(&l2);
}
__device__ __forceinline__ uint32_t pack2h(float x, float y) {
    __half2 h2 = __floats2half2_rn(x, y);
    return *reinterpret_cast<uint32_t*>(&h2);
}

__device__ __forceinline__ uint32_t sw256(int r, int q) {
    return (uint32_t)(r * 256 + ((q ^ (r & 7)) << 4));
}

// ---------------------------------------------------------------------------
// prep: all 7 input conversions in one launch; 2 float4 per thread
// ---------------------------------------------------------------------------
struct PrepArgs {
    const float* src[7];
    void* dst[7];
    int n4[7];
    int n[7];
    int type[7];
};

__device__ __forceinline__ void prep_one(const PrepArgs& a, int z, int i) {
    const float4 v = ((const float4*)a.src[z])[i];
    const int n = a.n[z];
    if (a.type[z] == 0) {
        uint32_t h0, l0, h1, l1;
        split2(v.x, v.y, h0, l0);
        split2(v.z, v.w, h1, l1);
        uint32_t* hp = (uint32_t*)a.dst[z];
        uint32_t* lp = (uint32_t*)((__nv_bfloat16*)a.dst[z] + n);
        hp[2 * i] = h0; hp[2 * i + 1] = h1;
        lp[2 * i] = l0; lp[2 * i + 1] = l1;
    } else {
        uint32_t* hp = (uint32_t*)a.dst[z];
        hp[2 * i]     = pack2h(v.x, v.y);
        hp[2 * i + 1] = pack2h(v.z, v.w);
    }
}

__global__ __launch_bounds__(256)
void prep(PrepArgs a)
{
    const int z = blockIdx.z;
    const int half = a.n4[z] >> 1;
    const int i = blockIdx.x * 256 + threadIdx.x;
    if (i >= half) return;
    prep_one(a, z, i);
    prep_one(a, z, i + half);
}

// ---------------------------------------------------------------------------
// GEMM geometry (unchanged from round 8)
// ---------------------------------------------------------------------------
#define TILE_B   8192
#define NSTAGE   3
#define NCHUNK   (DMODEL / 32)
#define STAGE4_B (4 * TILE_B)
#define GS4_B    (NSTAGE * STAGE4_B)   // 96 KB

#define TILEH_B  16384
#define STAGEH_B (2 * TILEH_B)
#define GSH_B    (NSTAGE * STAGEH_B)   // 96 KB
#define NCHUNK64 (DMODEL / 64)

__device__ __forceinline__ void mainloop_bf3(
    const __nv_bfloat16* Ahi, const __nv_bfloat16* Alo,
    const __nv_bfloat16* Bhi, const __nv_bfloat16* Blo,
    int bm, int bn, uint32_t sbase, float acc[4][4][4])
{
    const int tid = threadIdx.x;
    const int lane = tid & 31;
    const int wid = tid >> 5;
    const int wm = wid & 1;
    const int wn = wid >> 1;
    const int r = tid >> 2;
    const int q = tid & 3;

    auto load_stage = [&](int kc, int s) {
        const int k0 = kc * 32;
        const uint32_t st = sbase + (uint32_t)s * STAGE4_B;
        const __nv_bfloat16* srcs[4] = {Ahi, Alo, Bhi, Blo};
        const int row0[4] = {bm, bm, bn, bn};
#pragma unroll
        for (int t = 0; t < 4; t++) {
            const __nv_bfloat16* g0 =
                srcs[t] + (size_t)(row0[t] + r) * DMODEL + k0 + q * 8;
#pragma unroll
            for (int half = 0; half < 2; half++) {
                const int rr = r + half * 64;
                const uint32_t soff = (uint32_t)t * TILE_B + rr * 64 +
                                      ((q ^ ((rr >> 1) & 3)) * 16);
                cp16(st + soff, g0 + (size_t)half * 64 * DMODEL);
            }
        }
    };

    load_stage(0, 0); CP_COMMIT();
    load_stage(1, 1); CP_COMMIT();

    for (int kc = 0; kc < NCHUNK; kc++) {
        const int s = kc % NSTAGE;
        CP_WAIT(1);
        __syncthreads();
        if (kc + 2 < NCHUNK) load_stage(kc + 2, (kc + 2) % NSTAGE);
        CP_COMMIT();

        const uint32_t st = sbase + (uint32_t)s * STAGE4_B;
        const uint32_t sAh = st;
        const uint32_t sAl = st + TILE_B;
        const uint32_t sBh = st + 2 * TILE_B;
        const uint32_t sBl = st + 3 * TILE_B;

#pragma unroll
        for (int ks = 0; ks < 2; ks++) {
            uint32_t ah[4][4], al[4][4], bh4[2][4], bl4[2][4];
#pragma unroll
            for (int mt = 0; mt < 4; mt++) {
                const int row = wm * 64 + mt * 16 + (lane & 15);
                const int kseg = ks * 2 + (lane >> 4);
                const uint32_t off =
                    row * 64 + ((kseg ^ ((row >> 1) & 3)) * 16);
                ldsm_x4(ah[mt], sAh + off);
                ldsm_x4(al[mt], sAl + off);
            }
#pragma unroll
            for (int p = 0; p < 2; p++) {
                const int nrow = wn * 32 + p * 16 + ((lane >> 4) & 1) * 8 +
                                 (lane & 7);
                const int kseg = ks * 2 + ((lane >> 3) & 1);
                const uint32_t off =
                    nrow * 64 + ((kseg ^ ((nrow >> 1) & 3)) * 16);
                ldsm_x4(bh4[p], sBh + off);
                ldsm_x4(bl4[p], sBl + off);
            }
#pragma unroll
            for (int mt = 0; mt < 4; mt++)
#pragma unroll
                for (int nt = 0; nt < 4; nt++) {
                    const uint32_t* bh = &bh4[nt >> 1][(nt & 1) * 2];
                    const uint32_t* bl = &bl4[nt >> 1][(nt & 1) * 2];
                    mma_bf16(acc[mt][nt], ah[mt], bh);
                    mma_bf16(acc[mt][nt], ah[mt], bl);
                    mma_bf16(acc[mt][nt], al[mt], bh);
                }
        }
    }
}

__device__ __forceinline__ void mainloop_h1(
    const __half* A, const __half* B,
    int bm, int bn, uint32_t sbase, float acc[4][4][4])
{
    const int tid = threadIdx.x;
    const int lane = tid & 31;
    const int wid = tid >> 5;
    const int wm = wid & 1;
    const int wn = wid >> 1;

    auto load_stage = [&](int kc, int s) {
        const int k0 = kc * 64;
        const uint32_t st = sbase + (uint32_t)s * STAGEH_B;
#pragma unroll
        for (int j = 0; j < 8; j++) {
            const int c = tid + 256 * j;
            const int t = c >> 10;
            const int u = c & 1023;
            const int r = u >> 3;
            const int q = u & 7;
            const __half* g = (t ? B + (size_t)(bn + r) * DMODEL
                                 : A + (size_t)(bm + r) * DMODEL) + k0 + q * 8;
            cp16(st + (uint32_t)t * TILEH_B + r * 128 +
                 (((q ^ (r & 7)) << 4)), g);
        }
    };

    load_stage(0, 0); CP_COMMIT();
    load_stage(1, 1); CP_COMMIT();

    for (int kc = 0; kc < NCHUNK64; kc++) {
        const int s = kc % NSTAGE;
        CP_WAIT(1);
        __syncthreads();
        if (kc + 2 < NCHUNK64) load_stage(kc + 2, (kc + 2) % NSTAGE);
        CP_COMMIT();

        const uint32_t sA = sbase + (uint32_t)s * STAGEH_B;
        const uint32_t sB = sA + TILEH_B;

#pragma unroll
        for (int ks = 0; ks < 4; ks++) {
            uint32_t ah[4][4], b4[2][4];
#pragma unroll
            for (int mt = 0; mt < 4; mt++) {
                const int row = wm * 64 + mt * 16 + (lane & 15);
                const int kseg = ks * 2 + (lane >> 4);
                ldsm_x4(ah[mt], sA + row * 128 + ((kseg ^ (row & 7)) << 4));
            }
#pragma unroll
            for (int p = 0; p < 2; p++) {
                const int nrow = wn * 32 + p * 16 + ((lane >> 4) & 1) * 8 +
                                 (lane & 7);
                const int kseg = ks * 2 + ((lane >> 3) & 1);
                ldsm_x4(b4[p], sB + nrow * 128 + ((kseg ^ (nrow & 7)) << 4));
            }
#pragma unroll
            for (int mt = 0; mt < 4; mt++)
#pragma unroll
                for (int nt = 0; nt < 4; nt++)
                    mma_f16(acc[mt][nt], ah[mt], &b4[nt >> 1][(nt & 1) * 2]);
        }
    }
}

// ---------------------------------------------------------------------------
// Fused Q/K/V projection GEMM (unchanged)
// ---------------------------------------------------------------------------
struct QKVArgs {
    const __nv_bfloat16* Ah[2];
    const __nv_bfloat16* Al[2];
    const __nv_bfloat16* Bh[2];
    const __nv_bfloat16* Bl[2];
    const float* bias[2];
    __nv_bfloat16* Ch[2];
    __nv_bfloat16* Cl[2];
    const __half* vA;
    const __half* vB;
    const float* vbias;
    __half* vC;
};

__global__ __launch_bounds__(256)
void gemm_qkv(QKVArgs args)
{
    extern __shared__ char smb[];
    const uint32_t sbase = smem_u32(smb);
    const int sel = blockIdx.z;
    const int bn = blockIdx.x * 128;
    const int bm = blockIdx.y * 128;
    const int lane = threadIdx.x & 31;
    const int wid = threadIdx.x >> 5;
    const int wm = wid & 1;
    const int wn = wid >> 1;

    float acc[4][4][4];
#pragma unroll
    for (int i = 0; i < 4; i++)
#pragma unroll
        for (int j = 0; j < 4; j++)
#pragma unroll
            for (int c = 0; c < 4; c++) acc[i][j][c] = 0.f;

    if (sel < 2) {
        mainloop_bf3(args.Ah[sel], args.Al[sel], args.Bh[sel], args.Bl[sel],
                     bm, bn, sbase, acc);
        const float* bias = args.bias[sel];
        __nv_bfloat16* Ch = args.Ch[sel];
        __nv_bfloat16* Cl = args.Cl[sel];
#pragma unroll
        for (int mt = 0; mt < 4; mt++) {
#pragma unroll
            for (int nt = 0; nt < 4; nt++) {
                const int m0 = bm + wm * 64 + mt * 16 + (lane >> 2);
                const int n0 = bn + wn * 32 + nt * 8 + (lane & 3) * 2;
                const float bia0 = __ldg(&bias[n0]);
                const float bia1 = __ldg(&bias[n0 + 1]);
#pragma unroll
                for (int half = 0; half < 2; half++) {
                    const int m = m0 + half * 8;
                    const float x0 = acc[mt][nt][half * 2] + bia0;
                    const float x1 = acc[mt][nt][half * 2 + 1] + bia1;
                    const int h = bn >> 7;
                    const int b = m >> 11;
                    const int l = m & (LSEQ - 1);
                    const size_t idx =
                        (((size_t)(b * NH + h) * LSEQ + l) * DH) + (n0 & 127);
                    uint32_t hi, lo;
                    split2(x0, x1, hi, lo);
                    *(uint32_t*)(Ch + idx) = hi;
                    *(uint32_t*)(Cl + idx) = lo;
                }
            }
        }
    } else {
        mainloop_h1(args.vA, args.vB, bm, bn, sbase, acc);
        const float* bias = args.vbias;
        __half* C = args.vC;
#pragma unroll
        for (int mt = 0; mt < 4; mt++) {
#pragma unroll
            for (int nt = 0; nt < 4; nt++) {
                const int m0 = bm + wm * 64 + mt * 16 + (lane >> 2);
                const int n0 = bn + wn * 32 + nt * 8 + (lane & 3) * 2;
                const float bia0 = __ldg(&bias[n0]);
                const float bia1 = __ldg(&bias[n0 + 1]);
#pragma unroll
                for (int half = 0; half < 2; half++) {
                    const int m = m0 + half * 8;
                    const int h = bn >> 7;
                    const int b = m >> 11;
                    const int l = m & (LSEQ - 1);
                    const size_t idx =
                        (((size_t)(b * NH + h) * LSEQ + l) * DH) + (n0 & 127);
                    *(uint32_t*)(C + idx) =
                        pack2h(acc[mt][nt][half * 2] + bia0,
                               acc[mt][nt][half * 2 + 1] + bia1);
                }
            }
        }
    }
}

// ---------------------------------------------------------------------------
// Output projection (unchanged)
// ---------------------------------------------------------------------------
__global__ __launch_bounds__(256)
void gemm_wo(const __half* __restrict__ A, const __half* __restrict__ B,
             const float* __restrict__ bias, float* __restrict__ C)
{
    extern __shared__ char smb[];
    const uint32_t sbase = smem_u32(smb);
    const int bn = blockIdx.x * 128;
    const int bm = blockIdx.y * 128;
    const int lane = threadIdx.x & 31;
    const int wid = threadIdx.x >> 5;
    const int wm = wid & 1;
    const int wn = wid >> 1;

    float acc[4][4][4];
#pragma unroll
    for (int i = 0; i < 4; i++)
#pragma unroll
        for (int j = 0; j < 4; j++)
#pragma unroll
            for (int c = 0; c < 4; c++) acc[i][j][c] = 0.f;

    mainloop_h1(A, B, bm, bn, sbase, acc);

#pragma unroll
    for (int mt = 0; mt < 4; mt++) {
#pragma unroll
        for (int nt = 0; nt < 4; nt++) {
            const int m0 = bm + wm * 64 + mt * 16 + (lane >> 2);
            const int n0 = bn + wn * 32 + nt * 8 + (lane & 3) * 2;
            const float bia0 = __ldg(&bias[n0]);
            const float bia1 = __ldg(&bias[n0 + 1]);
#pragma unroll
            for (int half = 0; half < 2; half++) {
                const int m = m0 + half * 8;
                *(float2*)(C + (size_t)m * DMODEL + n0) =
                    make_float2(acc[mt][nt][half * 2] + bia0,
                                acc[mt][nt][half * 2 + 1] + bia1);
            }
        }
    }
}

// ---------------------------------------------------------------------------
// Flash attention (causal), K-tile = 64. QK: bf16 hi/lo 3-product (Q-hi in
// regs, Q-lo re-ldsm'd per ks from smem). PV: fp16 P x fp16 V.
// Smem: Q hi/lo 64 KB + 3 stages x 48 KB = 208 KB, 1 CTA/SM.
// Softmax/shfl/rescale/sync cost per MMA halved vs K-tile 32.
// ---------------------------------------------------------------------------
#define NQT (LSEQ / 128)
#define FST_B (3 * 64 * 256)                     // 48 KB (Kh, Kl, V; 64 rows)
#define FQ_B  (2 * 128 * 256)                    // 64 KB (Q hi + lo)
#define FSMEM_B (FQ_B + 3 * FST_B)               // 208 KB
#define FSCALE 11.31370849898476f

__global__ __launch_bounds__(256, 1)
void flash_mma(const __nv_bfloat16* __restrict__ Qhi,
               const __nv_bfloat16* __restrict__ Qlo,
               const __nv_bfloat16* __restrict__ Khi,
               const __nv_bfloat16* __restrict__ Klo,
               const __half* __restrict__ V,
               __half* __restrict__ O)
{
    extern __shared__ char smb[];
    const uint32_t sbase = smem_u32(smb);
    const uint32_t qlo_s = sbase + 128 * 256;
    const uint32_t stage0 = sbase + FQ_B;

    const int tid = threadIdx.x;
    const int lane = tid & 31;
    const int w = tid >> 5;

    const int bx = blockIdx.x;
    const int qt = (NQT - 1) - (bx >> 5);
    const int hb = bx & 31;
    const int h = hb & 15;
    const int b = hb >> 4;
    const int bh = b * NH + h;
    const int NKT = 2 * (qt + 1);               // 64-row k tiles, >= 2

    const __nv_bfloat16* qh_g = Qhi + (size_t)bh * LSEQ * DH;
    const __nv_bfloat16* ql_g = Qlo + (size_t)bh * LSEQ * DH;
    const __nv_bfloat16* kh_g = Khi + (size_t)bh * LSEQ * DH;
    const __nv_bfloat16* kl_g = Klo + (size_t)bh * LSEQ * DH;
    const __half*        v_g  = V   + (size_t)bh * LSEQ * DH;

    // ---- Q load (bf16 hi/lo, 64 KB) ----
    {
#pragma unroll
        for (int j = 0; j < 16; j++) {
            const int c = tid + 256 * j;
            const int t = c >> 11;
            const int u = c & 2047;
            const int r = u >> 4;
            const int q = u & 15;
            const __nv_bfloat16* src = (t ? ql_g : qh_g) +
                (size_t)(qt * 128 + r) * DH + q * 8;
            cp16(sbase + (uint32_t)t * (128 * 256) + sw256(r, q), src);
        }
        CP_COMMIT();
    }

    // ---- stage loader: Kh, Kl, V (64 rows x 128 cols each, 48 KB) ----
    auto load_stage = [&](int kt, int s) {
        const uint32_t st = stage0 + (uint32_t)s * FST_B;
#pragma unroll
        for (int j = 0; j < 12; j++) {
            const int c = tid + 256 * j;       // 0..3071 16B chunks
            const int t = c >> 10;             // 0 Kh, 1 Kl, 2 V
            const int u = c & 1023;
            const int r = u >> 4;              // 0..63
            const int q = u & 15;
            const char* src =
                (t == 0 ? (const char*)kh_g :
                 t == 1 ? (const char*)kl_g : (const char*)v_g) +
                ((size_t)(kt * 64 + r) * DH + q * 8) * 2;
            cp16(st + (uint32_t)t * 16384 + sw256(r, q), src);
        }
        CP_COMMIT();
    };

    load_stage(0, 0);
    load_stage(1, 1);

    CP_WAIT(2);                  // Q complete (stage0/1 may pend)
    __syncthreads();

    // Q-hi fragments to registers (Q-lo stays in smem, ldsm'd per ks)
    uint32_t qfh[8][4];
#pragma unroll
    for (int ks = 0; ks < 8; ks++) {
        const int row = w * 16 + (lane & 15);
        const int q = ks * 2 + (lane >> 4);
        ldsm_x4(qfh[ks], sbase + sw256(row, q));
    }

    float O_acc[16][4];
#pragma unroll
    for (int nd = 0; nd < 16; nd++)
#pragma unroll
        for (int c = 0; c < 4; c++) O_acc[nd][c] = 0.f;
    float m0 = -3.0e38f, m1 = -3.0e38f, l0 = 0.f, l1 = 0.f;

    const int iq0 = qt * 128 + w * 16 + (lane >> 2);
    const int jcol = (lane & 3) * 2;

    for (int kt = 0; kt < NKT; kt++) {
        if (kt + 1 < NKT) { CP_WAIT(1); } else { CP_WAIT(0); }
        __syncthreads();
        if (kt + 2 < NKT) load_stage(kt + 2, (kt + 2) % 3);

        const uint32_t st = stage0 + (uint32_t)(kt % 3) * FST_B;
        const uint32_t sKh = st;
        const uint32_t sKl = st + 16384;
        const uint32_t sV  = st + 32768;

        // ---- S = Q K^T (3-product bf16), 8 n-tiles ----
        float S[8][4];
#pragma unroll
        for (int nt = 0; nt < 8; nt++)
#pragma unroll
            for (int c = 0; c < 4; c++) S[nt][c] = 0.f;

#pragma unroll
        for (int ks = 0; ks < 8; ks++) {
            uint32_t ql[4];
            {
                const int row = w * 16 + (lane & 15);
                const int q = ks * 2 + (lane >> 4);
                ldsm_x4(ql, qlo_s + sw256(row, q));
            }
            uint32_t kh4[4][4], kl4[4][4];
#pragma unroll
            for (int p = 0; p < 4; p++) {
                const int row = p * 16 + ((lane >> 4) & 1) * 8 + (lane & 7);
                const int q = ks * 2 + ((lane >> 3) & 1);
                ldsm_x4(kh4[p], sKh + sw256(row, q));
                ldsm_x4(kl4[p], sKl + sw256(row, q));
            }
#pragma unroll
            for (int nt = 0; nt < 8; nt++) {
                const uint32_t* kh = &kh4[nt >> 1][(nt & 1) * 2];
                const uint32_t* kl = &kl4[nt >> 1][(nt & 1) * 2];
                mma_bf16(S[nt], qfh[ks], kh);
                mma_bf16(S[nt], qfh[ks], kl);
                mma_bf16(S[nt], ql, kh);
            }
        }

        // ---- scale + mask ----
        const bool tilemask = (kt * 64 + 63) > (qt * 128 + w * 16);
#pragma unroll
        for (int nt = 0; nt < 8; nt++) {
#pragma unroll
            for (int c = 0; c < 4; c++) {
                float s = S[nt][c] * FSCALE;
                if (tilemask) {
                    const int i = iq0 + ((c & 2) ? 8 : 0);
                    const int j = kt * 64 + nt * 8 + jcol + (c & 1);
                    if (j > i) s -= 1e7f;
                }
                S[nt][c] = s;
            }
        }

        // ---- online softmax ----
        float tm0 = -3.0e38f, tm1 = -3.0e38f;
#pragma unroll
        for (int nt = 0; nt < 8; nt++) {
            tm0 = fmaxf(tm0, fmaxf(S[nt][0], S[nt][1]));
            tm1 = fmaxf(tm1, fmaxf(S[nt][2], S[nt][3]));
        }
        tm0 = fmaxf(tm0, __shfl_xor_sync(0xffffffffu, tm0, 1));
        tm0 = fmaxf(tm0, __shfl_xor_sync(0xffffffffu, tm0, 2));
        tm1 = fmaxf(tm1, __shfl_xor_sync(0xffffffffu, tm1, 1));
        tm1 = fmaxf(tm1, __shfl_xor_sync(0xffffffffu, tm1, 2));
        const float nm0 = fmaxf(m0, tm0);
        const float nm1 = fmaxf(m1, tm1);

        const unsigned skip =
            __all_sync(0xffffffffu, (nm0 == m0) && (nm1 == m1));
        if (!skip) {
            const float a0 = __expf(m0 - nm0);
            const float a1 = __expf(m1 - nm1);
            l0 *= a0; l1 *= a1;
#pragma unroll
            for (int nd = 0; nd < 16; nd++) {
                O_acc[nd][0] *= a0; O_acc[nd][1] *= a0;
                O_acc[nd][2] *= a1; O_acc[nd][3] *= a1;
            }
            m0 = nm0; m1 = nm1;
        }

        float s0 = 0.f, s1 = 0.f;
#pragma unroll
        for (int nt = 0; nt < 8; nt++) {
            S[nt][0] = __half2float(__float2half_rn(__expf(S[nt][0] - m0)));
            S[nt][1] = __half2float(__float2half_rn(__expf(S[nt][1] - m0)));
            S[nt][2] = __half2float(__float2half_rn(__expf(S[nt][2] - m1)));
            S[nt][3] = __half2float(__float2half_rn(__expf(S[nt][3] - m1)));
            s0 += S[nt][0] + S[nt][1];
            s1 += S[nt][2] + S[nt][3];
        }
        s0 += __shfl_xor_sync(0xffffffffu, s0, 1);
        s0 += __shfl_xor_sync(0xffffffffu, s0, 2);
        s1 += __shfl_xor_sync(0xffffffffu, s1, 1);
        s1 += __shfl_xor_sync(0xffffffffu, s1, 2);
        l0 += s0;
        l1 += s1;

        // ---- O += P V (fp16, 4 k-steps of 16 V rows) ----
#pragma unroll
        for (int ks2 = 0; ks2 < 4; ks2++) {
            const int nt0 = 2 * ks2, nt1 = nt0 + 1;
            uint32_t ph[4];
            ph[0] = pack2h(S[nt0][0], S[nt0][1]);
            ph[1] = pack2h(S[nt0][2], S[nt0][3]);
            ph[2] = pack2h(S[nt1][0], S[nt1][1]);
            ph[3] = pack2h(S[nt1][2], S[nt1][3]);
            const int vrow = ks2 * 16 + (lane & 15);
#pragma unroll
            for (int np = 0; np < 8; np++) {
                uint32_t vv[4];
                const int seg = np * 2 + (lane >> 4);
                ldsm_x4t(vv, sV + sw256(vrow, seg));
                mma_f16(O_acc[2 * np],     ph, vv);
                mma_f16(O_acc[2 * np + 1], ph, vv + 2);
            }
        }
    }

    // ---- epilogue: normalize, fp16 single, write [b, l, D] ----
    const float inv0 = 1.0f / l0;
    const float inv1 = 1.0f / l1;
    const size_t tok0 = (size_t)b * LSEQ + qt * 128 + w * 16 + (lane >> 2);
    const size_t tok1 = tok0 + 8;
    const int col = h * DH + jcol;
#pragma unroll
    for (int nd = 0; nd < 16; nd++) {
        const int cc = col + nd * 8;
        *(uint32_t*)(O + tok0 * DMODEL + cc) =
            pack2h(O_acc[nd][0] * inv0, O_acc[nd][1] * inv0);
        *(uint32_t*)(O + tok1 * DMODEL + cc) =
            pack2h(O_acc[nd][2] * inv1, O_acc[nd][3] * inv1);
    }
}

// ---------------------------------------------------------------------------
extern "C" void kernel_launch(void* const* d_in, const int* in_sizes, int n_in,
                              void* d_out, int out_size)
{
    (void)in_sizes; (void)n_in; (void)out_size;
    const float* q  = (const float*)d_in[0];
    const float* k  = (const float*)d_in[1];
    const float* v  = (const float*)d_in[2];
    const float* Wq = (const float*)d_in[3];
    const float* bq = (const float*)d_in[4];
    const float* Wk = (const float*)d_in[5];
    const float* bk = (const float*)d_in[6];
    const float* Wv = (const float*)d_in[7];
    const float* bv = (const float*)d_in[8];
    const float* Wo = (const float*)d_in[9];
    const float* bo = (const float*)d_in[10];
    float* out = (float*)d_out;

    __nv_bfloat16 *sq, *sk, *qh2, *kh2, *swq, *swk;
    __half *sv, *sa, *vh2, *swv, *swo;
    cudaGetSymbolAddress((void**)&sq, g_sq);
    cudaGetSymbolAddress((void**)&sk, g_sk);
    cudaGetSymbolAddress((void**)&sv, g_sv);
    cudaGetSymbolAddress((void**)&sa, g_sa);
    cudaGetSymbolAddress((void**)&qh2, g_qh2);
    cudaGetSymbolAddress((void**)&kh2, g_kh2);
    cudaGetSymbolAddress((void**)&vh2, g_vh2);
    cudaGetSymbolAddress((void**)&swq, g_swq);
    cudaGetSymbolAddress((void**)&swk, g_swk);
    cudaGetSymbolAddress((void**)&swv, g_swv);
    cudaGetSymbolAddress((void**)&swo, g_swo);

    cudaFuncSetAttribute(gemm_qkv, cudaFuncAttributeMaxDynamicSharedMemorySize,
                         GS4_B);
    cudaFuncSetAttribute(gemm_wo, cudaFuncAttributeMaxDynamicSharedMemorySize,
                         GSH_B);
    cudaFuncSetAttribute(flash_mma, cudaFuncAttributeMaxDynamicSharedMemorySize,
                         FSMEM_B);

    // ---- prep: all conversions in one launch ----
    PrepArgs pa;
    pa.src[0] = q;  pa.dst[0] = sq;  pa.n[0] = (int)ACT_ELEMS; pa.type[0] = 0;
    pa.src[1] = k;  pa.dst[1] = sk;  pa.n[1] = (int)ACT_ELEMS; pa.type[1] = 0;
    pa.src[2] = v;  pa.dst[2] = sv;  pa.n[2] = (int)ACT_ELEMS; pa.type[2] = 2;
    pa.src[3] = Wq; pa.dst[3] = swq; pa.n[3] = (int)W_ELEMS;   pa.type[3] = 0;
    pa.src[4] = Wk; pa.dst[4] = swk; pa.n[4] = (int)W_ELEMS;   pa.type[4] = 0;
    pa.src[5] = Wv; pa.dst[5] = swv; pa.n[5] = (int)W_ELEMS;   pa.type[5] = 2;
    pa.src[6] = Wo; pa.dst[6] = swo; pa.n[6] = (int)W_ELEMS;   pa.type[6] = 2;
    for (int i = 0; i < 7; i++) pa.n4[i] = pa.n[i] / 4;
    prep<<<dim3((int)(ACT_ELEMS / 8 / 256), 1, 7), 256>>>(pa);

    // ---- fused Q/K/V projections ----
    QKVArgs qa;
    qa.Ah[0] = sq;  qa.Al[0] = sq + ACT_ELEMS;
    qa.Ah[1] = sk;  qa.Al[1] = sk + ACT_ELEMS;
    qa.Bh[0] = swq; qa.Bl[0] = swq + W_ELEMS;
    qa.Bh[1] = swk; qa.Bl[1] = swk + W_ELEMS;
    qa.bias[0] = bq; qa.bias[1] = bk;
    qa.Ch[0] = qh2; qa.Cl[0] = qh2 + ACT_ELEMS;
    qa.Ch[1] = kh2; qa.Cl[1] = kh2 + ACT_ELEMS;
    qa.vA = sv; qa.vB = swv; qa.vbias = bv; qa.vC = vh2;
    gemm_qkv<<<dim3(DMODEL / 128, MTOK / 128, 3), 256, GS4_B>>>(qa);

    // ---- attention ----
    flash_mma<<<NQT * NH * BATCH, 256, FSMEM_B>>>(
        qh2, qh2 + ACT_ELEMS, kh2, kh2 + ACT_ELEMS, vh2, sa);

    // ---- output projection (fp16 1-product, BK=64) ----
    gemm_wo<<<dim3(DMODEL / 128, MTOK / 128), 256, GSH_B>>>(sa, swo, bo, out);
}